// round 5
// baseline (speedup 1.0000x reference)
#include <cuda_runtime.h>
#include <cuda_bf16.h>
#include <math.h>
#include <stdint.h>

// Problem constants
#define NEMBD 1024
#define NHEAD 16
#define HDIM  64
#define TSEQ  2048
#define BATCH 4
#define BH    (BATCH * NHEAD)
#define QSCALE 0.18033688011112042f   // 0.125 * log2(e)

// ---------------------------------------------------------------------------
// Scratch (device globals; allocation in kernel_launch is forbidden)
// ---------------------------------------------------------------------------
__device__ float g_qkv[(size_t)BATCH * TSEQ * 3 * NEMBD]; // [B,T,3C] fp32
__device__ __nv_bfloat16 g_a_hi[(size_t)BATCH * TSEQ * NEMBD]; // GEMM A operand (x, then y)
__device__ __nv_bfloat16 g_a_lo[(size_t)BATCH * TSEQ * NEMBD];
__device__ __nv_bfloat16 g_wq_hi[(size_t)3 * NEMBD * NEMBD];   // w_attn^T [3072][1024]
__device__ __nv_bfloat16 g_wq_lo[(size_t)3 * NEMBD * NEMBD];
__device__ __nv_bfloat16 g_wp_hi[(size_t)NEMBD * NEMBD];       // w_proj^T [1024][1024]
__device__ __nv_bfloat16 g_wp_lo[(size_t)NEMBD * NEMBD];
// Attention operand buffers
__device__ __nv_bfloat16 g_q_hi[(size_t)BH * TSEQ * HDIM];  // [bh][t][d], pre-scaled
__device__ __nv_bfloat16 g_q_lo[(size_t)BH * TSEQ * HDIM];
__device__ __nv_bfloat16 g_k_hi[(size_t)BH * TSEQ * HDIM];  // [bh][t][d]
__device__ __nv_bfloat16 g_k_lo[(size_t)BH * TSEQ * HDIM];
__device__ __nv_bfloat16 g_vt_hi[(size_t)BH * HDIM * TSEQ]; // [bh][d][t]
__device__ __nv_bfloat16 g_vt_lo[(size_t)BH * HDIM * TSEQ];

// ---------------------------------------------------------------------------
// PTX helpers (base ISA only — harness targets sm_103 without 'a')
// ---------------------------------------------------------------------------
__device__ __forceinline__ uint32_t smem_u32(const void* p) {
    uint32_t a;
    asm("{ .reg .u64 t; cvta.to.shared.u64 t, %1; cvt.u32.u64 %0, t; }" : "=r"(a) : "l"(p));
    return a;
}
#define CP_ASYNC16(sm, gm) \
    asm volatile("cp.async.cg.shared.global [%0], [%1], 16;" :: "r"(sm), "l"(gm))
#define CP_COMMIT() asm volatile("cp.async.commit_group;" ::: "memory")
#define CP_WAIT(n)  asm volatile("cp.async.wait_group %0;" :: "n"(n) : "memory")

__device__ __forceinline__ void mma16816(float* c, const uint32_t* a, const uint32_t* b) {
    asm volatile(
        "mma.sync.aligned.m16n8k16.row.col.f32.bf16.bf16.f32 "
        "{%0,%1,%2,%3}, {%4,%5,%6,%7}, {%8,%9}, {%0,%1,%2,%3};"
        : "+f"(c[0]), "+f"(c[1]), "+f"(c[2]), "+f"(c[3])
        : "r"(a[0]), "r"(a[1]), "r"(a[2]), "r"(a[3]), "r"(b[0]), "r"(b[1]));
}
__device__ __forceinline__ void mma_bb(float* c, const uint32_t* a, uint32_t b0, uint32_t b1) {
    asm volatile(
        "mma.sync.aligned.m16n8k16.row.col.f32.bf16.bf16.f32 "
        "{%0,%1,%2,%3}, {%4,%5,%6,%7}, {%8,%9}, {%0,%1,%2,%3};"
        : "+f"(c[0]), "+f"(c[1]), "+f"(c[2]), "+f"(c[3])
        : "r"(a[0]), "r"(a[1]), "r"(a[2]), "r"(a[3]), "r"(b0), "r"(b1));
}
// pack (lo,hi) floats into bf16x2 word: low half = lo, high half = hi
__device__ __forceinline__ uint32_t pack_bf16(float lo, float hi) {
    uint32_t r;
    asm("cvt.rn.bf16x2.f32 %0, %1, %2;" : "=r"(r) : "f"(hi), "f"(lo));
    return r;
}
// FFMA-only 2^t (avoids MUFU). err ~2e-9.
__device__ __forceinline__ float exp2p(float t) {
    t = fmaxf(t, -126.0f);
    float fi = rintf(t);
    float f = t - fi;
    float p = 0.0013333558f;
    p = fmaf(p, f, 0.0096181291f);
    p = fmaf(p, f, 0.0555041087f);
    p = fmaf(p, f, 0.2402265070f);
    p = fmaf(p, f, 0.6931471806f);
    p = fmaf(p, f, 1.0f);
    int ii = (int)fi;
    return p * __int_as_float((uint32_t)(ii + 127) << 23);
}

// ---------------------------------------------------------------------------
// Conversion kernels
// ---------------------------------------------------------------------------
__global__ __launch_bounds__(256)
void split_kernel(const float* __restrict__ in, __nv_bfloat16* __restrict__ hi,
                  __nv_bfloat16* __restrict__ lo, int n4)
{
    int idx = blockIdx.x * blockDim.x + threadIdx.x;
    if (idx >= n4) return;
    float4 v = ((const float4*)in)[idx];
    __nv_bfloat16 h[4], l[4];
    float f[4] = {v.x, v.y, v.z, v.w};
#pragma unroll
    for (int i = 0; i < 4; ++i) {
        h[i] = __float2bfloat16_rn(f[i]);
        l[i] = __float2bfloat16_rn(f[i] - __bfloat162float(h[i]));
    }
    ((uint2*)hi)[idx] = *(const uint2*)h;
    ((uint2*)lo)[idx] = *(const uint2*)l;
}

// w [K][N] fp32 -> hi/lo bf16 [N][K] (transposed). Block (32,8), grid (N/32, K/32).
__global__ __launch_bounds__(256)
void tsplit_kernel(const float* __restrict__ w, __nv_bfloat16* __restrict__ hi,
                   __nv_bfloat16* __restrict__ lo, int K, int N)
{
    __shared__ float t[32][33];
    const int n0 = blockIdx.x * 32;
    const int k0 = blockIdx.y * 32;
#pragma unroll
    for (int i = 0; i < 4; ++i) {
        int kk = threadIdx.y + i * 8;
        t[kk][threadIdx.x] = w[(size_t)(k0 + kk) * N + n0 + threadIdx.x];
    }
    __syncthreads();
#pragma unroll
    for (int i = 0; i < 4; ++i) {
        int nn = threadIdx.y + i * 8;
        int kk = threadIdx.x;
        float v = t[kk][nn];
        __nv_bfloat16 h = __float2bfloat16_rn(v);
        __nv_bfloat16 l = __float2bfloat16_rn(v - __bfloat162float(h));
        size_t o = (size_t)(n0 + nn) * K + k0 + kk;
        hi[o] = h;
        lo[o] = l;
    }
}

// Extract Q (scaled by QSCALE) and K from qkv into [bh][t][64] bf16 hi/lo.
__global__ __launch_bounds__(256)
void qk_split_kernel(const float* __restrict__ qkv,
                     __nv_bfloat16* __restrict__ qhi, __nv_bfloat16* __restrict__ qlo,
                     __nv_bfloat16* __restrict__ khi, __nv_bfloat16* __restrict__ klo)
{
    int idx = blockIdx.x * 256 + threadIdx.x;     // float4 units
    int d4 = idx & 15;
    int t  = (idx >> 4) & (TSEQ - 1);
    int bh = idx >> 15;
    int b = bh >> 4, h = bh & 15;
    const float* src = qkv + ((size_t)(b * TSEQ + t)) * (3 * NEMBD) + h * HDIM + d4 * 4;
    size_t dst = ((size_t)(bh * TSEQ + t)) * HDIM / 4 + d4;
    {
        float4 v = *(const float4*)src;
        float f[4] = {v.x * QSCALE, v.y * QSCALE, v.z * QSCALE, v.w * QSCALE};
        __nv_bfloat16 hh[4], ll[4];
#pragma unroll
        for (int i = 0; i < 4; ++i) {
            hh[i] = __float2bfloat16_rn(f[i]);
            ll[i] = __float2bfloat16_rn(f[i] - __bfloat162float(hh[i]));
        }
        ((uint2*)qhi)[dst] = *(const uint2*)hh;
        ((uint2*)qlo)[dst] = *(const uint2*)ll;
    }
    {
        float4 v = *(const float4*)(src + NEMBD);
        float f[4] = {v.x, v.y, v.z, v.w};
        __nv_bfloat16 hh[4], ll[4];
#pragma unroll
        for (int i = 0; i < 4; ++i) {
            hh[i] = __float2bfloat16_rn(f[i]);
            ll[i] = __float2bfloat16_rn(f[i] - __bfloat162float(hh[i]));
        }
        ((uint2*)khi)[dst] = *(const uint2*)hh;
        ((uint2*)klo)[dst] = *(const uint2*)ll;
    }
}

// V from qkv -> transposed [bh][d][t] bf16 hi/lo.
__global__ __launch_bounds__(256)
void v_tsplit_kernel(const float* __restrict__ qkv,
                     __nv_bfloat16* __restrict__ vhi, __nv_bfloat16* __restrict__ vlo)
{
    __shared__ float sm[32][33];
    const int t0 = blockIdx.x * 32;
    const int d0 = blockIdx.y * 32;
    const int bh = blockIdx.z;
    const int b = bh >> 4, h = bh & 15;
#pragma unroll
    for (int i = 0; i < 4; ++i) {
        int t = t0 + threadIdx.y + i * 8;
        sm[threadIdx.y + i * 8][threadIdx.x] =
            qkv[((size_t)(b * TSEQ + t)) * (3 * NEMBD) + 2 * NEMBD + h * HDIM + d0 + threadIdx.x];
    }
    __syncthreads();
#pragma unroll
    for (int i = 0; i < 4; ++i) {
        int d = d0 + threadIdx.y + i * 8;
        int t = t0 + threadIdx.x;
        float v = sm[threadIdx.x][threadIdx.y + i * 8];
        __nv_bfloat16 hh = __float2bfloat16_rn(v);
        __nv_bfloat16 ll = __float2bfloat16_rn(v - __bfloat162float(hh));
        size_t o = ((size_t)(bh * HDIM + d)) * TSEQ + t;
        vhi[o] = hh;
        vlo[o] = ll;
    }
}

// ---------------------------------------------------------------------------
// HMMA GEMM v2: C = A @ B^T, bf16 hi/lo 3-product.
// BM=128, BN=64, BK=32; 8 warps (4m x 2n), warp tile 32x32; 2 CTAs/SM target.
// ---------------------------------------------------------------------------
#define BK 32
#define ASTR 40                          // bf16 elems per smem row (32 + 8 pad)
#define A_TILE_B (128 * ASTR * 2)        // 10240 B
#define B_TILE_B (64 * ASTR * 2)         // 5120 B
#define GBUF_B (2 * A_TILE_B + 2 * B_TILE_B)  // 30720 B
#define GEMM_SMEM (2 * GBUF_B)           // 61440 B

__global__ __launch_bounds__(256, 2)
void gemm_hmma3_kernel(const __nv_bfloat16* __restrict__ Ahi,
                       const __nv_bfloat16* __restrict__ Alo,
                       const __nv_bfloat16* __restrict__ Bhi,
                       const __nv_bfloat16* __restrict__ Blo,
                       float* __restrict__ C, int N, int K)
{
    extern __shared__ char smem[];
    const uint32_t sbase = smem_u32(smem);
    const int tid = threadIdx.x;
    const int wid = tid >> 5;
    const int lane = tid & 31;
    const int grp = lane >> 2;
    const int tig = lane & 3;
    const int warp_m = wid & 3;     // 0..3
    const int warp_n = wid >> 2;    // 0..1
    const int rowBase = blockIdx.y * 128;
    const int colBase = blockIdx.x * 64;

    float acc[2][4][4];
#pragma unroll
    for (int i = 0; i < 2; ++i)
#pragma unroll
        for (int j = 0; j < 4; ++j)
#pragma unroll
            for (int k = 0; k < 4; ++k) acc[i][j][k] = 0.0f;

    const int nstages = K / BK;

#define LOAD_STAGE(s) do {                                                      \
        const int _k0 = (s) * BK;                                               \
        const uint32_t _buf = sbase + ((s) & 1) * GBUF_B;                       \
        _Pragma("unroll")                                                       \
        for (int _i = 0; _i < 2; ++_i) {       /* A hi/lo: 512 f4 each */       \
            int _idx = tid + _i * 256;                                          \
            int _r = _idx >> 2, _c = _idx & 3;                                  \
            CP_ASYNC16(_buf + _r * (ASTR * 2) + _c * 16,                        \
                       Ahi + (size_t)(rowBase + _r) * K + _k0 + _c * 8);        \
            CP_ASYNC16(_buf + A_TILE_B + _r * (ASTR * 2) + _c * 16,             \
                       Alo + (size_t)(rowBase + _r) * K + _k0 + _c * 8);        \
        }                                                                       \
        {                                      /* B hi/lo: 256 f4 each */       \
            int _r = tid >> 2, _c = tid & 3;                                    \
            CP_ASYNC16(_buf + 2 * A_TILE_B + _r * (ASTR * 2) + _c * 16,         \
                       Bhi + (size_t)(colBase + _r) * K + _k0 + _c * 8);        \
            CP_ASYNC16(_buf + 2 * A_TILE_B + B_TILE_B + _r * (ASTR * 2) + _c * 16, \
                       Blo + (size_t)(colBase + _r) * K + _k0 + _c * 8);        \
        }                                                                       \
        CP_COMMIT();                                                            \
    } while (0)

    LOAD_STAGE(0);

    for (int s = 0; s < nstages; ++s) {
        if (s + 1 < nstages) { LOAD_STAGE(s + 1); CP_WAIT(1); }
        else                 { CP_WAIT(0); }
        __syncthreads();

        const uint32_t buf = sbase + (s & 1) * GBUF_B;
        const uint32_t smAh = buf;
        const uint32_t smAl = buf + A_TILE_B;
        const uint32_t smBh = buf + 2 * A_TILE_B;
        const uint32_t smBl = buf + 2 * A_TILE_B + B_TILE_B;

#pragma unroll
        for (int kk = 0; kk < BK; kk += 16) {
            uint32_t ah[2][4], al[2][4], bhf[4][2], blf[4][2];
#pragma unroll
            for (int mt = 0; mt < 2; ++mt) {
                int rbase = warp_m * 32 + mt * 16 + grp;
                uint32_t o00 = (uint32_t)(rbase * (ASTR * 2) + (kk + tig * 2) * 2);
                uint32_t o10 = o00 + 8 * (ASTR * 2);
                asm volatile("ld.shared.b32 %0, [%1];" : "=r"(ah[mt][0]) : "r"(smAh + o00));
                asm volatile("ld.shared.b32 %0, [%1];" : "=r"(ah[mt][1]) : "r"(smAh + o10));
                asm volatile("ld.shared.b32 %0, [%1];" : "=r"(ah[mt][2]) : "r"(smAh + o00 + 16));
                asm volatile("ld.shared.b32 %0, [%1];" : "=r"(ah[mt][3]) : "r"(smAh + o10 + 16));
                asm volatile("ld.shared.b32 %0, [%1];" : "=r"(al[mt][0]) : "r"(smAl + o00));
                asm volatile("ld.shared.b32 %0, [%1];" : "=r"(al[mt][1]) : "r"(smAl + o10));
                asm volatile("ld.shared.b32 %0, [%1];" : "=r"(al[mt][2]) : "r"(smAl + o00 + 16));
                asm volatile("ld.shared.b32 %0, [%1];" : "=r"(al[mt][3]) : "r"(smAl + o10 + 16));
            }
#pragma unroll
            for (int nt = 0; nt < 4; ++nt) {
                int nbase = warp_n * 32 + nt * 8 + grp;
                uint32_t o = (uint32_t)(nbase * (ASTR * 2) + (kk + tig * 2) * 2);
                asm volatile("ld.shared.b32 %0, [%1];" : "=r"(bhf[nt][0]) : "r"(smBh + o));
                asm volatile("ld.shared.b32 %0, [%1];" : "=r"(bhf[nt][1]) : "r"(smBh + o + 16));
                asm volatile("ld.shared.b32 %0, [%1];" : "=r"(blf[nt][0]) : "r"(smBl + o));
                asm volatile("ld.shared.b32 %0, [%1];" : "=r"(blf[nt][1]) : "r"(smBl + o + 16));
            }
#pragma unroll
            for (int mt = 0; mt < 2; ++mt)
#pragma unroll
                for (int nt = 0; nt < 4; ++nt) {
                    mma16816(acc[mt][nt], ah[mt], bhf[nt]);
                    mma16816(acc[mt][nt], ah[mt], blf[nt]);
                    mma16816(acc[mt][nt], al[mt], bhf[nt]);
                }
        }
        __syncthreads();
    }

#pragma unroll
    for (int mt = 0; mt < 2; ++mt) {
        int r = rowBase + warp_m * 32 + mt * 16 + grp;
#pragma unroll
        for (int nt = 0; nt < 4; ++nt) {
            int c = colBase + warp_n * 32 + nt * 8 + tig * 2;
            *(float2*)(C + (size_t)r * N + c) = make_float2(acc[mt][nt][0], acc[mt][nt][1]);
            *(float2*)(C + (size_t)(r + 8) * N + c) = make_float2(acc[mt][nt][2], acc[mt][nt][3]);
        }
    }
#undef LOAD_STAGE
}

// ---------------------------------------------------------------------------
// HMMA flash attention v2: 128q x 64kv tiles, double-buffered, 2 CTAs/SM.
// ---------------------------------------------------------------------------
#define AQ  128
#define AKV 64
#define KSW 36   // Q/K smem row stride in words (32 + 4 pad)
#define VSW 36   // V^T smem row stride in words
#define QHI_W 0
#define QLO_W 4608
#define STG0_W 9216
#define STG_SZ_W 9216
#define KHI_W 0
#define KLO_W 2304
#define VHI_W 4608
#define VLO_W 6912
#define ATTN_SMEM_B ((STG0_W + 2 * STG_SZ_W) * 4)   // 110592 bytes

__global__ __launch_bounds__(256, 2)
void attn_hmma_kernel(const __nv_bfloat16* __restrict__ Qh, const __nv_bfloat16* __restrict__ Ql,
                      const __nv_bfloat16* __restrict__ Kh, const __nv_bfloat16* __restrict__ Kl,
                      const __nv_bfloat16* __restrict__ Vth, const __nv_bfloat16* __restrict__ Vtl,
                      uint32_t* __restrict__ yhi, uint32_t* __restrict__ ylo)
{
    extern __shared__ uint32_t smw[];
    const uint32_t sbase = smem_u32(smw);
    const int tid = threadIdx.x;
    const int warp = tid >> 5;
    const int lane = tid & 31;
    const int grp = lane >> 2;
    const int tig = lane & 3;
    const int qb = (int)(gridDim.x - 1 - blockIdx.x);  // heavy tiles first
    const int bh = blockIdx.y;
    const int q0 = qb * AQ;
    const size_t bhT = (size_t)bh * TSEQ;

    // ---- Q loads (128 rows x 8 f4, hi+lo) ----
#pragma unroll
    for (int i = 0; i < 4; ++i) {
        int idx = tid + i * 256;
        int r = idx >> 3, c = idx & 7;
        CP_ASYNC16(sbase + (QHI_W + r * KSW) * 4 + c * 16, Qh + (bhT + q0 + r) * HDIM + c * 8);
        CP_ASYNC16(sbase + (QLO_W + r * KSW) * 4 + c * 16, Ql + (bhT + q0 + r) * HDIM + c * 8);
    }
    CP_COMMIT();

#define LOAD_KV(kb_, st_) do {                                                          \
        const int _kv0 = (kb_) * AKV;                                                  \
        const uint32_t _sb = sbase + (STG0_W + (st_) * STG_SZ_W) * 4;                   \
        _Pragma("unroll")                                                               \
        for (int _i = 0; _i < 2; ++_i) {   /* K: 64 rows x 8 f4, hi+lo */               \
            int _idx = tid + _i * 256;                                                  \
            int _r = _idx >> 3, _c = _idx & 7;                                          \
            CP_ASYNC16(_sb + (KHI_W + _r * KSW) * 4 + _c * 16,                          \
                       Kh + (bhT + _kv0 + _r) * HDIM + _c * 8);                         \
            CP_ASYNC16(_sb + (KLO_W + _r * KSW) * 4 + _c * 16,                          \
                       Kl + (bhT + _kv0 + _r) * HDIM + _c * 8);                         \
        }                                                                               \
        _Pragma("unroll")                                                               \
        for (int _i = 0; _i < 2; ++_i) {   /* V^T: 64 d-rows x 8 f4, hi+lo */           \
            int _idx = tid + _i * 256;                                                  \
            int _r = _idx >> 3, _c = _idx & 7;                                          \
            CP_ASYNC16(_sb + (VHI_W + _r * VSW) * 4 + _c * 16,                          \
                       Vth + ((size_t)bh * HDIM + _r) * TSEQ + _kv0 + _c * 8);          \
            CP_ASYNC16(_sb + (VLO_W + _r * VSW) * 4 + _c * 16,                          \
                       Vtl + ((size_t)bh * HDIM + _r) * TSEQ + _kv0 + _c * 8);          \
        }                                                                               \
        CP_COMMIT();                                                                    \
    } while (0)

    LOAD_KV(0, 0);
    CP_WAIT(0);
    __syncthreads();

    // ---- Q fragments in registers ----
    uint32_t qfh[4][4], qfl[4][4];
    {
        const int r0 = warp * 16 + grp;
#pragma unroll
        for (int ks = 0; ks < 4; ++ks) {
            uint32_t b0 = (uint32_t)(QHI_W + r0 * KSW + ks * 8 + tig);
            qfh[ks][0] = smw[b0];
            qfh[ks][1] = smw[b0 + 8 * KSW];
            qfh[ks][2] = smw[b0 + 4];
            qfh[ks][3] = smw[b0 + 8 * KSW + 4];
            uint32_t b1 = b0 + (QLO_W - QHI_W);
            qfl[ks][0] = smw[b1];
            qfl[ks][1] = smw[b1 + 8 * KSW];
            qfl[ks][2] = smw[b1 + 4];
            qfl[ks][3] = smw[b1 + 8 * KSW + 4];
        }
    }

    float o[8][4];
#pragma unroll
    for (int i = 0; i < 8; ++i)
#pragma unroll
        for (int j = 0; j < 4; ++j) o[i][j] = 0.0f;
    float m0 = -1e30f, m1 = -1e30f, l0 = 0.0f, l1 = 0.0f;

    const int nkb = 2 * (qb + 1);
    for (int kb = 0; kb < nkb; ++kb) {
        if (kb) { CP_WAIT(0); __syncthreads(); }
        if (kb + 1 < nkb) LOAD_KV(kb + 1, (kb + 1) & 1);

        const uint32_t stw = STG0_W + (kb & 1) * STG_SZ_W;
        const uint32_t khW = stw + KHI_W, klW = stw + KLO_W;
        const uint32_t vhW = stw + VHI_W, vlW = stw + VLO_W;

        // ---- S = Q @ K^T (3 products), 64 kv cols ----
        float s[8][4];
#pragma unroll
        for (int nt = 0; nt < 8; ++nt) {
            s[nt][0] = s[nt][1] = s[nt][2] = s[nt][3] = 0.0f;
            const uint32_t rowW = (uint32_t)((nt * 8 + grp) * KSW + tig);
#pragma unroll
            for (int ks = 0; ks < 4; ++ks) {
                uint32_t oh = khW + rowW + ks * 8;
                uint32_t bh0 = smw[oh], bh1 = smw[oh + 4];
                uint32_t ol = klW + rowW + ks * 8;
                uint32_t bl0 = smw[ol], bl1 = smw[ol + 4];
                mma_bb(s[nt], qfh[ks], bh0, bh1);
                mma_bb(s[nt], qfl[ks], bh0, bh1);
                mma_bb(s[nt], qfh[ks], bl0, bl1);
            }
        }

        // ---- causal mask (last two kv blocks overlap the diagonal) ----
        if (kb >= nkb - 2) {
            const int kv0 = kb * AKV;
            const int r0g = q0 + warp * 16 + grp;
            const int r1g = r0g + 8;
#pragma unroll
            for (int nt = 0; nt < 8; ++nt) {
                int c0 = kv0 + nt * 8 + tig * 2;
                if (c0 > r0g)     s[nt][0] = -1e30f;
                if (c0 + 1 > r0g) s[nt][1] = -1e30f;
                if (c0 > r1g)     s[nt][2] = -1e30f;
                if (c0 + 1 > r1g) s[nt][3] = -1e30f;
            }
        }

        // ---- online softmax (base-2) ----
        float mx0 = -1e30f, mx1 = -1e30f;
#pragma unroll
        for (int nt = 0; nt < 8; ++nt) {
            mx0 = fmaxf(mx0, fmaxf(s[nt][0], s[nt][1]));
            mx1 = fmaxf(mx1, fmaxf(s[nt][2], s[nt][3]));
        }
        mx0 = fmaxf(mx0, __shfl_xor_sync(0xffffffffu, mx0, 1));
        mx0 = fmaxf(mx0, __shfl_xor_sync(0xffffffffu, mx0, 2));
        mx1 = fmaxf(mx1, __shfl_xor_sync(0xffffffffu, mx1, 1));
        mx1 = fmaxf(mx1, __shfl_xor_sync(0xffffffffu, mx1, 2));
        float mn0 = fmaxf(m0, mx0), mn1 = fmaxf(m1, mx1);
        float a0 = exp2p(m0 - mn0), a1 = exp2p(m1 - mn1);
        m0 = mn0; m1 = mn1;
        l0 *= a0; l1 *= a1;
#pragma unroll
        for (int nt = 0; nt < 8; ++nt) {
            o[nt][0] *= a0; o[nt][1] *= a0;
            o[nt][2] *= a1; o[nt][3] *= a1;
        }
        float sum0 = 0.0f, sum1 = 0.0f;
#pragma unroll
        for (int nt = 0; nt < 8; ++nt) {
            float p0 = exp2p(s[nt][0] - m0);
            float p1 = exp2p(s[nt][1] - m0);
            float p2 = exp2p(s[nt][2] - m1);
            float p3 = exp2p(s[nt][3] - m1);
            sum0 += p0 + p1; sum1 += p2 + p3;
            s[nt][0] = p0; s[nt][1] = p1; s[nt][2] = p2; s[nt][3] = p3;
        }
        l0 += sum0; l1 += sum1;

        // ---- O += P @ V (3 products) ----
#pragma unroll
        for (int j = 0; j < 4; ++j) {
            uint32_t ah4[4], al4[4];
#pragma unroll
            for (int u = 0; u < 2; ++u) {
                const float* pv = s[2 * j + u];
                uint32_t h01 = pack_bf16(pv[0], pv[1]);
                uint32_t h23 = pack_bf16(pv[2], pv[3]);
                float r0f = __uint_as_float(h01 << 16);
                float r1f = __uint_as_float(h01 & 0xffff0000u);
                float r2f = __uint_as_float(h23 << 16);
                float r3f = __uint_as_float(h23 & 0xffff0000u);
                ah4[u * 2 + 0] = h01;
                ah4[u * 2 + 1] = h23;
                al4[u * 2 + 0] = pack_bf16(pv[0] - r0f, pv[1] - r1f);
                al4[u * 2 + 1] = pack_bf16(pv[2] - r2f, pv[3] - r3f);
            }
#pragma unroll
            for (int nt = 0; nt < 8; ++nt) {
                const uint32_t rowW = (uint32_t)((nt * 8 + grp) * VSW + j * 8 + tig);
                uint32_t vh0 = smw[vhW + rowW], vh1 = smw[vhW + rowW + 4];
                uint32_t vl0 = smw[vlW + rowW], vl1 = smw[vlW + rowW + 4];
                mma_bb(o[nt], ah4, vh0, vh1);
                mma_bb(o[nt], al4, vh0, vh1);
                mma_bb(o[nt], ah4, vl0, vl1);
            }
        }
    }

    // ---- epilogue: normalize, store packed bf16 hi/lo y ----
    l0 += __shfl_xor_sync(0xffffffffu, l0, 1);
    l0 += __shfl_xor_sync(0xffffffffu, l0, 2);
    l1 += __shfl_xor_sync(0xffffffffu, l1, 1);
    l1 += __shfl_xor_sync(0xffffffffu, l1, 2);
    const float inv0 = 1.0f / l0, inv1 = 1.0f / l1;

    const int b = bh >> 4, h = bh & 15;
    const int rowg = q0 + warp * 16 + grp;
    const size_t base0 = ((size_t)(b * TSEQ) + rowg) * (NEMBD / 2) + h * (HDIM / 2);
    const size_t base1 = base0 + 8 * (NEMBD / 2);
#pragma unroll
    for (int nt = 0; nt < 8; ++nt) {
        int cw = nt * 4 + tig;
        {
            float f0 = o[nt][0] * inv0, f1 = o[nt][1] * inv0;
            uint32_t hp = pack_bf16(f0, f1);
            float r0f = __uint_as_float(hp << 16);
            float r1f = __uint_as_float(hp & 0xffff0000u);
            yhi[base0 + cw] = hp;
            ylo[base0 + cw] = pack_bf16(f0 - r0f, f1 - r1f);
        }
        {
            float f0 = o[nt][2] * inv1, f1 = o[nt][3] * inv1;
            uint32_t hp = pack_bf16(f0, f1);
            float r0f = __uint_as_float(hp << 16);
            float r1f = __uint_as_float(hp & 0xffff0000u);
            yhi[base1 + cw] = hp;
            ylo[base1 + cw] = pack_bf16(f0 - r0f, f1 - r1f);
        }
    }
#undef LOAD_KV
}

// ---------------------------------------------------------------------------
// Launch
// ---------------------------------------------------------------------------
extern "C" void kernel_launch(void* const* d_in, const int* in_sizes, int n_in,
                              void* d_out, int out_size)
{
    const float* x      = (const float*)d_in[0]; // [4,2048,1024]
    const float* w_attn = (const float*)d_in[1]; // [1024,3072]
    const float* w_proj = (const float*)d_in[2]; // [1024,1024]
    float* out = (float*)d_out;                  // [4,2048,1024]

    float* qkv;
    __nv_bfloat16 *ahi, *alo, *wqhi, *wqlo, *wphi, *wplo;
    __nv_bfloat16 *qhi, *qlo, *khi, *klo, *vthi, *vtlo;
    cudaGetSymbolAddress((void**)&qkv, g_qkv);
    cudaGetSymbolAddress((void**)&ahi, g_a_hi);
    cudaGetSymbolAddress((void**)&alo, g_a_lo);
    cudaGetSymbolAddress((void**)&wqhi, g_wq_hi);
    cudaGetSymbolAddress((void**)&wqlo, g_wq_lo);
    cudaGetSymbolAddress((void**)&wphi, g_wp_hi);
    cudaGetSymbolAddress((void**)&wplo, g_wp_lo);
    cudaGetSymbolAddress((void**)&qhi, g_q_hi);
    cudaGetSymbolAddress((void**)&qlo, g_q_lo);
    cudaGetSymbolAddress((void**)&khi, g_k_hi);
    cudaGetSymbolAddress((void**)&klo, g_k_lo);
    cudaGetSymbolAddress((void**)&vthi, g_vt_hi);
    cudaGetSymbolAddress((void**)&vtlo, g_vt_lo);

    cudaFuncSetAttribute(gemm_hmma3_kernel,
                         cudaFuncAttributeMaxDynamicSharedMemorySize, GEMM_SMEM);
    cudaFuncSetAttribute(attn_hmma_kernel,
                         cudaFuncAttributeMaxDynamicSharedMemorySize, ATTN_SMEM_B);

    const int M = BATCH * TSEQ;   // 8192
    const int K = NEMBD;          // 1024
    const int N1 = 3 * NEMBD;     // 3072
    const int N2 = NEMBD;         // 1024

    // Split x -> bf16 hi/lo
    {
        int n4 = (M * K) / 4;
        split_kernel<<<(n4 + 255) / 256, 256>>>(x, ahi, alo, n4);
    }
    // Transpose+split weights
    {
        dim3 g1(N1 / 32, K / 32);
        tsplit_kernel<<<g1, dim3(32, 8)>>>(w_attn, wqhi, wqlo, K, N1);
        dim3 g2(N2 / 32, K / 32);
        tsplit_kernel<<<g2, dim3(32, 8)>>>(w_proj, wphi, wplo, K, N2);
    }
    // Stage 1: qkv = x @ w_attn
    {
        dim3 grid(N1 / 64, M / 128);
        gemm_hmma3_kernel<<<grid, 256, GEMM_SMEM>>>(ahi, alo, wqhi, wqlo, qkv, N1, K);
    }
    // Prepass: extract/split Q,K and transposed V
    {
        int nthr = BH * TSEQ * 16;
        qk_split_kernel<<<nthr / 256, 256>>>(qkv, qhi, qlo, khi, klo);
        dim3 gv(TSEQ / 32, HDIM / 32, BH);
        v_tsplit_kernel<<<gv, dim3(32, 8)>>>(qkv, vthi, vtlo);
    }
    // Stage 2: HMMA flash attention -> y (bf16 hi/lo into ahi/alo)
    {
        dim3 grid(TSEQ / AQ, BH);
        attn_hmma_kernel<<<grid, 256, ATTN_SMEM_B>>>(qhi, qlo, khi, klo, vthi, vtlo,
                                                     (uint32_t*)ahi, (uint32_t*)alo);
    }
    // Stage 3: out = y @ w_proj
    {
        dim3 grid(N2 / 64, M / 128);
        gemm_hmma3_kernel<<<grid, 256, GEMM_SMEM>>>(ahi, alo, wphi, wplo, out, N2, K);
    }
}

// round 6
// speedup vs baseline: 1.3120x; 1.3120x over previous
#include <cuda_runtime.h>
#include <cuda_fp16.h>
#include <math.h>
#include <stdint.h>

// Problem constants
#define NEMBD 1024
#define NHEAD 16
#define HDIM  64
#define TSEQ  2048
#define BATCH 4
#define BH    (BATCH * NHEAD)
#define QSCALE 0.18033688011112042f   // 0.125 * log2(e)

// ---------------------------------------------------------------------------
// Scratch (device globals)
// ---------------------------------------------------------------------------
__device__ float g_qkv[(size_t)BATCH * TSEQ * 3 * NEMBD]; // [B,T,3C] fp32
__device__ __half g_a_hi[(size_t)BATCH * TSEQ * NEMBD];   // GEMM A operand (x, then y)
__device__ __half g_a_lo[(size_t)BATCH * TSEQ * NEMBD];
__device__ __half g_wq[(size_t)3 * NEMBD * NEMBD];        // w_attn^T [3072][1024] fp16
__device__ __half g_wp[(size_t)NEMBD * NEMBD];            // w_proj^T [1024][1024] fp16
// Attention operands
__device__ __half g_q_hi[(size_t)BH * TSEQ * HDIM];  // [bh][t][d], pre-scaled
__device__ __half g_q_lo[(size_t)BH * TSEQ * HDIM];
__device__ __half g_k[(size_t)BH * TSEQ * HDIM];     // [bh][t][d] single fp16
__device__ __half g_vt[(size_t)BH * HDIM * TSEQ];    // [bh][d][t] single fp16

// ---------------------------------------------------------------------------
// PTX helpers (base ISA only)
// ---------------------------------------------------------------------------
__device__ __forceinline__ uint32_t smem_u32(const void* p) {
    uint32_t a;
    asm("{ .reg .u64 t; cvta.to.shared.u64 t, %1; cvt.u32.u64 %0, t; }" : "=r"(a) : "l"(p));
    return a;
}
#define CP_ASYNC16(sm, gm) \
    asm volatile("cp.async.cg.shared.global [%0], [%1], 16;" :: "r"(sm), "l"(gm))
#define CP_COMMIT() asm volatile("cp.async.commit_group;" ::: "memory")
#define CP_WAIT(n)  asm volatile("cp.async.wait_group %0;" :: "n"(n) : "memory")

__device__ __forceinline__ void mma16816(float* c, const uint32_t* a, const uint32_t* b) {
    asm volatile(
        "mma.sync.aligned.m16n8k16.row.col.f32.f16.f16.f32 "
        "{%0,%1,%2,%3}, {%4,%5,%6,%7}, {%8,%9}, {%0,%1,%2,%3};"
        : "+f"(c[0]), "+f"(c[1]), "+f"(c[2]), "+f"(c[3])
        : "r"(a[0]), "r"(a[1]), "r"(a[2]), "r"(a[3]), "r"(b[0]), "r"(b[1]));
}
__device__ __forceinline__ void mma_bb(float* c, const uint32_t* a, uint32_t b0, uint32_t b1) {
    asm volatile(
        "mma.sync.aligned.m16n8k16.row.col.f32.f16.f16.f32 "
        "{%0,%1,%2,%3}, {%4,%5,%6,%7}, {%8,%9}, {%0,%1,%2,%3};"
        : "+f"(c[0]), "+f"(c[1]), "+f"(c[2]), "+f"(c[3])
        : "r"(a[0]), "r"(a[1]), "r"(a[2]), "r"(a[3]), "r"(b0), "r"(b1));
}
// pack two floats into half2 word (low = first arg)
__device__ __forceinline__ uint32_t pack_h2(float a, float b) {
    __half2 h = __floats2half2_rn(a, b);
    return *(uint32_t*)&h;
}
// FFMA-only 2^t (avoids MUFU)
__device__ __forceinline__ float exp2p(float t) {
    t = fmaxf(t, -126.0f);
    float fi = rintf(t);
    float f = t - fi;
    float p = 0.0013333558f;
    p = fmaf(p, f, 0.0096181291f);
    p = fmaf(p, f, 0.0555041087f);
    p = fmaf(p, f, 0.2402265070f);
    p = fmaf(p, f, 0.6931471806f);
    p = fmaf(p, f, 1.0f);
    int ii = (int)fi;
    return p * __int_as_float((uint32_t)(ii + 127) << 23);
}

// ---------------------------------------------------------------------------
// Conversion kernels
// ---------------------------------------------------------------------------
__global__ __launch_bounds__(256)
void split_kernel(const float* __restrict__ in, __half* __restrict__ hi,
                  __half* __restrict__ lo, int n4)
{
    int idx = blockIdx.x * blockDim.x + threadIdx.x;
    if (idx >= n4) return;
    float4 v = ((const float4*)in)[idx];
    __half h[4], l[4];
    float f[4] = {v.x, v.y, v.z, v.w};
#pragma unroll
    for (int i = 0; i < 4; ++i) {
        h[i] = __float2half_rn(f[i]);
        l[i] = __float2half_rn(f[i] - __half2float(h[i]));
    }
    ((uint2*)hi)[idx] = *(const uint2*)h;
    ((uint2*)lo)[idx] = *(const uint2*)l;
}

// w [K][N] fp32 -> fp16 [N][K] (transposed, single precision level).
__global__ __launch_bounds__(256)
void tsplit_kernel(const float* __restrict__ w, __half* __restrict__ wt, int K, int N)
{
    __shared__ float t[32][33];
    const int n0 = blockIdx.x * 32;
    const int k0 = blockIdx.y * 32;
#pragma unroll
    for (int i = 0; i < 4; ++i) {
        int kk = threadIdx.y + i * 8;
        t[kk][threadIdx.x] = w[(size_t)(k0 + kk) * N + n0 + threadIdx.x];
    }
    __syncthreads();
#pragma unroll
    for (int i = 0; i < 4; ++i) {
        int nn = threadIdx.y + i * 8;
        int kk = threadIdx.x;
        wt[(size_t)(n0 + nn) * K + k0 + kk] = __float2half_rn(t[kk][nn]);
    }
}

// Extract Q (scaled, hi/lo) and K (single) from qkv into [bh][t][64].
__global__ __launch_bounds__(256)
void qk_split_kernel(const float* __restrict__ qkv,
                     __half* __restrict__ qhi, __half* __restrict__ qlo,
                     __half* __restrict__ kk)
{
    int idx = blockIdx.x * 256 + threadIdx.x;     // float4 units
    int d4 = idx & 15;
    int t  = (idx >> 4) & (TSEQ - 1);
    int bh = idx >> 15;
    int b = bh >> 4, h = bh & 15;
    const float* src = qkv + ((size_t)(b * TSEQ + t)) * (3 * NEMBD) + h * HDIM + d4 * 4;
    size_t dst = ((size_t)(bh * TSEQ + t)) * HDIM / 4 + d4;
    {
        float4 v = *(const float4*)src;
        float f[4] = {v.x * QSCALE, v.y * QSCALE, v.z * QSCALE, v.w * QSCALE};
        __half hh[4], ll[4];
#pragma unroll
        for (int i = 0; i < 4; ++i) {
            hh[i] = __float2half_rn(f[i]);
            ll[i] = __float2half_rn(f[i] - __half2float(hh[i]));
        }
        ((uint2*)qhi)[dst] = *(const uint2*)hh;
        ((uint2*)qlo)[dst] = *(const uint2*)ll;
    }
    {
        float4 v = *(const float4*)(src + NEMBD);
        __half hh[4] = {__float2half_rn(v.x), __float2half_rn(v.y),
                        __float2half_rn(v.z), __float2half_rn(v.w)};
        ((uint2*)kk)[dst] = *(const uint2*)hh;
    }
}

// V from qkv -> transposed [bh][d][t] single fp16.
__global__ __launch_bounds__(256)
void v_tsplit_kernel(const float* __restrict__ qkv, __half* __restrict__ vt)
{
    __shared__ float sm[32][33];
    const int t0 = blockIdx.x * 32;
    const int d0 = blockIdx.y * 32;
    const int bh = blockIdx.z;
    const int b = bh >> 4, h = bh & 15;
#pragma unroll
    for (int i = 0; i < 4; ++i) {
        int t = t0 + threadIdx.y + i * 8;
        sm[threadIdx.y + i * 8][threadIdx.x] =
            qkv[((size_t)(b * TSEQ + t)) * (3 * NEMBD) + 2 * NEMBD + h * HDIM + d0 + threadIdx.x];
    }
    __syncthreads();
#pragma unroll
    for (int i = 0; i < 4; ++i) {
        int d = d0 + threadIdx.y + i * 8;
        int t = t0 + threadIdx.x;
        vt[((size_t)(bh * HDIM + d)) * TSEQ + t] = __float2half_rn(sm[threadIdx.x][threadIdx.y + i * 8]);
    }
}

// ---------------------------------------------------------------------------
// HMMA GEMM (fp16 2-product): C = (Ah+Al) @ Bh^T.  B stored [N][K] fp16.
// BM=128, BN=64, BK=32; 8 warps (4m x 2n), warp tile 32x32.
// ---------------------------------------------------------------------------
#define BK 32
#define ASTR 40                          // half elems per smem row (32 + 8 pad)
#define A_TILE_B (128 * ASTR * 2)        // 10240 B
#define B_TILE_B (64 * ASTR * 2)         // 5120 B
#define GBUF_B (2 * A_TILE_B + B_TILE_B) // 25600 B
#define GEMM_SMEM (2 * GBUF_B)           // 51200 B

__global__ __launch_bounds__(256, 2)
void gemm_hmma2_kernel(const __half* __restrict__ Ahi,
                       const __half* __restrict__ Alo,
                       const __half* __restrict__ B,
                       float* __restrict__ C, int N, int K)
{
    extern __shared__ char smem[];
    const uint32_t sbase = smem_u32(smem);
    const int tid = threadIdx.x;
    const int wid = tid >> 5;
    const int lane = tid & 31;
    const int grp = lane >> 2;
    const int tig = lane & 3;
    const int warp_m = wid & 3;
    const int warp_n = wid >> 2;
    const int rowBase = blockIdx.y * 128;
    const int colBase = blockIdx.x * 64;

    float acc[2][4][4];
#pragma unroll
    for (int i = 0; i < 2; ++i)
#pragma unroll
        for (int j = 0; j < 4; ++j)
#pragma unroll
            for (int k = 0; k < 4; ++k) acc[i][j][k] = 0.0f;

    const int nstages = K / BK;

#define LOAD_STAGE(s) do {                                                      \
        const int _k0 = (s) * BK;                                               \
        const uint32_t _buf = sbase + ((s) & 1) * GBUF_B;                       \
        _Pragma("unroll")                                                       \
        for (int _i = 0; _i < 2; ++_i) {       /* A hi/lo: 512 f4 each */       \
            int _idx = tid + _i * 256;                                          \
            int _r = _idx >> 2, _c = _idx & 3;                                  \
            CP_ASYNC16(_buf + _r * (ASTR * 2) + _c * 16,                        \
                       Ahi + (size_t)(rowBase + _r) * K + _k0 + _c * 8);        \
            CP_ASYNC16(_buf + A_TILE_B + _r * (ASTR * 2) + _c * 16,             \
                       Alo + (size_t)(rowBase + _r) * K + _k0 + _c * 8);        \
        }                                                                       \
        {                                      /* B: 256 f4 */                  \
            int _r = tid >> 2, _c = tid & 3;                                    \
            CP_ASYNC16(_buf + 2 * A_TILE_B + _r * (ASTR * 2) + _c * 16,         \
                       B + (size_t)(colBase + _r) * K + _k0 + _c * 8);          \
        }                                                                       \
        CP_COMMIT();                                                            \
    } while (0)

    LOAD_STAGE(0);

    for (int s = 0; s < nstages; ++s) {
        if (s + 1 < nstages) { LOAD_STAGE(s + 1); CP_WAIT(1); }
        else                 { CP_WAIT(0); }
        __syncthreads();

        const uint32_t buf = sbase + (s & 1) * GBUF_B;
        const uint32_t smAh = buf;
        const uint32_t smAl = buf + A_TILE_B;
        const uint32_t smB  = buf + 2 * A_TILE_B;

#pragma unroll
        for (int kk = 0; kk < BK; kk += 16) {
            uint32_t ah[2][4], al[2][4], bf[4][2];
#pragma unroll
            for (int mt = 0; mt < 2; ++mt) {
                int rbase = warp_m * 32 + mt * 16 + grp;
                uint32_t o00 = (uint32_t)(rbase * (ASTR * 2) + (kk + tig * 2) * 2);
                uint32_t o10 = o00 + 8 * (ASTR * 2);
                asm volatile("ld.shared.b32 %0, [%1];" : "=r"(ah[mt][0]) : "r"(smAh + o00));
                asm volatile("ld.shared.b32 %0, [%1];" : "=r"(ah[mt][1]) : "r"(smAh + o10));
                asm volatile("ld.shared.b32 %0, [%1];" : "=r"(ah[mt][2]) : "r"(smAh + o00 + 16));
                asm volatile("ld.shared.b32 %0, [%1];" : "=r"(ah[mt][3]) : "r"(smAh + o10 + 16));
                asm volatile("ld.shared.b32 %0, [%1];" : "=r"(al[mt][0]) : "r"(smAl + o00));
                asm volatile("ld.shared.b32 %0, [%1];" : "=r"(al[mt][1]) : "r"(smAl + o10));
                asm volatile("ld.shared.b32 %0, [%1];" : "=r"(al[mt][2]) : "r"(smAl + o00 + 16));
                asm volatile("ld.shared.b32 %0, [%1];" : "=r"(al[mt][3]) : "r"(smAl + o10 + 16));
            }
#pragma unroll
            for (int nt = 0; nt < 4; ++nt) {
                int nbase = warp_n * 32 + nt * 8 + grp;
                uint32_t o = (uint32_t)(nbase * (ASTR * 2) + (kk + tig * 2) * 2);
                asm volatile("ld.shared.b32 %0, [%1];" : "=r"(bf[nt][0]) : "r"(smB + o));
                asm volatile("ld.shared.b32 %0, [%1];" : "=r"(bf[nt][1]) : "r"(smB + o + 16));
            }
#pragma unroll
            for (int mt = 0; mt < 2; ++mt)
#pragma unroll
                for (int nt = 0; nt < 4; ++nt) {
                    mma16816(acc[mt][nt], ah[mt], bf[nt]);
                    mma16816(acc[mt][nt], al[mt], bf[nt]);
                }
        }
        __syncthreads();
    }

#pragma unroll
    for (int mt = 0; mt < 2; ++mt) {
        int r = rowBase + warp_m * 32 + mt * 16 + grp;
#pragma unroll
        for (int nt = 0; nt < 4; ++nt) {
            int c = colBase + warp_n * 32 + nt * 8 + tig * 2;
            *(float2*)(C + (size_t)r * N + c) = make_float2(acc[mt][nt][0], acc[mt][nt][1]);
            *(float2*)(C + (size_t)(r + 8) * N + c) = make_float2(acc[mt][nt][2], acc[mt][nt][3]);
        }
    }
#undef LOAD_STAGE
}

// ---------------------------------------------------------------------------
// HMMA flash attention (fp16 2-product): 128q x 64kv tiles, double-buffered.
// S = (Qh+Ql)@K^T; O += (Ph+Pl)@V.  K,V single fp16.
// ---------------------------------------------------------------------------
#define AQ  128
#define AKV 64
#define KSW 36
#define VSW 36
#define QHI_W 0
#define QLO_W 4608
#define STG0_W 9216
#define STG_SZ_W 4608
#define KOFF_W 0
#define VOFF_W 2304
#define ATTN_SMEM_B ((STG0_W + 2 * STG_SZ_W) * 4)   // 73728 bytes

__global__ __launch_bounds__(256, 2)
void attn_hmma_kernel(const __half* __restrict__ Qh, const __half* __restrict__ Ql,
                      const __half* __restrict__ Kt, const __half* __restrict__ Vt,
                      uint32_t* __restrict__ yhi, uint32_t* __restrict__ ylo)
{
    extern __shared__ uint32_t smw[];
    const uint32_t sbase = smem_u32(smw);
    const int tid = threadIdx.x;
    const int warp = tid >> 5;
    const int lane = tid & 31;
    const int grp = lane >> 2;
    const int tig = lane & 3;
    const int qb = (int)(gridDim.x - 1 - blockIdx.x);
    const int bh = blockIdx.y;
    const int q0 = qb * AQ;
    const size_t bhT = (size_t)bh * TSEQ;

    // Q loads (128 rows x 8 f4, hi+lo)
#pragma unroll
    for (int i = 0; i < 4; ++i) {
        int idx = tid + i * 256;
        int r = idx >> 3, c = idx & 7;
        CP_ASYNC16(sbase + (QHI_W + r * KSW) * 4 + c * 16, Qh + (bhT + q0 + r) * HDIM + c * 8);
        CP_ASYNC16(sbase + (QLO_W + r * KSW) * 4 + c * 16, Ql + (bhT + q0 + r) * HDIM + c * 8);
    }
    CP_COMMIT();

#define LOAD_KV(kb_, st_) do {                                                          \
        const int _kv0 = (kb_) * AKV;                                                  \
        const uint32_t _sb = sbase + (STG0_W + (st_) * STG_SZ_W) * 4;                   \
        _Pragma("unroll")                                                               \
        for (int _i = 0; _i < 2; ++_i) {   /* K: 64 rows x 8 f4 */                      \
            int _idx = tid + _i * 256;                                                  \
            int _r = _idx >> 3, _c = _idx & 7;                                          \
            CP_ASYNC16(_sb + (KOFF_W + _r * KSW) * 4 + _c * 16,                         \
                       Kt + (bhT + _kv0 + _r) * HDIM + _c * 8);                         \
        }                                                                               \
        _Pragma("unroll")                                                               \
        for (int _i = 0; _i < 2; ++_i) {   /* V^T: 64 d-rows x 8 f4 */                  \
            int _idx = tid + _i * 256;                                                  \
            int _r = _idx >> 3, _c = _idx & 7;                                          \
            CP_ASYNC16(_sb + (VOFF_W + _r * VSW) * 4 + _c * 16,                         \
                       Vt + ((size_t)bh * HDIM + _r) * TSEQ + _kv0 + _c * 8);           \
        }                                                                               \
        CP_COMMIT();                                                                    \
    } while (0)

    LOAD_KV(0, 0);
    CP_WAIT(0);
    __syncthreads();

    // Q fragments
    uint32_t qfh[4][4], qfl[4][4];
    {
        const int r0 = warp * 16 + grp;
#pragma unroll
        for (int ks = 0; ks < 4; ++ks) {
            uint32_t b0 = (uint32_t)(QHI_W + r0 * KSW + ks * 8 + tig);
            qfh[ks][0] = smw[b0];
            qfh[ks][1] = smw[b0 + 8 * KSW];
            qfh[ks][2] = smw[b0 + 4];
            qfh[ks][3] = smw[b0 + 8 * KSW + 4];
            uint32_t b1 = b0 + (QLO_W - QHI_W);
            qfl[ks][0] = smw[b1];
            qfl[ks][1] = smw[b1 + 8 * KSW];
            qfl[ks][2] = smw[b1 + 4];
            qfl[ks][3] = smw[b1 + 8 * KSW + 4];
        }
    }

    float o[8][4];
#pragma unroll
    for (int i = 0; i < 8; ++i)
#pragma unroll
        for (int j = 0; j < 4; ++j) o[i][j] = 0.0f;
    float m0 = -1e30f, m1 = -1e30f, l0 = 0.0f, l1 = 0.0f;

    const int nkb = 2 * (qb + 1);
    for (int kb = 0; kb < nkb; ++kb) {
        if (kb) { CP_WAIT(0); __syncthreads(); }
        if (kb + 1 < nkb) LOAD_KV(kb + 1, (kb + 1) & 1);

        const uint32_t stw = STG0_W + (kb & 1) * STG_SZ_W;
        const uint32_t kW = stw + KOFF_W;
        const uint32_t vW = stw + VOFF_W;

        // S = Q @ K^T (2 products)
        float s[8][4];
#pragma unroll
        for (int nt = 0; nt < 8; ++nt) {
            s[nt][0] = s[nt][1] = s[nt][2] = s[nt][3] = 0.0f;
            const uint32_t rowW = (uint32_t)((nt * 8 + grp) * KSW + tig);
#pragma unroll
            for (int ks = 0; ks < 4; ++ks) {
                uint32_t oh = kW + rowW + ks * 8;
                uint32_t b0 = smw[oh], b1 = smw[oh + 4];
                mma_bb(s[nt], qfh[ks], b0, b1);
                mma_bb(s[nt], qfl[ks], b0, b1);
            }
        }

        // causal mask (last two kv blocks overlap diagonal)
        if (kb >= nkb - 2) {
            const int kv0 = kb * AKV;
            const int r0g = q0 + warp * 16 + grp;
            const int r1g = r0g + 8;
#pragma unroll
            for (int nt = 0; nt < 8; ++nt) {
                int c0 = kv0 + nt * 8 + tig * 2;
                if (c0 > r0g)     s[nt][0] = -1e30f;
                if (c0 + 1 > r0g) s[nt][1] = -1e30f;
                if (c0 > r1g)     s[nt][2] = -1e30f;
                if (c0 + 1 > r1g) s[nt][3] = -1e30f;
            }
        }

        // online softmax (base-2)
        float mx0 = -1e30f, mx1 = -1e30f;
#pragma unroll
        for (int nt = 0; nt < 8; ++nt) {
            mx0 = fmaxf(mx0, fmaxf(s[nt][0], s[nt][1]));
            mx1 = fmaxf(mx1, fmaxf(s[nt][2], s[nt][3]));
        }
        mx0 = fmaxf(mx0, __shfl_xor_sync(0xffffffffu, mx0, 1));
        mx0 = fmaxf(mx0, __shfl_xor_sync(0xffffffffu, mx0, 2));
        mx1 = fmaxf(mx1, __shfl_xor_sync(0xffffffffu, mx1, 1));
        mx1 = fmaxf(mx1, __shfl_xor_sync(0xffffffffu, mx1, 2));
        float mn0 = fmaxf(m0, mx0), mn1 = fmaxf(m1, mx1);
        float a0 = exp2p(m0 - mn0), a1 = exp2p(m1 - mn1);
        m0 = mn0; m1 = mn1;
        l0 *= a0; l1 *= a1;
#pragma unroll
        for (int nt = 0; nt < 8; ++nt) {
            o[nt][0] *= a0; o[nt][1] *= a0;
            o[nt][2] *= a1; o[nt][3] *= a1;
        }
        float sum0 = 0.0f, sum1 = 0.0f;
#pragma unroll
        for (int nt = 0; nt < 8; ++nt) {
            float p0 = exp2p(s[nt][0] - m0);
            float p1 = exp2p(s[nt][1] - m0);
            float p2 = exp2p(s[nt][2] - m1);
            float p3 = exp2p(s[nt][3] - m1);
            sum0 += p0 + p1; sum1 += p2 + p3;
            s[nt][0] = p0; s[nt][1] = p1; s[nt][2] = p2; s[nt][3] = p3;
        }
        l0 += sum0; l1 += sum1;

        // O += P @ V (2 products: P hi/lo, V single)
#pragma unroll
        for (int j = 0; j < 4; ++j) {
            uint32_t ah4[4], al4[4];
#pragma unroll
            for (int u = 0; u < 2; ++u) {
                const float* pv = s[2 * j + u];
                uint32_t h01 = pack_h2(pv[0], pv[1]);
                uint32_t h23 = pack_h2(pv[2], pv[3]);
                float2 f01 = __half22float2(*(__half2*)&h01);
                float2 f23 = __half22float2(*(__half2*)&h23);
                ah4[u * 2 + 0] = h01;
                ah4[u * 2 + 1] = h23;
                al4[u * 2 + 0] = pack_h2(pv[0] - f01.x, pv[1] - f01.y);
                al4[u * 2 + 1] = pack_h2(pv[2] - f23.x, pv[3] - f23.y);
            }
#pragma unroll
            for (int nt = 0; nt < 8; ++nt) {
                const uint32_t rowW = (uint32_t)((nt * 8 + grp) * VSW + j * 8 + tig);
                uint32_t v0 = smw[vW + rowW], v1 = smw[vW + rowW + 4];
                mma_bb(o[nt], ah4, v0, v1);
                mma_bb(o[nt], al4, v0, v1);
            }
        }
    }

    // epilogue: normalize, store packed fp16 hi/lo y
    l0 += __shfl_xor_sync(0xffffffffu, l0, 1);
    l0 += __shfl_xor_sync(0xffffffffu, l0, 2);
    l1 += __shfl_xor_sync(0xffffffffu, l1, 1);
    l1 += __shfl_xor_sync(0xffffffffu, l1, 2);
    const float inv0 = 1.0f / l0, inv1 = 1.0f / l1;

    const int b = bh >> 4, h = bh & 15;
    const int rowg = q0 + warp * 16 + grp;
    const size_t base0 = ((size_t)(b * TSEQ) + rowg) * (NEMBD / 2) + h * (HDIM / 2);
    const size_t base1 = base0 + 8 * (NEMBD / 2);
#pragma unroll
    for (int nt = 0; nt < 8; ++nt) {
        int cw = nt * 4 + tig;
        {
            float f0 = o[nt][0] * inv0, f1 = o[nt][1] * inv0;
            uint32_t hp = pack_h2(f0, f1);
            float2 fr = __half22float2(*(__half2*)&hp);
            yhi[base0 + cw] = hp;
            ylo[base0 + cw] = pack_h2(f0 - fr.x, f1 - fr.y);
        }
        {
            float f0 = o[nt][2] * inv1, f1 = o[nt][3] * inv1;
            uint32_t hp = pack_h2(f0, f1);
            float2 fr = __half22float2(*(__half2*)&hp);
            yhi[base1 + cw] = hp;
            ylo[base1 + cw] = pack_h2(f0 - fr.x, f1 - fr.y);
        }
    }
#undef LOAD_KV
}

// ---------------------------------------------------------------------------
// Launch
// ---------------------------------------------------------------------------
extern "C" void kernel_launch(void* const* d_in, const int* in_sizes, int n_in,
                              void* d_out, int out_size)
{
    const float* x      = (const float*)d_in[0];
    const float* w_attn = (const float*)d_in[1];
    const float* w_proj = (const float*)d_in[2];
    float* out = (float*)d_out;

    float* qkv;
    __half *ahi, *alo, *wq, *wp, *qhi, *qlo, *kk, *vt;
    cudaGetSymbolAddress((void**)&qkv, g_qkv);
    cudaGetSymbolAddress((void**)&ahi, g_a_hi);
    cudaGetSymbolAddress((void**)&alo, g_a_lo);
    cudaGetSymbolAddress((void**)&wq, g_wq);
    cudaGetSymbolAddress((void**)&wp, g_wp);
    cudaGetSymbolAddress((void**)&qhi, g_q_hi);
    cudaGetSymbolAddress((void**)&qlo, g_q_lo);
    cudaGetSymbolAddress((void**)&kk, g_k);
    cudaGetSymbolAddress((void**)&vt, g_vt);

    cudaFuncSetAttribute(gemm_hmma2_kernel,
                         cudaFuncAttributeMaxDynamicSharedMemorySize, GEMM_SMEM);
    cudaFuncSetAttribute(attn_hmma_kernel,
                         cudaFuncAttributeMaxDynamicSharedMemorySize, ATTN_SMEM_B);

    const int M = BATCH * TSEQ;   // 8192
    const int K = NEMBD;          // 1024
    const int N1 = 3 * NEMBD;     // 3072
    const int N2 = NEMBD;         // 1024

    // Split x -> fp16 hi/lo
    {
        int n4 = (M * K) / 4;
        split_kernel<<<(n4 + 255) / 256, 256>>>(x, ahi, alo, n4);
    }
    // Transpose weights -> fp16
    {
        dim3 g1(N1 / 32, K / 32);
        tsplit_kernel<<<g1, dim3(32, 8)>>>(w_attn, wq, K, N1);
        dim3 g2(N2 / 32, K / 32);
        tsplit_kernel<<<g2, dim3(32, 8)>>>(w_proj, wp, K, N2);
    }
    // Stage 1: qkv = x @ w_attn
    {
        dim3 grid(N1 / 64, M / 128);
        gemm_hmma2_kernel<<<grid, 256, GEMM_SMEM>>>(ahi, alo, wq, qkv, N1, K);
    }
    // Prepass: Q (hi/lo) + K, transposed V
    {
        int nthr = BH * TSEQ * 16;
        qk_split_kernel<<<nthr / 256, 256>>>(qkv, qhi, qlo, kk);
        dim3 gv(TSEQ / 32, HDIM / 32, BH);
        v_tsplit_kernel<<<gv, dim3(32, 8)>>>(qkv, vt);
    }
    // Stage 2: flash attention -> y (fp16 hi/lo into ahi/alo)
    {
        dim3 grid(TSEQ / AQ, BH);
        attn_hmma_kernel<<<grid, 256, ATTN_SMEM_B>>>(qhi, qlo, kk, vt,
                                                     (uint32_t*)ahi, (uint32_t*)alo);
    }
    // Stage 3: out = y @ w_proj
    {
        dim3 grid(N2 / 64, M / 128);
        gemm_hmma2_kernel<<<grid, 256, GEMM_SMEM>>>(ahi, alo, wp, out, N2, K);
    }
}

// round 7
// speedup vs baseline: 1.3883x; 1.0582x over previous
#include <cuda_runtime.h>
#include <cuda_fp16.h>
#include <math.h>
#include <stdint.h>

// Problem constants
#define NEMBD 1024
#define NHEAD 16
#define HDIM  64
#define TSEQ  2048
#define BATCH 4
#define BH    (BATCH * NHEAD)
#define QSCALE 0.18033688011112042f   // 0.125 * log2(e)

// ---------------------------------------------------------------------------
// Scratch (device globals)
// ---------------------------------------------------------------------------
__device__ float g_qkv[(size_t)BATCH * TSEQ * 3 * NEMBD]; // [B,T,3C] fp32
__device__ __half g_a_hi[(size_t)BATCH * TSEQ * NEMBD];   // GEMM A operand (x, then y)
__device__ __half g_a_lo[(size_t)BATCH * TSEQ * NEMBD];
__device__ __half g_wq[(size_t)3 * NEMBD * NEMBD];        // w_attn^T [3072][1024] fp16
__device__ __half g_wp[(size_t)NEMBD * NEMBD];            // w_proj^T [1024][1024] fp16
// Attention operands
__device__ __half g_q_hi[(size_t)BH * TSEQ * HDIM];  // [bh][t][d], pre-scaled
__device__ __half g_q_lo[(size_t)BH * TSEQ * HDIM];
__device__ __half g_k[(size_t)BH * TSEQ * HDIM];     // [bh][t][d] single fp16
__device__ __half g_vt[(size_t)BH * HDIM * TSEQ];    // [bh][d][t] single fp16

// ---------------------------------------------------------------------------
// PTX helpers (base ISA only)
// ---------------------------------------------------------------------------
__device__ __forceinline__ uint32_t smem_u32(const void* p) {
    uint32_t a;
    asm("{ .reg .u64 t; cvta.to.shared.u64 t, %1; cvt.u32.u64 %0, t; }" : "=r"(a) : "l"(p));
    return a;
}
#define CP_ASYNC16(sm, gm) \
    asm volatile("cp.async.cg.shared.global [%0], [%1], 16;" :: "r"(sm), "l"(gm))
#define CP_COMMIT() asm volatile("cp.async.commit_group;" ::: "memory")
#define CP_WAIT(n)  asm volatile("cp.async.wait_group %0;" :: "n"(n) : "memory")

#define LDSM_X4(r0, r1, r2, r3, a) \
    asm volatile("ldmatrix.sync.aligned.m8n8.x4.shared.b16 {%0,%1,%2,%3}, [%4];" \
        : "=r"(r0), "=r"(r1), "=r"(r2), "=r"(r3) : "r"(a))

__device__ __forceinline__ void mma16816(float* c, const uint32_t* a, const uint32_t* b) {
    asm volatile(
        "mma.sync.aligned.m16n8k16.row.col.f32.f16.f16.f32 "
        "{%0,%1,%2,%3}, {%4,%5,%6,%7}, {%8,%9}, {%0,%1,%2,%3};"
        : "+f"(c[0]), "+f"(c[1]), "+f"(c[2]), "+f"(c[3])
        : "r"(a[0]), "r"(a[1]), "r"(a[2]), "r"(a[3]), "r"(b[0]), "r"(b[1]));
}
__device__ __forceinline__ void mma_bb(float* c, const uint32_t* a, uint32_t b0, uint32_t b1) {
    asm volatile(
        "mma.sync.aligned.m16n8k16.row.col.f32.f16.f16.f32 "
        "{%0,%1,%2,%3}, {%4,%5,%6,%7}, {%8,%9}, {%0,%1,%2,%3};"
        : "+f"(c[0]), "+f"(c[1]), "+f"(c[2]), "+f"(c[3])
        : "r"(a[0]), "r"(a[1]), "r"(a[2]), "r"(a[3]), "r"(b0), "r"(b1));
}
__device__ __forceinline__ uint32_t pack_h2(float a, float b) {
    __half2 h = __floats2half2_rn(a, b);
    return *(uint32_t*)&h;
}
// FFMA-only 2^t (avoids MUFU)
__device__ __forceinline__ float exp2p(float t) {
    t = fmaxf(t, -126.0f);
    float fi = rintf(t);
    float f = t - fi;
    float p = 0.0013333558f;
    p = fmaf(p, f, 0.0096181291f);
    p = fmaf(p, f, 0.0555041087f);
    p = fmaf(p, f, 0.2402265070f);
    p = fmaf(p, f, 0.6931471806f);
    p = fmaf(p, f, 1.0f);
    int ii = (int)fi;
    return p * __int_as_float((uint32_t)(ii + 127) << 23);
}

// ---------------------------------------------------------------------------
// Conversion kernels
// ---------------------------------------------------------------------------
__global__ __launch_bounds__(256)
void split_kernel(const float* __restrict__ in, __half* __restrict__ hi,
                  __half* __restrict__ lo, int n4)
{
    int idx = blockIdx.x * blockDim.x + threadIdx.x;
    if (idx >= n4) return;
    float4 v = ((const float4*)in)[idx];
    __half h[4], l[4];
    float f[4] = {v.x, v.y, v.z, v.w};
#pragma unroll
    for (int i = 0; i < 4; ++i) {
        h[i] = __float2half_rn(f[i]);
        l[i] = __float2half_rn(f[i] - __half2float(h[i]));
    }
    ((uint2*)hi)[idx] = *(const uint2*)h;
    ((uint2*)lo)[idx] = *(const uint2*)l;
}

__global__ __launch_bounds__(256)
void tsplit_kernel(const float* __restrict__ w, __half* __restrict__ wt, int K, int N)
{
    __shared__ float t[32][33];
    const int n0 = blockIdx.x * 32;
    const int k0 = blockIdx.y * 32;
#pragma unroll
    for (int i = 0; i < 4; ++i) {
        int kk = threadIdx.y + i * 8;
        t[kk][threadIdx.x] = w[(size_t)(k0 + kk) * N + n0 + threadIdx.x];
    }
    __syncthreads();
#pragma unroll
    for (int i = 0; i < 4; ++i) {
        int nn = threadIdx.y + i * 8;
        int kk = threadIdx.x;
        wt[(size_t)(n0 + nn) * K + k0 + kk] = __float2half_rn(t[kk][nn]);
    }
}

__global__ __launch_bounds__(256)
void qk_split_kernel(const float* __restrict__ qkv,
                     __half* __restrict__ qhi, __half* __restrict__ qlo,
                     __half* __restrict__ kk)
{
    int idx = blockIdx.x * 256 + threadIdx.x;     // float4 units
    int d4 = idx & 15;
    int t  = (idx >> 4) & (TSEQ - 1);
    int bh = idx >> 15;
    int b = bh >> 4, h = bh & 15;
    const float* src = qkv + ((size_t)(b * TSEQ + t)) * (3 * NEMBD) + h * HDIM + d4 * 4;
    size_t dst = ((size_t)(bh * TSEQ + t)) * HDIM / 4 + d4;
    {
        float4 v = *(const float4*)src;
        float f[4] = {v.x * QSCALE, v.y * QSCALE, v.z * QSCALE, v.w * QSCALE};
        __half hh[4], ll[4];
#pragma unroll
        for (int i = 0; i < 4; ++i) {
            hh[i] = __float2half_rn(f[i]);
            ll[i] = __float2half_rn(f[i] - __half2float(hh[i]));
        }
        ((uint2*)qhi)[dst] = *(const uint2*)hh;
        ((uint2*)qlo)[dst] = *(const uint2*)ll;
    }
    {
        float4 v = *(const float4*)(src + NEMBD);
        __half hh[4] = {__float2half_rn(v.x), __float2half_rn(v.y),
                        __float2half_rn(v.z), __float2half_rn(v.w)};
        ((uint2*)kk)[dst] = *(const uint2*)hh;
    }
}

__global__ __launch_bounds__(256)
void v_tsplit_kernel(const float* __restrict__ qkv, __half* __restrict__ vt)
{
    __shared__ float sm[32][33];
    const int t0 = blockIdx.x * 32;
    const int d0 = blockIdx.y * 32;
    const int bh = blockIdx.z;
    const int b = bh >> 4, h = bh & 15;
#pragma unroll
    for (int i = 0; i < 4; ++i) {
        int t = t0 + threadIdx.y + i * 8;
        sm[threadIdx.y + i * 8][threadIdx.x] =
            qkv[((size_t)(b * TSEQ + t)) * (3 * NEMBD) + 2 * NEMBD + h * HDIM + d0 + threadIdx.x];
    }
    __syncthreads();
#pragma unroll
    for (int i = 0; i < 4; ++i) {
        int d = d0 + threadIdx.y + i * 8;
        int t = t0 + threadIdx.x;
        vt[((size_t)(bh * HDIM + d)) * TSEQ + t] = __float2half_rn(sm[threadIdx.x][threadIdx.y + i * 8]);
    }
}

// ---------------------------------------------------------------------------
// HMMA GEMM (fp16 2-product, ldmatrix, 3-stage pipeline).
// BM=128, BN=64, BK=32; 8 warps (4m x 2n), warp tile 32x32.
// ---------------------------------------------------------------------------
#define BK 32
#define ASTR 40                          // half elems per smem row (32 + 8 pad), 20 words
#define A_TILE_B (128 * ASTR * 2)        // 10240 B
#define B_TILE_B (64 * ASTR * 2)         // 5120 B
#define GBUF_B (2 * A_TILE_B + B_TILE_B) // 25600 B
#define GEMM_SMEM (3 * GBUF_B)           // 76800 B

__global__ __launch_bounds__(256, 2)
void gemm_hmma2_kernel(const __half* __restrict__ Ahi,
                       const __half* __restrict__ Alo,
                       const __half* __restrict__ B,
                       float* __restrict__ C, int N, int K)
{
    extern __shared__ char smem[];
    const uint32_t sbase = smem_u32(smem);
    const int tid = threadIdx.x;
    const int wid = tid >> 5;
    const int lane = tid & 31;
    const int grp = lane >> 2;
    const int tig = lane & 3;
    const int warp_m = wid & 3;
    const int warp_n = wid >> 2;
    const int rowBase = blockIdx.y * 128;
    const int colBase = blockIdx.x * 64;

    // ldmatrix per-thread byte offsets (relative to tile base)
    const int a_row = lane & 15;
    const int a_kh  = (lane >> 4) * 8;                       // k-half select
    uint32_t aoff[2];
#pragma unroll
    for (int mt = 0; mt < 2; ++mt)
        aoff[mt] = (uint32_t)(((warp_m * 32 + mt * 16 + a_row) * ASTR + a_kh) * 2);
    const int b_n  = (lane & 7) + ((lane >> 4) & 1) * 8;
    const int b_kh = ((lane >> 3) & 1) * 8;
    uint32_t boff[2];
#pragma unroll
    for (int np = 0; np < 2; ++np)
        boff[np] = (uint32_t)(((warp_n * 32 + np * 16 + b_n) * ASTR + b_kh) * 2);

    float acc[2][4][4];
#pragma unroll
    for (int i = 0; i < 2; ++i)
#pragma unroll
        for (int j = 0; j < 4; ++j)
#pragma unroll
            for (int k = 0; k < 4; ++k) acc[i][j][k] = 0.0f;

    const int nstages = K / BK;

#define LOAD_STAGE(s) do {                                                      \
        const int _k0 = (s) * BK;                                               \
        const uint32_t _buf = sbase + ((s) % 3) * GBUF_B;                       \
        _Pragma("unroll")                                                       \
        for (int _i = 0; _i < 2; ++_i) {       /* A hi/lo: 512 f4 each */       \
            int _idx = tid + _i * 256;                                          \
            int _r = _idx >> 2, _c = _idx & 3;                                  \
            CP_ASYNC16(_buf + _r * (ASTR * 2) + _c * 16,                        \
                       Ahi + (size_t)(rowBase + _r) * K + _k0 + _c * 8);        \
            CP_ASYNC16(_buf + A_TILE_B + _r * (ASTR * 2) + _c * 16,             \
                       Alo + (size_t)(rowBase + _r) * K + _k0 + _c * 8);        \
        }                                                                       \
        {                                      /* B: 256 f4 */                  \
            int _r = tid >> 2, _c = tid & 3;                                    \
            CP_ASYNC16(_buf + 2 * A_TILE_B + _r * (ASTR * 2) + _c * 16,         \
                       B + (size_t)(colBase + _r) * K + _k0 + _c * 8);          \
        }                                                                       \
        CP_COMMIT();                                                            \
    } while (0)

    LOAD_STAGE(0);
    LOAD_STAGE(1);

    for (int s = 0; s < nstages; ++s) {
        if (s + 2 < nstages) { LOAD_STAGE(s + 2); CP_WAIT(2); }
        else if (s + 1 < nstages) { CP_WAIT(1); }
        else { CP_WAIT(0); }
        __syncthreads();

        const uint32_t buf = sbase + (s % 3) * GBUF_B;
        const uint32_t smAh = buf;
        const uint32_t smAl = buf + A_TILE_B;
        const uint32_t smB  = buf + 2 * A_TILE_B;

#pragma unroll
        for (int kk = 0; kk < BK; kk += 16) {
            uint32_t ah[2][4], al[2][4], bf[2][4];
#pragma unroll
            for (int mt = 0; mt < 2; ++mt) {
                LDSM_X4(ah[mt][0], ah[mt][1], ah[mt][2], ah[mt][3], smAh + aoff[mt] + kk * 2);
                LDSM_X4(al[mt][0], al[mt][1], al[mt][2], al[mt][3], smAl + aoff[mt] + kk * 2);
            }
#pragma unroll
            for (int np = 0; np < 2; ++np)
                LDSM_X4(bf[np][0], bf[np][1], bf[np][2], bf[np][3], smB + boff[np] + kk * 2);
#pragma unroll
            for (int mt = 0; mt < 2; ++mt)
#pragma unroll
                for (int nt = 0; nt < 4; ++nt) {
                    uint32_t b0 = bf[nt >> 1][(nt & 1) * 2];
                    uint32_t b1 = bf[nt >> 1][(nt & 1) * 2 + 1];
                    mma_bb(acc[mt][nt], ah[mt], b0, b1);
                    mma_bb(acc[mt][nt], al[mt], b0, b1);
                }
        }
        __syncthreads();
    }

#pragma unroll
    for (int mt = 0; mt < 2; ++mt) {
        int r = rowBase + warp_m * 32 + mt * 16 + grp;
#pragma unroll
        for (int nt = 0; nt < 4; ++nt) {
            int c = colBase + warp_n * 32 + nt * 8 + tig * 2;
            *(float2*)(C + (size_t)r * N + c) = make_float2(acc[mt][nt][0], acc[mt][nt][1]);
            *(float2*)(C + (size_t)(r + 8) * N + c) = make_float2(acc[mt][nt][2], acc[mt][nt][3]);
        }
    }
#undef LOAD_STAGE
}

// ---------------------------------------------------------------------------
// HMMA flash attention (fp16 2-product, ldmatrix): 128q x 64kv, double-buffered.
// ---------------------------------------------------------------------------
#define AQ  128
#define AKV 64
#define KSW 36   // words per row (32 + 4 pad); r*36 mod 32 covers distinct groups
#define VSW 36
#define QHI_W 0
#define QLO_W 4608
#define STG0_W 9216
#define STG_SZ_W 4608
#define KOFF_W 0
#define VOFF_W 2304
#define ATTN_SMEM_B ((STG0_W + 2 * STG_SZ_W) * 4)   // 73728 bytes

__global__ __launch_bounds__(256, 2)
void attn_hmma_kernel(const __half* __restrict__ Qh, const __half* __restrict__ Ql,
                      const __half* __restrict__ Kt, const __half* __restrict__ Vt,
                      uint32_t* __restrict__ yhi, uint32_t* __restrict__ ylo)
{
    extern __shared__ uint32_t smw[];
    const uint32_t sbase = smem_u32(smw);
    const int tid = threadIdx.x;
    const int warp = tid >> 5;
    const int lane = tid & 31;
    const int grp = lane >> 2;
    const int tig = lane & 3;
    const int qb = (int)(gridDim.x - 1 - blockIdx.x);
    const int bh = blockIdx.y;
    const int q0 = qb * AQ;
    const size_t bhT = (size_t)bh * TSEQ;

    // ldmatrix lane mappings
    const int a_row = lane & 15;
    const int a_kh  = (lane >> 4) * 8;
    const int b_n   = (lane & 7) + ((lane >> 4) & 1) * 8;
    const int b_kh  = ((lane >> 3) & 1) * 8;

    // Q loads (128 rows x 8 f4, hi+lo)
#pragma unroll
    for (int i = 0; i < 4; ++i) {
        int idx = tid + i * 256;
        int r = idx >> 3, c = idx & 7;
        CP_ASYNC16(sbase + (QHI_W + r * KSW) * 4 + c * 16, Qh + (bhT + q0 + r) * HDIM + c * 8);
        CP_ASYNC16(sbase + (QLO_W + r * KSW) * 4 + c * 16, Ql + (bhT + q0 + r) * HDIM + c * 8);
    }
    CP_COMMIT();

#define LOAD_KV(kb_, st_) do {                                                          \
        const int _kv0 = (kb_) * AKV;                                                  \
        const uint32_t _sb = sbase + (STG0_W + (st_) * STG_SZ_W) * 4;                   \
        _Pragma("unroll")                                                               \
        for (int _i = 0; _i < 2; ++_i) {   /* K: 64 rows x 8 f4 */                      \
            int _idx = tid + _i * 256;                                                  \
            int _r = _idx >> 3, _c = _idx & 7;                                          \
            CP_ASYNC16(_sb + (KOFF_W + _r * KSW) * 4 + _c * 16,                         \
                       Kt + (bhT + _kv0 + _r) * HDIM + _c * 8);                         \
        }                                                                               \
        _Pragma("unroll")                                                               \
        for (int _i = 0; _i < 2; ++_i) {   /* V^T: 64 d-rows x 8 f4 */                  \
            int _idx = tid + _i * 256;                                                  \
            int _r = _idx >> 3, _c = _idx & 7;                                          \
            CP_ASYNC16(_sb + (VOFF_W + _r * VSW) * 4 + _c * 16,                         \
                       Vt + ((size_t)bh * HDIM + _r) * TSEQ + _kv0 + _c * 8);           \
        }                                                                               \
        CP_COMMIT();                                                                    \
    } while (0)

    LOAD_KV(0, 0);
    CP_WAIT(0);
    __syncthreads();

    // Q fragments via ldmatrix (A-operand layout)
    uint32_t qfh[4][4], qfl[4][4];
    {
        const uint32_t qrow = (uint32_t)((warp * 16 + a_row) * KSW);
#pragma unroll
        for (int ks = 0; ks < 4; ++ks) {
            uint32_t ao = sbase + (QHI_W + qrow) * 4 + (ks * 16 + a_kh) * 2;
            LDSM_X4(qfh[ks][0], qfh[ks][1], qfh[ks][2], qfh[ks][3], ao);
            uint32_t al_ = ao + (QLO_W - QHI_W) * 4;
            LDSM_X4(qfl[ks][0], qfl[ks][1], qfl[ks][2], qfl[ks][3], al_);
        }
    }

    float o[8][4];
#pragma unroll
    for (int i = 0; i < 8; ++i)
#pragma unroll
        for (int j = 0; j < 4; ++j) o[i][j] = 0.0f;
    float m0 = -1e30f, m1 = -1e30f, l0 = 0.0f, l1 = 0.0f;

    const int nkb = 2 * (qb + 1);
    for (int kb = 0; kb < nkb; ++kb) {
        if (kb) { CP_WAIT(0); __syncthreads(); }
        if (kb + 1 < nkb) LOAD_KV(kb + 1, (kb + 1) & 1);

        const uint32_t stw = STG0_W + (kb & 1) * STG_SZ_W;
        const uint32_t kW = stw + KOFF_W;
        const uint32_t vW = stw + VOFF_W;

        // S = Q @ K^T (2 products), ldmatrix B-operand
        float s[8][4];
#pragma unroll
        for (int i = 0; i < 8; ++i)
            s[i][0] = s[i][1] = s[i][2] = s[i][3] = 0.0f;
#pragma unroll
        for (int np = 0; np < 4; ++np) {
            const uint32_t krow = sbase + (kW + (np * 16 + b_n) * KSW) * 4;
#pragma unroll
            for (int ks = 0; ks < 4; ++ks) {
                uint32_t b0, b1, b2, b3;
                LDSM_X4(b0, b1, b2, b3, krow + (ks * 16 + b_kh) * 2);
                mma_bb(s[np * 2],     qfh[ks], b0, b1);
                mma_bb(s[np * 2],     qfl[ks], b0, b1);
                mma_bb(s[np * 2 + 1], qfh[ks], b2, b3);
                mma_bb(s[np * 2 + 1], qfl[ks], b2, b3);
            }
        }

        // causal mask (last two kv blocks overlap diagonal)
        if (kb >= nkb - 2) {
            const int kv0 = kb * AKV;
            const int r0g = q0 + warp * 16 + grp;
            const int r1g = r0g + 8;
#pragma unroll
            for (int nt = 0; nt < 8; ++nt) {
                int c0 = kv0 + nt * 8 + tig * 2;
                if (c0 > r0g)     s[nt][0] = -1e30f;
                if (c0 + 1 > r0g) s[nt][1] = -1e30f;
                if (c0 > r1g)     s[nt][2] = -1e30f;
                if (c0 + 1 > r1g) s[nt][3] = -1e30f;
            }
        }

        // online softmax (base-2)
        float mx0 = -1e30f, mx1 = -1e30f;
#pragma unroll
        for (int nt = 0; nt < 8; ++nt) {
            mx0 = fmaxf(mx0, fmaxf(s[nt][0], s[nt][1]));
            mx1 = fmaxf(mx1, fmaxf(s[nt][2], s[nt][3]));
        }
        mx0 = fmaxf(mx0, __shfl_xor_sync(0xffffffffu, mx0, 1));
        mx0 = fmaxf(mx0, __shfl_xor_sync(0xffffffffu, mx0, 2));
        mx1 = fmaxf(mx1, __shfl_xor_sync(0xffffffffu, mx1, 1));
        mx1 = fmaxf(mx1, __shfl_xor_sync(0xffffffffu, mx1, 2));
        float mn0 = fmaxf(m0, mx0), mn1 = fmaxf(m1, mx1);
        float a0 = exp2p(m0 - mn0), a1 = exp2p(m1 - mn1);
        m0 = mn0; m1 = mn1;
        l0 *= a0; l1 *= a1;
#pragma unroll
        for (int nt = 0; nt < 8; ++nt) {
            o[nt][0] *= a0; o[nt][1] *= a0;
            o[nt][2] *= a1; o[nt][3] *= a1;
        }
        float sum0 = 0.0f, sum1 = 0.0f;
#pragma unroll
        for (int nt = 0; nt < 8; ++nt) {
            float p0 = exp2p(s[nt][0] - m0);
            float p1 = exp2p(s[nt][1] - m0);
            float p2 = exp2p(s[nt][2] - m1);
            float p3 = exp2p(s[nt][3] - m1);
            sum0 += p0 + p1; sum1 += p2 + p3;
            s[nt][0] = p0; s[nt][1] = p1; s[nt][2] = p2; s[nt][3] = p3;
        }
        l0 += sum0; l1 += sum1;

        // O += P @ V (2 products), ldmatrix B-operand
#pragma unroll
        for (int j = 0; j < 4; ++j) {
            uint32_t ah4[4], al4[4];
#pragma unroll
            for (int u = 0; u < 2; ++u) {
                const float* pv = s[2 * j + u];
                uint32_t h01 = pack_h2(pv[0], pv[1]);
                uint32_t h23 = pack_h2(pv[2], pv[3]);
                float2 f01 = __half22float2(*(__half2*)&h01);
                float2 f23 = __half22float2(*(__half2*)&h23);
                ah4[u * 2 + 0] = h01;
                ah4[u * 2 + 1] = h23;
                al4[u * 2 + 0] = pack_h2(pv[0] - f01.x, pv[1] - f01.y);
                al4[u * 2 + 1] = pack_h2(pv[2] - f23.x, pv[3] - f23.y);
            }
#pragma unroll
            for (int np = 0; np < 4; ++np) {
                uint32_t v0, v1, v2, v3;
                uint32_t vrow = sbase + (vW + (np * 16 + b_n) * VSW) * 4;
                LDSM_X4(v0, v1, v2, v3, vrow + (j * 16 + b_kh) * 2);
                mma_bb(o[np * 2],     ah4, v0, v1);
                mma_bb(o[np * 2],     al4, v0, v1);
                mma_bb(o[np * 2 + 1], ah4, v2, v3);
                mma_bb(o[np * 2 + 1], al4, v2, v3);
            }
        }
    }

    // epilogue: normalize, store packed fp16 hi/lo y
    l0 += __shfl_xor_sync(0xffffffffu, l0, 1);
    l0 += __shfl_xor_sync(0xffffffffu, l0, 2);
    l1 += __shfl_xor_sync(0xffffffffu, l1, 1);
    l1 += __shfl_xor_sync(0xffffffffu, l1, 2);
    const float inv0 = 1.0f / l0, inv1 = 1.0f / l1;

    const int b = bh >> 4, h = bh & 15;
    const int rowg = q0 + warp * 16 + grp;
    const size_t base0 = ((size_t)(b * TSEQ) + rowg) * (NEMBD / 2) + h * (HDIM / 2);
    const size_t base1 = base0 + 8 * (NEMBD / 2);
#pragma unroll
    for (int nt = 0; nt < 8; ++nt) {
        int cw = nt * 4 + tig;
        {
            float f0 = o[nt][0] * inv0, f1 = o[nt][1] * inv0;
            uint32_t hp = pack_h2(f0, f1);
            float2 fr = __half22float2(*(__half2*)&hp);
            yhi[base0 + cw] = hp;
            ylo[base0 + cw] = pack_h2(f0 - fr.x, f1 - fr.y);
        }
        {
            float f0 = o[nt][2] * inv1, f1 = o[nt][3] * inv1;
            uint32_t hp = pack_h2(f0, f1);
            float2 fr = __half22float2(*(__half2*)&hp);
            yhi[base1 + cw] = hp;
            ylo[base1 + cw] = pack_h2(f0 - fr.x, f1 - fr.y);
        }
    }
#undef LOAD_KV
}

// ---------------------------------------------------------------------------
// Launch
// ---------------------------------------------------------------------------
extern "C" void kernel_launch(void* const* d_in, const int* in_sizes, int n_in,
                              void* d_out, int out_size)
{
    const float* x      = (const float*)d_in[0];
    const float* w_attn = (const float*)d_in[1];
    const float* w_proj = (const float*)d_in[2];
    float* out = (float*)d_out;

    float* qkv;
    __half *ahi, *alo, *wq, *wp, *qhi, *qlo, *kk, *vt;
    cudaGetSymbolAddress((void**)&qkv, g_qkv);
    cudaGetSymbolAddress((void**)&ahi, g_a_hi);
    cudaGetSymbolAddress((void**)&alo, g_a_lo);
    cudaGetSymbolAddress((void**)&wq, g_wq);
    cudaGetSymbolAddress((void**)&wp, g_wp);
    cudaGetSymbolAddress((void**)&qhi, g_q_hi);
    cudaGetSymbolAddress((void**)&qlo, g_q_lo);
    cudaGetSymbolAddress((void**)&kk, g_k);
    cudaGetSymbolAddress((void**)&vt, g_vt);

    cudaFuncSetAttribute(gemm_hmma2_kernel,
                         cudaFuncAttributeMaxDynamicSharedMemorySize, GEMM_SMEM);
    cudaFuncSetAttribute(attn_hmma_kernel,
                         cudaFuncAttributeMaxDynamicSharedMemorySize, ATTN_SMEM_B);

    const int M = BATCH * TSEQ;   // 8192
    const int K = NEMBD;          // 1024
    const int N1 = 3 * NEMBD;     // 3072
    const int N2 = NEMBD;         // 1024

    // Split x -> fp16 hi/lo
    {
        int n4 = (M * K) / 4;
        split_kernel<<<(n4 + 255) / 256, 256>>>(x, ahi, alo, n4);
    }
    // Transpose weights -> fp16
    {
        dim3 g1(N1 / 32, K / 32);
        tsplit_kernel<<<g1, dim3(32, 8)>>>(w_attn, wq, K, N1);
        dim3 g2(N2 / 32, K / 32);
        tsplit_kernel<<<g2, dim3(32, 8)>>>(w_proj, wp, K, N2);
    }
    // Stage 1: qkv = x @ w_attn
    {
        dim3 grid(N1 / 64, M / 128);
        gemm_hmma2_kernel<<<grid, 256, GEMM_SMEM>>>(ahi, alo, wq, qkv, N1, K);
    }
    // Prepass: Q (hi/lo) + K, transposed V
    {
        int nthr = BH * TSEQ * 16;
        qk_split_kernel<<<nthr / 256, 256>>>(qkv, qhi, qlo, kk);
        dim3 gv(TSEQ / 32, HDIM / 32, BH);
        v_tsplit_kernel<<<gv, dim3(32, 8)>>>(qkv, vt);
    }
    // Stage 2: flash attention -> y (fp16 hi/lo into ahi/alo)
    {
        dim3 grid(TSEQ / AQ, BH);
        attn_hmma_kernel<<<grid, 256, ATTN_SMEM_B>>>(qhi, qlo, kk, vt,
                                                     (uint32_t*)ahi, (uint32_t*)alo);
    }
    // Stage 3: out = y @ w_proj
    {
        dim3 grid(N2 / 64, M / 128);
        gemm_hmma2_kernel<<<grid, 256, GEMM_SMEM>>>(ahi, alo, wp, out, N2, K);
    }
}

// round 8
// speedup vs baseline: 1.4195x; 1.0225x over previous
#include <cuda_runtime.h>
#include <cuda_fp16.h>
#include <math.h>
#include <stdint.h>

// Problem constants
#define NEMBD 1024
#define NHEAD 16
#define HDIM  64
#define TSEQ  2048
#define BATCH 4
#define BH    (BATCH * NHEAD)
#define QSCALE 0.18033688011112042f   // 0.125 * log2(e)

// ---------------------------------------------------------------------------
// Scratch (device globals)
// ---------------------------------------------------------------------------
__device__ __half g_a_hi[(size_t)BATCH * TSEQ * NEMBD];   // GEMM A operand (x, then y)
__device__ __half g_a_lo[(size_t)BATCH * TSEQ * NEMBD];
__device__ __half g_wq[(size_t)3 * NEMBD * NEMBD];        // w_attn^T [3072][1024] fp16
__device__ __half g_wp[(size_t)NEMBD * NEMBD];            // w_proj^T [1024][1024] fp16
// Attention operands (q/k written directly by GEMM1 epilogue)
__device__ __half g_q_hi[(size_t)BH * TSEQ * HDIM];  // [bh][t][d], pre-scaled
__device__ __half g_q_lo[(size_t)BH * TSEQ * HDIM];
__device__ __half g_k[(size_t)BH * TSEQ * HDIM];     // [bh][t][d] single fp16
__device__ float  g_v32[(size_t)BH * TSEQ * HDIM];   // [bh][t][d] fp32 (pre-transpose)
__device__ __half g_vt[(size_t)BH * HDIM * TSEQ];    // [bh][d][t] single fp16

// ---------------------------------------------------------------------------
// PTX helpers (base ISA only)
// ---------------------------------------------------------------------------
__device__ __forceinline__ uint32_t smem_u32(const void* p) {
    uint32_t a;
    asm("{ .reg .u64 t; cvta.to.shared.u64 t, %1; cvt.u32.u64 %0, t; }" : "=r"(a) : "l"(p));
    return a;
}
#define CP_ASYNC16(sm, gm) \
    asm volatile("cp.async.cg.shared.global [%0], [%1], 16;" :: "r"(sm), "l"(gm))
#define CP_COMMIT() asm volatile("cp.async.commit_group;" ::: "memory")
#define CP_WAIT(n)  asm volatile("cp.async.wait_group %0;" :: "n"(n) : "memory")

#define LDSM_X4(r0, r1, r2, r3, a) \
    asm volatile("ldmatrix.sync.aligned.m8n8.x4.shared.b16 {%0,%1,%2,%3}, [%4];" \
        : "=r"(r0), "=r"(r1), "=r"(r2), "=r"(r3) : "r"(a))

__device__ __forceinline__ void mma_bb(float* c, const uint32_t* a, uint32_t b0, uint32_t b1) {
    asm volatile(
        "mma.sync.aligned.m16n8k16.row.col.f32.f16.f16.f32 "
        "{%0,%1,%2,%3}, {%4,%5,%6,%7}, {%8,%9}, {%0,%1,%2,%3};"
        : "+f"(c[0]), "+f"(c[1]), "+f"(c[2]), "+f"(c[3])
        : "r"(a[0]), "r"(a[1]), "r"(a[2]), "r"(a[3]), "r"(b0), "r"(b1));
}
__device__ __forceinline__ uint32_t pack_h2(float a, float b) {
    __half2 h = __floats2half2_rn(a, b);
    return *(uint32_t*)&h;
}
// FFMA-only 2^t (avoids MUFU)
__device__ __forceinline__ float exp2p(float t) {
    t = fmaxf(t, -126.0f);
    float fi = rintf(t);
    float f = t - fi;
    float p = 0.0013333558f;
    p = fmaf(p, f, 0.0096181291f);
    p = fmaf(p, f, 0.0555041087f);
    p = fmaf(p, f, 0.2402265070f);
    p = fmaf(p, f, 0.6931471806f);
    p = fmaf(p, f, 1.0f);
    int ii = (int)fi;
    return p * __int_as_float((uint32_t)(ii + 127) << 23);
}

// ---------------------------------------------------------------------------
// Conversion kernels
// ---------------------------------------------------------------------------
__global__ __launch_bounds__(256)
void split_kernel(const float* __restrict__ in, __half* __restrict__ hi,
                  __half* __restrict__ lo, int n4)
{
    int idx = blockIdx.x * blockDim.x + threadIdx.x;
    if (idx >= n4) return;
    float4 v = ((const float4*)in)[idx];
    __half h[4], l[4];
    float f[4] = {v.x, v.y, v.z, v.w};
#pragma unroll
    for (int i = 0; i < 4; ++i) {
        h[i] = __float2half_rn(f[i]);
        l[i] = __float2half_rn(f[i] - __half2float(h[i]));
    }
    ((uint2*)hi)[idx] = *(const uint2*)h;
    ((uint2*)lo)[idx] = *(const uint2*)l;
}

__global__ __launch_bounds__(256)
void tsplit_kernel(const float* __restrict__ w, __half* __restrict__ wt, int K, int N)
{
    __shared__ float t[32][33];
    const int n0 = blockIdx.x * 32;
    const int k0 = blockIdx.y * 32;
#pragma unroll
    for (int i = 0; i < 4; ++i) {
        int kk = threadIdx.y + i * 8;
        t[kk][threadIdx.x] = w[(size_t)(k0 + kk) * N + n0 + threadIdx.x];
    }
    __syncthreads();
#pragma unroll
    for (int i = 0; i < 4; ++i) {
        int nn = threadIdx.y + i * 8;
        int kk = threadIdx.x;
        wt[(size_t)(n0 + nn) * K + k0 + kk] = __float2half_rn(t[kk][nn]);
    }
}

// V transpose: g_v32 [bh][t][64] fp32 -> vt [bh][d][t] fp16.
__global__ __launch_bounds__(256)
void v_tsplit_kernel(const float* __restrict__ v32, __half* __restrict__ vt)
{
    __shared__ float sm[32][33];
    const int t0 = blockIdx.x * 32;
    const int d0 = blockIdx.y * 32;
    const int bh = blockIdx.z;
#pragma unroll
    for (int i = 0; i < 4; ++i) {
        int t = t0 + threadIdx.y + i * 8;
        sm[threadIdx.y + i * 8][threadIdx.x] =
            v32[((size_t)bh * TSEQ + t) * HDIM + d0 + threadIdx.x];
    }
    __syncthreads();
#pragma unroll
    for (int i = 0; i < 4; ++i) {
        int d = d0 + threadIdx.y + i * 8;
        int t = t0 + threadIdx.x;
        vt[((size_t)(bh * HDIM + d)) * TSEQ + t] = __float2half_rn(sm[threadIdx.x][threadIdx.y + i * 8]);
    }
}

// ---------------------------------------------------------------------------
// HMMA GEMM (fp16 2-product, ldmatrix, 3-stage pipeline).
// BM=128, BN=64, BK=32; 8 warps (4m x 2n), warp tile 32x32.
// MODE 0: plain fp32 C.  MODE 1: fused qkv epilogue (q hi/lo, k fp16, v fp32).
// ---------------------------------------------------------------------------
#define BK 32
#define ASTR 40                          // half elems per smem row (32 + 8 pad), 20 words
#define A_TILE_B (128 * ASTR * 2)        // 10240 B
#define B_TILE_B (64 * ASTR * 2)         // 5120 B
#define GBUF_B (2 * A_TILE_B + B_TILE_B) // 25600 B
#define GEMM_SMEM (3 * GBUF_B)           // 76800 B

template<int MODE>
__global__ __launch_bounds__(256, 2)
void gemm_hmma2_kernel(const __half* __restrict__ Ahi,
                       const __half* __restrict__ Alo,
                       const __half* __restrict__ B,
                       float* __restrict__ C,
                       uint32_t* __restrict__ qhi, uint32_t* __restrict__ qlo,
                       uint32_t* __restrict__ kk, float* __restrict__ v32,
                       int N, int K)
{
    extern __shared__ char smem[];
    const uint32_t sbase = smem_u32(smem);
    const int tid = threadIdx.x;
    const int wid = tid >> 5;
    const int lane = tid & 31;
    const int grp = lane >> 2;
    const int tig = lane & 3;
    const int warp_m = wid & 3;
    const int warp_n = wid >> 2;
    const int rowBase = blockIdx.y * 128;
    const int colBase = blockIdx.x * 64;

    // ldmatrix per-thread byte offsets
    const int a_row = lane & 15;
    const int a_kh  = (lane >> 4) * 8;
    uint32_t aoff[2];
#pragma unroll
    for (int mt = 0; mt < 2; ++mt)
        aoff[mt] = (uint32_t)(((warp_m * 32 + mt * 16 + a_row) * ASTR + a_kh) * 2);
    const int b_n  = (lane & 7) + ((lane >> 4) & 1) * 8;
    const int b_kh = ((lane >> 3) & 1) * 8;
    uint32_t boff[2];
#pragma unroll
    for (int np = 0; np < 2; ++np)
        boff[np] = (uint32_t)(((warp_n * 32 + np * 16 + b_n) * ASTR + b_kh) * 2);

    float acc[2][4][4];
#pragma unroll
    for (int i = 0; i < 2; ++i)
#pragma unroll
        for (int j = 0; j < 4; ++j)
#pragma unroll
            for (int k = 0; k < 4; ++k) acc[i][j][k] = 0.0f;

    const int nstages = K / BK;

#define LOAD_STAGE(s) do {                                                      \
        const int _k0 = (s) * BK;                                               \
        const uint32_t _buf = sbase + ((s) % 3) * GBUF_B;                       \
        _Pragma("unroll")                                                       \
        for (int _i = 0; _i < 2; ++_i) {                                        \
            int _idx = tid + _i * 256;                                          \
            int _r = _idx >> 2, _c = _idx & 3;                                  \
            CP_ASYNC16(_buf + _r * (ASTR * 2) + _c * 16,                        \
                       Ahi + (size_t)(rowBase + _r) * K + _k0 + _c * 8);        \
            CP_ASYNC16(_buf + A_TILE_B + _r * (ASTR * 2) + _c * 16,             \
                       Alo + (size_t)(rowBase + _r) * K + _k0 + _c * 8);        \
        }                                                                       \
        {                                                                       \
            int _r = tid >> 2, _c = tid & 3;                                    \
            CP_ASYNC16(_buf + 2 * A_TILE_B + _r * (ASTR * 2) + _c * 16,         \
                       B + (size_t)(colBase + _r) * K + _k0 + _c * 8);          \
        }                                                                       \
        CP_COMMIT();                                                            \
    } while (0)

    LOAD_STAGE(0);
    LOAD_STAGE(1);

    for (int s = 0; s < nstages; ++s) {
        if (s + 2 < nstages) { LOAD_STAGE(s + 2); CP_WAIT(2); }
        else if (s + 1 < nstages) { CP_WAIT(1); }
        else { CP_WAIT(0); }
        __syncthreads();

        const uint32_t buf = sbase + (s % 3) * GBUF_B;
        const uint32_t smAh = buf;
        const uint32_t smAl = buf + A_TILE_B;
        const uint32_t smB  = buf + 2 * A_TILE_B;

#pragma unroll
        for (int kkk = 0; kkk < BK; kkk += 16) {
            uint32_t ah[2][4], al[2][4], bf[2][4];
#pragma unroll
            for (int mt = 0; mt < 2; ++mt) {
                LDSM_X4(ah[mt][0], ah[mt][1], ah[mt][2], ah[mt][3], smAh + aoff[mt] + kkk * 2);
                LDSM_X4(al[mt][0], al[mt][1], al[mt][2], al[mt][3], smAl + aoff[mt] + kkk * 2);
            }
#pragma unroll
            for (int np = 0; np < 2; ++np)
                LDSM_X4(bf[np][0], bf[np][1], bf[np][2], bf[np][3], smB + boff[np] + kkk * 2);
#pragma unroll
            for (int mt = 0; mt < 2; ++mt)
#pragma unroll
                for (int nt = 0; nt < 4; ++nt) {
                    uint32_t b0 = bf[nt >> 1][(nt & 1) * 2];
                    uint32_t b1 = bf[nt >> 1][(nt & 1) * 2 + 1];
                    mma_bb(acc[mt][nt], ah[mt], b0, b1);
                    mma_bb(acc[mt][nt], al[mt], b0, b1);
                }
        }
        __syncthreads();
    }

    if (MODE == 0) {
#pragma unroll
        for (int mt = 0; mt < 2; ++mt) {
            int r = rowBase + warp_m * 32 + mt * 16 + grp;
#pragma unroll
            for (int nt = 0; nt < 4; ++nt) {
                int c = colBase + warp_n * 32 + nt * 8 + tig * 2;
                *(float2*)(C + (size_t)r * N + c) = make_float2(acc[mt][nt][0], acc[mt][nt][1]);
                *(float2*)(C + (size_t)(r + 8) * N + c) = make_float2(acc[mt][nt][2], acc[mt][nt][3]);
            }
        }
    } else {
        // Fused qkv epilogue. colBase aligns with head boundaries (64 cols/head).
        const int sec = colBase >> 10;           // 0=q, 1=k, 2=v
        const int h = (colBase & 1023) >> 6;     // head index
#pragma unroll
        for (int mt = 0; mt < 2; ++mt) {
            const int r0 = rowBase + warp_m * 32 + mt * 16 + grp;
#pragma unroll
            for (int hf = 0; hf < 2; ++hf) {
                const int r = r0 + hf * 8;
                const int b = r >> 11;
                const int t = r & (TSEQ - 1);
                const size_t bhT = (size_t)(b * NHEAD + h) * TSEQ + t;
#pragma unroll
                for (int nt = 0; nt < 4; ++nt) {
                    float v0 = acc[mt][nt][hf * 2], v1 = acc[mt][nt][hf * 2 + 1];
                    const int dw = warp_n * 16 + nt * 4 + tig;   // word index in [0,32)
                    if (sec == 0) {
                        float q0 = v0 * QSCALE, q1 = v1 * QSCALE;
                        uint32_t hp = pack_h2(q0, q1);
                        float2 fr = __half22float2(*(__half2*)&hp);
                        qhi[bhT * 32 + dw] = hp;
                        qlo[bhT * 32 + dw] = pack_h2(q0 - fr.x, q1 - fr.y);
                    } else if (sec == 1) {
                        kk[bhT * 32 + dw] = pack_h2(v0, v1);
                    } else {
                        *(float2*)(v32 + bhT * 64 + dw * 2) = make_float2(v0, v1);
                    }
                }
            }
        }
    }
#undef LOAD_STAGE
}

// ---------------------------------------------------------------------------
// HMMA flash attention (fp16 2-product, ldmatrix): 128q x 64kv, double-buffered.
// ---------------------------------------------------------------------------
#define AQ  128
#define AKV 64
#define KSW 36
#define VSW 36
#define QHI_W 0
#define QLO_W 4608
#define STG0_W 9216
#define STG_SZ_W 4608
#define KOFF_W 0
#define VOFF_W 2304
#define ATTN_SMEM_B ((STG0_W + 2 * STG_SZ_W) * 4)   // 73728 bytes

__global__ __launch_bounds__(256, 2)
void attn_hmma_kernel(const __half* __restrict__ Qh, const __half* __restrict__ Ql,
                      const __half* __restrict__ Kt, const __half* __restrict__ Vt,
                      uint32_t* __restrict__ yhi, uint32_t* __restrict__ ylo)
{
    extern __shared__ uint32_t smw[];
    const uint32_t sbase = smem_u32(smw);
    const int tid = threadIdx.x;
    const int warp = tid >> 5;
    const int lane = tid & 31;
    const int grp = lane >> 2;
    const int tig = lane & 3;
    const int qb = (int)(gridDim.x - 1 - blockIdx.x);
    const int bh = blockIdx.y;
    const int q0 = qb * AQ;
    const size_t bhT = (size_t)bh * TSEQ;

    const int a_row = lane & 15;
    const int a_kh  = (lane >> 4) * 8;
    const int b_n   = (lane & 7) + ((lane >> 4) & 1) * 8;
    const int b_kh  = ((lane >> 3) & 1) * 8;

#pragma unroll
    for (int i = 0; i < 4; ++i) {
        int idx = tid + i * 256;
        int r = idx >> 3, c = idx & 7;
        CP_ASYNC16(sbase + (QHI_W + r * KSW) * 4 + c * 16, Qh + (bhT + q0 + r) * HDIM + c * 8);
        CP_ASYNC16(sbase + (QLO_W + r * KSW) * 4 + c * 16, Ql + (bhT + q0 + r) * HDIM + c * 8);
    }
    CP_COMMIT();

#define LOAD_KV(kb_, st_) do {                                                          \
        const int _kv0 = (kb_) * AKV;                                                  \
        const uint32_t _sb = sbase + (STG0_W + (st_) * STG_SZ_W) * 4;                   \
        _Pragma("unroll")                                                               \
        for (int _i = 0; _i < 2; ++_i) {                                                \
            int _idx = tid + _i * 256;                                                  \
            int _r = _idx >> 3, _c = _idx & 7;                                          \
            CP_ASYNC16(_sb + (KOFF_W + _r * KSW) * 4 + _c * 16,                         \
                       Kt + (bhT + _kv0 + _r) * HDIM + _c * 8);                         \
        }                                                                               \
        _Pragma("unroll")                                                               \
        for (int _i = 0; _i < 2; ++_i) {                                                \
            int _idx = tid + _i * 256;                                                  \
            int _r = _idx >> 3, _c = _idx & 7;                                          \
            CP_ASYNC16(_sb + (VOFF_W + _r * VSW) * 4 + _c * 16,                         \
                       Vt + ((size_t)bh * HDIM + _r) * TSEQ + _kv0 + _c * 8);           \
        }                                                                               \
        CP_COMMIT();                                                                    \
    } while (0)

    LOAD_KV(0, 0);
    CP_WAIT(0);
    __syncthreads();

    uint32_t qfh[4][4], qfl[4][4];
    {
        const uint32_t qrow = (uint32_t)((warp * 16 + a_row) * KSW);
#pragma unroll
        for (int ks = 0; ks < 4; ++ks) {
            uint32_t ao = sbase + (QHI_W + qrow) * 4 + (ks * 16 + a_kh) * 2;
            LDSM_X4(qfh[ks][0], qfh[ks][1], qfh[ks][2], qfh[ks][3], ao);
            uint32_t al_ = ao + (QLO_W - QHI_W) * 4;
            LDSM_X4(qfl[ks][0], qfl[ks][1], qfl[ks][2], qfl[ks][3], al_);
        }
    }

    float o[8][4];
#pragma unroll
    for (int i = 0; i < 8; ++i)
#pragma unroll
        for (int j = 0; j < 4; ++j) o[i][j] = 0.0f;
    float m0 = -1e30f, m1 = -1e30f, l0 = 0.0f, l1 = 0.0f;

    const int nkb = 2 * (qb + 1);
    for (int kb = 0; kb < nkb; ++kb) {
        if (kb) { CP_WAIT(0); __syncthreads(); }
        if (kb + 1 < nkb) LOAD_KV(kb + 1, (kb + 1) & 1);

        const uint32_t stw = STG0_W + (kb & 1) * STG_SZ_W;
        const uint32_t kW = stw + KOFF_W;
        const uint32_t vW = stw + VOFF_W;

        float s[8][4];
#pragma unroll
        for (int i = 0; i < 8; ++i)
            s[i][0] = s[i][1] = s[i][2] = s[i][3] = 0.0f;
#pragma unroll
        for (int np = 0; np < 4; ++np) {
            const uint32_t krow = sbase + (kW + (np * 16 + b_n) * KSW) * 4;
#pragma unroll
            for (int ks = 0; ks < 4; ++ks) {
                uint32_t b0, b1, b2, b3;
                LDSM_X4(b0, b1, b2, b3, krow + (ks * 16 + b_kh) * 2);
                mma_bb(s[np * 2],     qfh[ks], b0, b1);
                mma_bb(s[np * 2],     qfl[ks], b0, b1);
                mma_bb(s[np * 2 + 1], qfh[ks], b2, b3);
                mma_bb(s[np * 2 + 1], qfl[ks], b2, b3);
            }
        }

        if (kb >= nkb - 2) {
            const int kv0 = kb * AKV;
            const int r0g = q0 + warp * 16 + grp;
            const int r1g = r0g + 8;
#pragma unroll
            for (int nt = 0; nt < 8; ++nt) {
                int c0 = kv0 + nt * 8 + tig * 2;
                if (c0 > r0g)     s[nt][0] = -1e30f;
                if (c0 + 1 > r0g) s[nt][1] = -1e30f;
                if (c0 > r1g)     s[nt][2] = -1e30f;
                if (c0 + 1 > r1g) s[nt][3] = -1e30f;
            }
        }

        float mx0 = -1e30f, mx1 = -1e30f;
#pragma unroll
        for (int nt = 0; nt < 8; ++nt) {
            mx0 = fmaxf(mx0, fmaxf(s[nt][0], s[nt][1]));
            mx1 = fmaxf(mx1, fmaxf(s[nt][2], s[nt][3]));
        }
        mx0 = fmaxf(mx0, __shfl_xor_sync(0xffffffffu, mx0, 1));
        mx0 = fmaxf(mx0, __shfl_xor_sync(0xffffffffu, mx0, 2));
        mx1 = fmaxf(mx1, __shfl_xor_sync(0xffffffffu, mx1, 1));
        mx1 = fmaxf(mx1, __shfl_xor_sync(0xffffffffu, mx1, 2));
        float mn0 = fmaxf(m0, mx0), mn1 = fmaxf(m1, mx1);
        float a0 = exp2p(m0 - mn0), a1 = exp2p(m1 - mn1);
        m0 = mn0; m1 = mn1;
        l0 *= a0; l1 *= a1;
#pragma unroll
        for (int nt = 0; nt < 8; ++nt) {
            o[nt][0] *= a0; o[nt][1] *= a0;
            o[nt][2] *= a1; o[nt][3] *= a1;
        }
        float sum0 = 0.0f, sum1 = 0.0f;
#pragma unroll
        for (int nt = 0; nt < 8; ++nt) {
            float p0 = exp2p(s[nt][0] - m0);
            float p1 = exp2p(s[nt][1] - m0);
            float p2 = exp2p(s[nt][2] - m1);
            float p3 = exp2p(s[nt][3] - m1);
            sum0 += p0 + p1; sum1 += p2 + p3;
            s[nt][0] = p0; s[nt][1] = p1; s[nt][2] = p2; s[nt][3] = p3;
        }
        l0 += sum0; l1 += sum1;

#pragma unroll
        for (int j = 0; j < 4; ++j) {
            uint32_t ah4[4], al4[4];
#pragma unroll
            for (int u = 0; u < 2; ++u) {
                const float* pv = s[2 * j + u];
                uint32_t h01 = pack_h2(pv[0], pv[1]);
                uint32_t h23 = pack_h2(pv[2], pv[3]);
                float2 f01 = __half22float2(*(__half2*)&h01);
                float2 f23 = __half22float2(*(__half2*)&h23);
                ah4[u * 2 + 0] = h01;
                ah4[u * 2 + 1] = h23;
                al4[u * 2 + 0] = pack_h2(pv[0] - f01.x, pv[1] - f01.y);
                al4[u * 2 + 1] = pack_h2(pv[2] - f23.x, pv[3] - f23.y);
            }
#pragma unroll
            for (int np = 0; np < 4; ++np) {
                uint32_t v0, v1, v2, v3;
                uint32_t vrow = sbase + (vW + (np * 16 + b_n) * VSW) * 4;
                LDSM_X4(v0, v1, v2, v3, vrow + (j * 16 + b_kh) * 2);
                mma_bb(o[np * 2],     ah4, v0, v1);
                mma_bb(o[np * 2],     al4, v0, v1);
                mma_bb(o[np * 2 + 1], ah4, v2, v3);
                mma_bb(o[np * 2 + 1], al4, v2, v3);
            }
        }
    }

    l0 += __shfl_xor_sync(0xffffffffu, l0, 1);
    l0 += __shfl_xor_sync(0xffffffffu, l0, 2);
    l1 += __shfl_xor_sync(0xffffffffu, l1, 1);
    l1 += __shfl_xor_sync(0xffffffffu, l1, 2);
    const float inv0 = 1.0f / l0, inv1 = 1.0f / l1;

    const int b = bh >> 4, h = bh & 15;
    const int rowg = q0 + warp * 16 + grp;
    const size_t base0 = ((size_t)(b * TSEQ) + rowg) * (NEMBD / 2) + h * (HDIM / 2);
    const size_t base1 = base0 + 8 * (NEMBD / 2);
#pragma unroll
    for (int nt = 0; nt < 8; ++nt) {
        int cw = nt * 4 + tig;
        {
            float f0 = o[nt][0] * inv0, f1 = o[nt][1] * inv0;
            uint32_t hp = pack_h2(f0, f1);
            float2 fr = __half22float2(*(__half2*)&hp);
            yhi[base0 + cw] = hp;
            ylo[base0 + cw] = pack_h2(f0 - fr.x, f1 - fr.y);
        }
        {
            float f0 = o[nt][2] * inv1, f1 = o[nt][3] * inv1;
            uint32_t hp = pack_h2(f0, f1);
            float2 fr = __half22float2(*(__half2*)&hp);
            yhi[base1 + cw] = hp;
            ylo[base1 + cw] = pack_h2(f0 - fr.x, f1 - fr.y);
        }
    }
#undef LOAD_KV
}

// ---------------------------------------------------------------------------
// Launch
// ---------------------------------------------------------------------------
extern "C" void kernel_launch(void* const* d_in, const int* in_sizes, int n_in,
                              void* d_out, int out_size)
{
    const float* x      = (const float*)d_in[0];
    const float* w_attn = (const float*)d_in[1];
    const float* w_proj = (const float*)d_in[2];
    float* out = (float*)d_out;

    __half *ahi, *alo, *wq, *wp, *qhi, *qlo, *kk, *vt;
    float *v32;
    cudaGetSymbolAddress((void**)&ahi, g_a_hi);
    cudaGetSymbolAddress((void**)&alo, g_a_lo);
    cudaGetSymbolAddress((void**)&wq, g_wq);
    cudaGetSymbolAddress((void**)&wp, g_wp);
    cudaGetSymbolAddress((void**)&qhi, g_q_hi);
    cudaGetSymbolAddress((void**)&qlo, g_q_lo);
    cudaGetSymbolAddress((void**)&kk, g_k);
    cudaGetSymbolAddress((void**)&v32, g_v32);
    cudaGetSymbolAddress((void**)&vt, g_vt);

    cudaFuncSetAttribute(gemm_hmma2_kernel<0>,
                         cudaFuncAttributeMaxDynamicSharedMemorySize, GEMM_SMEM);
    cudaFuncSetAttribute(gemm_hmma2_kernel<1>,
                         cudaFuncAttributeMaxDynamicSharedMemorySize, GEMM_SMEM);
    cudaFuncSetAttribute(attn_hmma_kernel,
                         cudaFuncAttributeMaxDynamicSharedMemorySize, ATTN_SMEM_B);

    const int M = BATCH * TSEQ;   // 8192
    const int K = NEMBD;          // 1024
    const int N1 = 3 * NEMBD;     // 3072
    const int N2 = NEMBD;         // 1024

    // Split x -> fp16 hi/lo
    {
        int n4 = (M * K) / 4;
        split_kernel<<<(n4 + 255) / 256, 256>>>(x, ahi, alo, n4);
    }
    // Transpose weights -> fp16
    {
        dim3 g1(N1 / 32, K / 32);
        tsplit_kernel<<<g1, dim3(32, 8)>>>(w_attn, wq, K, N1);
        dim3 g2(N2 / 32, K / 32);
        tsplit_kernel<<<g2, dim3(32, 8)>>>(w_proj, wp, K, N2);
    }
    // Stage 1: fused qkv GEMM -> q hi/lo (scaled), k fp16, v fp32
    {
        dim3 grid(N1 / 64, M / 128);
        gemm_hmma2_kernel<1><<<grid, 256, GEMM_SMEM>>>(
            ahi, alo, wq, nullptr,
            (uint32_t*)qhi, (uint32_t*)qlo, (uint32_t*)kk, v32, N1, K);
    }
    // V transpose -> [bh][d][t] fp16
    {
        dim3 gv(TSEQ / 32, HDIM / 32, BH);
        v_tsplit_kernel<<<gv, dim3(32, 8)>>>(v32, vt);
    }
    // Stage 2: flash attention -> y (fp16 hi/lo into ahi/alo)
    {
        dim3 grid(TSEQ / AQ, BH);
        attn_hmma_kernel<<<grid, 256, ATTN_SMEM_B>>>(qhi, qlo, kk, vt,
                                                     (uint32_t*)ahi, (uint32_t*)alo);
    }
    // Stage 3: out = y @ w_proj
    {
        dim3 grid(N2 / 64, M / 128);
        gemm_hmma2_kernel<0><<<grid, 256, GEMM_SMEM>>>(
            ahi, alo, wp, out, nullptr, nullptr, nullptr, nullptr, N2, K);
    }
}

// round 9
// speedup vs baseline: 1.8567x; 1.3080x over previous
#include <cuda_runtime.h>
#include <cuda_fp16.h>
#include <math.h>
#include <stdint.h>

// Problem constants
#define NEMBD 1024
#define NHEAD 16
#define HDIM  64
#define TSEQ  2048
#define BATCH 4
#define BH    (BATCH * NHEAD)
#define QSCALE 0.18033688011112042f   // 0.125 * log2(e)

// ---------------------------------------------------------------------------
// Scratch (device globals)
// ---------------------------------------------------------------------------
__device__ __half g_a_hi[(size_t)BATCH * TSEQ * NEMBD];   // x hi, then y (single)
__device__ __half g_a_lo[(size_t)BATCH * TSEQ * NEMBD];   // x lo
__device__ __half g_wq[(size_t)3 * NEMBD * NEMBD];        // w_attn^T [3072][1024] fp16
__device__ __half g_wp[(size_t)NEMBD * NEMBD];            // w_proj^T [1024][1024] fp16
__device__ __half g_q_hi[(size_t)BH * TSEQ * HDIM];  // [bh][t][d], pre-scaled
__device__ __half g_q_lo[(size_t)BH * TSEQ * HDIM];
__device__ __half g_k[(size_t)BH * TSEQ * HDIM];     // [bh][t][d] single fp16
__device__ float  g_v32[(size_t)BH * TSEQ * HDIM];   // [bh][t][d] fp32 (pre-transpose)
__device__ __half g_vt[(size_t)BH * HDIM * TSEQ];    // [bh][d][t] single fp16

// ---------------------------------------------------------------------------
// PTX helpers (base ISA only)
// ---------------------------------------------------------------------------
__device__ __forceinline__ uint32_t smem_u32(const void* p) {
    uint32_t a;
    asm("{ .reg .u64 t; cvta.to.shared.u64 t, %1; cvt.u32.u64 %0, t; }" : "=r"(a) : "l"(p));
    return a;
}
#define CP_ASYNC16(sm, gm) \
    asm volatile("cp.async.cg.shared.global [%0], [%1], 16;" :: "r"(sm), "l"(gm))
#define CP_COMMIT() asm volatile("cp.async.commit_group;" ::: "memory")
#define CP_WAIT(n)  asm volatile("cp.async.wait_group %0;" :: "n"(n) : "memory")

#define LDSM_X4(r0, r1, r2, r3, a) \
    asm volatile("ldmatrix.sync.aligned.m8n8.x4.shared.b16 {%0,%1,%2,%3}, [%4];" \
        : "=r"(r0), "=r"(r1), "=r"(r2), "=r"(r3) : "r"(a))

__device__ __forceinline__ void mma_bb(float* c, const uint32_t* a, uint32_t b0, uint32_t b1) {
    asm volatile(
        "mma.sync.aligned.m16n8k16.row.col.f32.f16.f16.f32 "
        "{%0,%1,%2,%3}, {%4,%5,%6,%7}, {%8,%9}, {%0,%1,%2,%3};"
        : "+f"(c[0]), "+f"(c[1]), "+f"(c[2]), "+f"(c[3])
        : "r"(a[0]), "r"(a[1]), "r"(a[2]), "r"(a[3]), "r"(b0), "r"(b1));
}
__device__ __forceinline__ uint32_t pack_h2(float a, float b) {
    __half2 h = __floats2half2_rn(a, b);
    return *(uint32_t*)&h;
}
// FFMA-only 2^t (avoids MUFU)
__device__ __forceinline__ float exp2p(float t) {
    t = fmaxf(t, -126.0f);
    float fi = rintf(t);
    float f = t - fi;
    float p = 0.0013333558f;
    p = fmaf(p, f, 0.0096181291f);
    p = fmaf(p, f, 0.0555041087f);
    p = fmaf(p, f, 0.2402265070f);
    p = fmaf(p, f, 0.6931471806f);
    p = fmaf(p, f, 1.0f);
    int ii = (int)fi;
    return p * __int_as_float((uint32_t)(ii + 127) << 23);
}

// ---------------------------------------------------------------------------
// Conversion kernels
// ---------------------------------------------------------------------------
__global__ __launch_bounds__(256)
void split_kernel(const float* __restrict__ in, __half* __restrict__ hi,
                  __half* __restrict__ lo, int n4)
{
    int idx = blockIdx.x * blockDim.x + threadIdx.x;
    if (idx >= n4) return;
    float4 v = ((const float4*)in)[idx];
    __half h[4], l[4];
    float f[4] = {v.x, v.y, v.z, v.w};
#pragma unroll
    for (int i = 0; i < 4; ++i) {
        h[i] = __float2half_rn(f[i]);
        l[i] = __float2half_rn(f[i] - __half2float(h[i]));
    }
    ((uint2*)hi)[idx] = *(const uint2*)h;
    ((uint2*)lo)[idx] = *(const uint2*)l;
}

__global__ __launch_bounds__(256)
void tsplit_kernel(const float* __restrict__ w, __half* __restrict__ wt, int K, int N)
{
    __shared__ float t[32][33];
    const int n0 = blockIdx.x * 32;
    const int k0 = blockIdx.y * 32;
#pragma unroll
    for (int i = 0; i < 4; ++i) {
        int kk = threadIdx.y + i * 8;
        t[kk][threadIdx.x] = w[(size_t)(k0 + kk) * N + n0 + threadIdx.x];
    }
    __syncthreads();
#pragma unroll
    for (int i = 0; i < 4; ++i) {
        int nn = threadIdx.y + i * 8;
        int kk = threadIdx.x;
        wt[(size_t)(n0 + nn) * K + k0 + kk] = __float2half_rn(t[kk][nn]);
    }
}

// V transpose: g_v32 [bh][t][64] fp32 -> vt [bh][d][t] fp16.
__global__ __launch_bounds__(256)
void v_tsplit_kernel(const float* __restrict__ v32, __half* __restrict__ vt)
{
    __shared__ float sm[32][33];
    const int t0 = blockIdx.x * 32;
    const int d0 = blockIdx.y * 32;
    const int bh = blockIdx.z;
#pragma unroll
    for (int i = 0; i < 4; ++i) {
        int t = t0 + threadIdx.y + i * 8;
        sm[threadIdx.y + i * 8][threadIdx.x] =
            v32[((size_t)bh * TSEQ + t) * HDIM + d0 + threadIdx.x];
    }
    __syncthreads();
#pragma unroll
    for (int i = 0; i < 4; ++i) {
        int d = d0 + threadIdx.y + i * 8;
        int t = t0 + threadIdx.x;
        vt[((size_t)(bh * HDIM + d)) * TSEQ + t] = __float2half_rn(sm[threadIdx.x][threadIdx.y + i * 8]);
    }
}

// ---------------------------------------------------------------------------
// HMMA GEMM (fp16, ldmatrix, 3-stage pipeline). TWOPROD: A = Ahi+Alo.
// BM=128, BN=64, BK=32; 8 warps (4m x 2n), warp tile 32x32.
// MODE 0: plain fp32 C.  MODE 1: q epilogue (scaled hi/lo).  MODE 2: k/v epilogue.
// ---------------------------------------------------------------------------
#define BK 32
#define ASTR 40                          // half elems per smem row (32 + 8 pad)
#define A_TILE_B (128 * ASTR * 2)        // 10240 B
#define B_TILE_B (64 * ASTR * 2)         // 5120 B

template<int MODE, bool TWOPROD>
__global__ __launch_bounds__(256, 2)
void gemm_hmma_kernel(const __half* __restrict__ Ahi,
                      const __half* __restrict__ Alo,
                      const __half* __restrict__ B,
                      float* __restrict__ C,
                      uint32_t* __restrict__ qhi, uint32_t* __restrict__ qlo,
                      uint32_t* __restrict__ kk, float* __restrict__ v32,
                      int N, int K, int colOff)
{
    constexpr uint32_t NA = TWOPROD ? 2u : 1u;
    constexpr uint32_t GBUF = NA * A_TILE_B + B_TILE_B;
    extern __shared__ char smem[];
    const uint32_t sbase = smem_u32(smem);
    const int tid = threadIdx.x;
    const int wid = tid >> 5;
    const int lane = tid & 31;
    const int grp = lane >> 2;
    const int tig = lane & 3;
    const int warp_m = wid & 3;
    const int warp_n = wid >> 2;
    const int rowBase = blockIdx.y * 128;
    const int colBase = blockIdx.x * 64;          // within this launch's slice

    const int a_row = lane & 15;
    const int a_kh  = (lane >> 4) * 8;
    uint32_t aoff[2];
#pragma unroll
    for (int mt = 0; mt < 2; ++mt)
        aoff[mt] = (uint32_t)(((warp_m * 32 + mt * 16 + a_row) * ASTR + a_kh) * 2);
    const int b_n  = (lane & 7) + ((lane >> 4) & 1) * 8;
    const int b_kh = ((lane >> 3) & 1) * 8;
    uint32_t boff[2];
#pragma unroll
    for (int np = 0; np < 2; ++np)
        boff[np] = (uint32_t)(((warp_n * 32 + np * 16 + b_n) * ASTR + b_kh) * 2);

    float acc[2][4][4];
#pragma unroll
    for (int i = 0; i < 2; ++i)
#pragma unroll
        for (int j = 0; j < 4; ++j)
#pragma unroll
            for (int k = 0; k < 4; ++k) acc[i][j][k] = 0.0f;

    const int nstages = K / BK;

#define LOAD_STAGE(s) do {                                                      \
        const int _k0 = (s) * BK;                                               \
        const uint32_t _buf = sbase + ((s) % 3) * GBUF;                         \
        _Pragma("unroll")                                                       \
        for (int _i = 0; _i < 2; ++_i) {                                        \
            int _idx = tid + _i * 256;                                          \
            int _r = _idx >> 2, _c = _idx & 3;                                  \
            CP_ASYNC16(_buf + _r * (ASTR * 2) + _c * 16,                        \
                       Ahi + (size_t)(rowBase + _r) * K + _k0 + _c * 8);        \
            if (TWOPROD)                                                        \
                CP_ASYNC16(_buf + A_TILE_B + _r * (ASTR * 2) + _c * 16,         \
                           Alo + (size_t)(rowBase + _r) * K + _k0 + _c * 8);    \
        }                                                                       \
        {                                                                       \
            int _r = tid >> 2, _c = tid & 3;                                    \
            CP_ASYNC16(_buf + NA * A_TILE_B + _r * (ASTR * 2) + _c * 16,        \
                       B + (size_t)(colBase + _r) * K + _k0 + _c * 8);          \
        }                                                                       \
        CP_COMMIT();                                                            \
    } while (0)

    LOAD_STAGE(0);
    LOAD_STAGE(1);

    for (int s = 0; s < nstages; ++s) {
        if (s + 2 < nstages) { LOAD_STAGE(s + 2); CP_WAIT(2); }
        else if (s + 1 < nstages) { CP_WAIT(1); }
        else { CP_WAIT(0); }
        __syncthreads();

        const uint32_t buf = sbase + (s % 3) * GBUF;
        const uint32_t smAh = buf;
        const uint32_t smAl = buf + A_TILE_B;
        const uint32_t smB  = buf + NA * A_TILE_B;

#pragma unroll
        for (int kkk = 0; kkk < BK; kkk += 16) {
            uint32_t ah[2][4], al[2][4], bf[2][4];
#pragma unroll
            for (int mt = 0; mt < 2; ++mt) {
                LDSM_X4(ah[mt][0], ah[mt][1], ah[mt][2], ah[mt][3], smAh + aoff[mt] + kkk * 2);
                if (TWOPROD)
                    LDSM_X4(al[mt][0], al[mt][1], al[mt][2], al[mt][3], smAl + aoff[mt] + kkk * 2);
            }
#pragma unroll
            for (int np = 0; np < 2; ++np)
                LDSM_X4(bf[np][0], bf[np][1], bf[np][2], bf[np][3], smB + boff[np] + kkk * 2);
#pragma unroll
            for (int mt = 0; mt < 2; ++mt)
#pragma unroll
                for (int nt = 0; nt < 4; ++nt) {
                    uint32_t b0 = bf[nt >> 1][(nt & 1) * 2];
                    uint32_t b1 = bf[nt >> 1][(nt & 1) * 2 + 1];
                    mma_bb(acc[mt][nt], ah[mt], b0, b1);
                    if (TWOPROD) mma_bb(acc[mt][nt], al[mt], b0, b1);
                }
        }
        __syncthreads();
    }

    if (MODE == 0) {
#pragma unroll
        for (int mt = 0; mt < 2; ++mt) {
            int r = rowBase + warp_m * 32 + mt * 16 + grp;
#pragma unroll
            for (int nt = 0; nt < 4; ++nt) {
                int c = colBase + warp_n * 32 + nt * 8 + tig * 2;
                *(float2*)(C + (size_t)r * N + c) = make_float2(acc[mt][nt][0], acc[mt][nt][1]);
                *(float2*)(C + (size_t)(r + 8) * N + c) = make_float2(acc[mt][nt][2], acc[mt][nt][3]);
            }
        }
    } else {
        const int col = colOff + colBase;
        const int sec = col >> 10;               // 0=q, 1=k, 2=v
        const int h = (col & 1023) >> 6;
#pragma unroll
        for (int mt = 0; mt < 2; ++mt) {
            const int r0 = rowBase + warp_m * 32 + mt * 16 + grp;
#pragma unroll
            for (int hf = 0; hf < 2; ++hf) {
                const int r = r0 + hf * 8;
                const int b = r >> 11;
                const int t = r & (TSEQ - 1);
                const size_t bhT = (size_t)(b * NHEAD + h) * TSEQ + t;
#pragma unroll
                for (int nt = 0; nt < 4; ++nt) {
                    float v0 = acc[mt][nt][hf * 2], v1 = acc[mt][nt][hf * 2 + 1];
                    const int dw = warp_n * 16 + nt * 4 + tig;
                    if (MODE == 1) {
                        float q0 = v0 * QSCALE, q1 = v1 * QSCALE;
                        uint32_t hp = pack_h2(q0, q1);
                        float2 fr = __half22float2(*(__half2*)&hp);
                        qhi[bhT * 32 + dw] = hp;
                        qlo[bhT * 32 + dw] = pack_h2(q0 - fr.x, q1 - fr.y);
                    } else {
                        if (sec == 1) {
                            kk[bhT * 32 + dw] = pack_h2(v0, v1);
                        } else {
                            *(float2*)(v32 + bhT * 64 + dw * 2) = make_float2(v0, v1);
                        }
                    }
                }
            }
        }
    }
#undef LOAD_STAGE
}

// ---------------------------------------------------------------------------
// HMMA flash attention: S 2-product (Q hi/lo), P@V single product, y fp16 out.
// 128q x 64kv, double-buffered.
// ---------------------------------------------------------------------------
#define AQ  128
#define AKV 64
#define KSW 36
#define VSW 36
#define QHI_W 0
#define QLO_W 4608
#define STG0_W 9216
#define STG_SZ_W 4608
#define KOFF_W 0
#define VOFF_W 2304
#define ATTN_SMEM_B ((STG0_W + 2 * STG_SZ_W) * 4)   // 73728 bytes

__global__ __launch_bounds__(256, 2)
void attn_hmma_kernel(const __half* __restrict__ Qh, const __half* __restrict__ Ql,
                      const __half* __restrict__ Kt, const __half* __restrict__ Vt,
                      uint32_t* __restrict__ yhi)
{
    extern __shared__ uint32_t smw[];
    const uint32_t sbase = smem_u32(smw);
    const int tid = threadIdx.x;
    const int warp = tid >> 5;
    const int lane = tid & 31;
    const int grp = lane >> 2;
    const int tig = lane & 3;
    const int qb = (int)(gridDim.x - 1 - blockIdx.x);
    const int bh = blockIdx.y;
    const int q0 = qb * AQ;
    const size_t bhT = (size_t)bh * TSEQ;

    const int a_row = lane & 15;
    const int a_kh  = (lane >> 4) * 8;
    const int b_n   = (lane & 7) + ((lane >> 4) & 1) * 8;
    const int b_kh  = ((lane >> 3) & 1) * 8;

#pragma unroll
    for (int i = 0; i < 4; ++i) {
        int idx = tid + i * 256;
        int r = idx >> 3, c = idx & 7;
        CP_ASYNC16(sbase + (QHI_W + r * KSW) * 4 + c * 16, Qh + (bhT + q0 + r) * HDIM + c * 8);
        CP_ASYNC16(sbase + (QLO_W + r * KSW) * 4 + c * 16, Ql + (bhT + q0 + r) * HDIM + c * 8);
    }
    CP_COMMIT();

#define LOAD_KV(kb_, st_) do {                                                          \
        const int _kv0 = (kb_) * AKV;                                                  \
        const uint32_t _sb = sbase + (STG0_W + (st_) * STG_SZ_W) * 4;                   \
        _Pragma("unroll")                                                               \
        for (int _i = 0; _i < 2; ++_i) {                                                \
            int _idx = tid + _i * 256;                                                  \
            int _r = _idx >> 3, _c = _idx & 7;                                          \
            CP_ASYNC16(_sb + (KOFF_W + _r * KSW) * 4 + _c * 16,                         \
                       Kt + (bhT + _kv0 + _r) * HDIM + _c * 8);                         \
        }                                                                               \
        _Pragma("unroll")                                                               \
        for (int _i = 0; _i < 2; ++_i) {                                                \
            int _idx = tid + _i * 256;                                                  \
            int _r = _idx >> 3, _c = _idx & 7;                                          \
            CP_ASYNC16(_sb + (VOFF_W + _r * VSW) * 4 + _c * 16,                         \
                       Vt + ((size_t)bh * HDIM + _r) * TSEQ + _kv0 + _c * 8);           \
        }                                                                               \
        CP_COMMIT();                                                                    \
    } while (0)

    LOAD_KV(0, 0);
    CP_WAIT(0);
    __syncthreads();

    uint32_t qfh[4][4], qfl[4][4];
    {
        const uint32_t qrow = (uint32_t)((warp * 16 + a_row) * KSW);
#pragma unroll
        for (int ks = 0; ks < 4; ++ks) {
            uint32_t ao = sbase + (QHI_W + qrow) * 4 + (ks * 16 + a_kh) * 2;
            LDSM_X4(qfh[ks][0], qfh[ks][1], qfh[ks][2], qfh[ks][3], ao);
            uint32_t al_ = ao + (QLO_W - QHI_W) * 4;
            LDSM_X4(qfl[ks][0], qfl[ks][1], qfl[ks][2], qfl[ks][3], al_);
        }
    }

    float o[8][4];
#pragma unroll
    for (int i = 0; i < 8; ++i)
#pragma unroll
        for (int j = 0; j < 4; ++j) o[i][j] = 0.0f;
    float m0 = -1e30f, m1 = -1e30f, l0 = 0.0f, l1 = 0.0f;

    const int nkb = 2 * (qb + 1);
    for (int kb = 0; kb < nkb; ++kb) {
        if (kb) { CP_WAIT(0); __syncthreads(); }
        if (kb + 1 < nkb) LOAD_KV(kb + 1, (kb + 1) & 1);

        const uint32_t stw = STG0_W + (kb & 1) * STG_SZ_W;
        const uint32_t kW = stw + KOFF_W;
        const uint32_t vW = stw + VOFF_W;

        float s[8][4];
#pragma unroll
        for (int i = 0; i < 8; ++i)
            s[i][0] = s[i][1] = s[i][2] = s[i][3] = 0.0f;
#pragma unroll
        for (int np = 0; np < 4; ++np) {
            const uint32_t krow = sbase + (kW + (np * 16 + b_n) * KSW) * 4;
#pragma unroll
            for (int ks = 0; ks < 4; ++ks) {
                uint32_t b0, b1, b2, b3;
                LDSM_X4(b0, b1, b2, b3, krow + (ks * 16 + b_kh) * 2);
                mma_bb(s[np * 2],     qfh[ks], b0, b1);
                mma_bb(s[np * 2],     qfl[ks], b0, b1);
                mma_bb(s[np * 2 + 1], qfh[ks], b2, b3);
                mma_bb(s[np * 2 + 1], qfl[ks], b2, b3);
            }
        }

        if (kb >= nkb - 2) {
            const int kv0 = kb * AKV;
            const int r0g = q0 + warp * 16 + grp;
            const int r1g = r0g + 8;
#pragma unroll
            for (int nt = 0; nt < 8; ++nt) {
                int c0 = kv0 + nt * 8 + tig * 2;
                if (c0 > r0g)     s[nt][0] = -1e30f;
                if (c0 + 1 > r0g) s[nt][1] = -1e30f;
                if (c0 > r1g)     s[nt][2] = -1e30f;
                if (c0 + 1 > r1g) s[nt][3] = -1e30f;
            }
        }

        float mx0 = -1e30f, mx1 = -1e30f;
#pragma unroll
        for (int nt = 0; nt < 8; ++nt) {
            mx0 = fmaxf(mx0, fmaxf(s[nt][0], s[nt][1]));
            mx1 = fmaxf(mx1, fmaxf(s[nt][2], s[nt][3]));
        }
        mx0 = fmaxf(mx0, __shfl_xor_sync(0xffffffffu, mx0, 1));
        mx0 = fmaxf(mx0, __shfl_xor_sync(0xffffffffu, mx0, 2));
        mx1 = fmaxf(mx1, __shfl_xor_sync(0xffffffffu, mx1, 1));
        mx1 = fmaxf(mx1, __shfl_xor_sync(0xffffffffu, mx1, 2));
        float mn0 = fmaxf(m0, mx0), mn1 = fmaxf(m1, mx1);
        float a0 = exp2p(m0 - mn0), a1 = exp2p(m1 - mn1);
        m0 = mn0; m1 = mn1;
        l0 *= a0; l1 *= a1;
#pragma unroll
        for (int nt = 0; nt < 8; ++nt) {
            o[nt][0] *= a0; o[nt][1] *= a0;
            o[nt][2] *= a1; o[nt][3] *= a1;
        }
        float sum0 = 0.0f, sum1 = 0.0f;
#pragma unroll
        for (int nt = 0; nt < 8; ++nt) {
            float p0 = exp2p(s[nt][0] - m0);
            float p1 = exp2p(s[nt][1] - m0);
            float p2 = exp2p(s[nt][2] - m1);
            float p3 = exp2p(s[nt][3] - m1);
            sum0 += p0 + p1; sum1 += p2 + p3;
            s[nt][0] = p0; s[nt][1] = p1; s[nt][2] = p2; s[nt][3] = p3;
        }
        l0 += sum0; l1 += sum1;

        // O += P @ V (single product, P fp16)
#pragma unroll
        for (int j = 0; j < 4; ++j) {
            uint32_t ah4[4];
#pragma unroll
            for (int u = 0; u < 2; ++u) {
                const float* pv = s[2 * j + u];
                ah4[u * 2 + 0] = pack_h2(pv[0], pv[1]);
                ah4[u * 2 + 1] = pack_h2(pv[2], pv[3]);
            }
#pragma unroll
            for (int np = 0; np < 4; ++np) {
                uint32_t v0, v1, v2, v3;
                uint32_t vrow = sbase + (vW + (np * 16 + b_n) * VSW) * 4;
                LDSM_X4(v0, v1, v2, v3, vrow + (j * 16 + b_kh) * 2);
                mma_bb(o[np * 2],     ah4, v0, v1);
                mma_bb(o[np * 2 + 1], ah4, v2, v3);
            }
        }
    }

    l0 += __shfl_xor_sync(0xffffffffu, l0, 1);
    l0 += __shfl_xor_sync(0xffffffffu, l0, 2);
    l1 += __shfl_xor_sync(0xffffffffu, l1, 1);
    l1 += __shfl_xor_sync(0xffffffffu, l1, 2);
    const float inv0 = 1.0f / l0, inv1 = 1.0f / l1;

    const int b = bh >> 4, h = bh & 15;
    const int rowg = q0 + warp * 16 + grp;
    const size_t base0 = ((size_t)(b * TSEQ) + rowg) * (NEMBD / 2) + h * (HDIM / 2);
    const size_t base1 = base0 + 8 * (NEMBD / 2);
#pragma unroll
    for (int nt = 0; nt < 8; ++nt) {
        int cw = nt * 4 + tig;
        yhi[base0 + cw] = pack_h2(o[nt][0] * inv0, o[nt][1] * inv0);
        yhi[base1 + cw] = pack_h2(o[nt][2] * inv1, o[nt][3] * inv1);
    }
#undef LOAD_KV
}

// ---------------------------------------------------------------------------
// Launch
// ---------------------------------------------------------------------------
extern "C" void kernel_launch(void* const* d_in, const int* in_sizes, int n_in,
                              void* d_out, int out_size)
{
    const float* x      = (const float*)d_in[0];
    const float* w_attn = (const float*)d_in[1];
    const float* w_proj = (const float*)d_in[2];
    float* out = (float*)d_out;

    __half *ahi, *alo, *wq, *wp, *qhi, *qlo, *kk, *vt;
    float *v32;
    cudaGetSymbolAddress((void**)&ahi, g_a_hi);
    cudaGetSymbolAddress((void**)&alo, g_a_lo);
    cudaGetSymbolAddress((void**)&wq, g_wq);
    cudaGetSymbolAddress((void**)&wp, g_wp);
    cudaGetSymbolAddress((void**)&qhi, g_q_hi);
    cudaGetSymbolAddress((void**)&qlo, g_q_lo);
    cudaGetSymbolAddress((void**)&kk, g_k);
    cudaGetSymbolAddress((void**)&v32, g_v32);
    cudaGetSymbolAddress((void**)&vt, g_vt);

    const int SM2 = 3 * (2 * A_TILE_B + B_TILE_B);  // two-product smem
    const int SM1 = 3 * (A_TILE_B + B_TILE_B);      // single-product smem
    cudaFuncSetAttribute(gemm_hmma_kernel<1, true>,
                         cudaFuncAttributeMaxDynamicSharedMemorySize, SM2);
    cudaFuncSetAttribute(gemm_hmma_kernel<2, false>,
                         cudaFuncAttributeMaxDynamicSharedMemorySize, SM1);
    cudaFuncSetAttribute(gemm_hmma_kernel<0, false>,
                         cudaFuncAttributeMaxDynamicSharedMemorySize, SM1);
    cudaFuncSetAttribute(attn_hmma_kernel,
                         cudaFuncAttributeMaxDynamicSharedMemorySize, ATTN_SMEM_B);

    const int M = BATCH * TSEQ;   // 8192
    const int K = NEMBD;          // 1024

    // Split x -> fp16 hi/lo
    {
        int n4 = (M * K) / 4;
        split_kernel<<<(n4 + 255) / 256, 256>>>(x, ahi, alo, n4);
    }
    // Transpose weights -> fp16
    {
        dim3 g1((3 * NEMBD) / 32, K / 32);
        tsplit_kernel<<<g1, dim3(32, 8)>>>(w_attn, wq, K, 3 * NEMBD);
        dim3 g2(NEMBD / 32, K / 32);
        tsplit_kernel<<<g2, dim3(32, 8)>>>(w_proj, wp, K, NEMBD);
    }
    // Stage 1a: q columns (2-product) -> q hi/lo scaled
    {
        dim3 grid(NEMBD / 64, M / 128);
        gemm_hmma_kernel<1, true><<<grid, 256, SM2>>>(
            ahi, alo, wq, nullptr,
            (uint32_t*)qhi, (uint32_t*)qlo, nullptr, nullptr, 0, K, 0);
    }
    // Stage 1b: k,v columns (1-product) -> k fp16, v fp32
    {
        dim3 grid((2 * NEMBD) / 64, M / 128);
        gemm_hmma_kernel<2, false><<<grid, 256, SM1>>>(
            ahi, nullptr, wq + (size_t)NEMBD * K, nullptr,
            nullptr, nullptr, (uint32_t*)kk, v32, 0, K, NEMBD);
    }
    // V transpose -> [bh][d][t] fp16
    {
        dim3 gv(TSEQ / 32, HDIM / 32, BH);
        v_tsplit_kernel<<<gv, dim3(32, 8)>>>(v32, vt);
    }
    // Stage 2: flash attention -> y fp16 (into g_a_hi)
    {
        dim3 grid(TSEQ / AQ, BH);
        attn_hmma_kernel<<<grid, 256, ATTN_SMEM_B>>>(qhi, qlo, kk, vt, (uint32_t*)ahi);
    }
    // Stage 3: out = y @ w_proj (1-product)
    {
        dim3 grid(NEMBD / 64, M / 128);
        gemm_hmma_kernel<0, false><<<grid, 256, SM1>>>(
            ahi, nullptr, wp, out, nullptr, nullptr, nullptr, nullptr, NEMBD, K, 0);
    }
}

// round 10
// speedup vs baseline: 1.9748x; 1.0636x over previous
#include <cuda_runtime.h>
#include <cuda_fp16.h>
#include <math.h>
#include <stdint.h>

// Problem constants
#define NEMBD 1024
#define NHEAD 16
#define HDIM  64
#define TSEQ  2048
#define BATCH 4
#define BH    (BATCH * NHEAD)
#define QSCALE 0.18033688011112042f   // 0.125 * log2(e)

// ---------------------------------------------------------------------------
// Scratch (device globals)
// ---------------------------------------------------------------------------
__device__ __half g_a_hi[(size_t)BATCH * TSEQ * NEMBD];   // x hi, then y (single)
__device__ __half g_a_lo[(size_t)BATCH * TSEQ * NEMBD];   // x lo
__device__ __half g_wq[(size_t)3 * NEMBD * NEMBD];        // w_attn^T [3072][1024] fp16
__device__ __half g_wp[(size_t)NEMBD * NEMBD];            // w_proj^T [1024][1024] fp16
__device__ __half g_q_hi[(size_t)BH * TSEQ * HDIM];
__device__ __half g_q_lo[(size_t)BH * TSEQ * HDIM];
__device__ __half g_k[(size_t)BH * TSEQ * HDIM];
__device__ float  g_v32[(size_t)BH * TSEQ * HDIM];
__device__ __half g_vt[(size_t)BH * HDIM * TSEQ];

// ---------------------------------------------------------------------------
// PTX helpers
// ---------------------------------------------------------------------------
__device__ __forceinline__ uint32_t smem_u32(const void* p) {
    uint32_t a;
    asm("{ .reg .u64 t; cvta.to.shared.u64 t, %1; cvt.u32.u64 %0, t; }" : "=r"(a) : "l"(p));
    return a;
}
#define CP_ASYNC16(sm, gm) \
    asm volatile("cp.async.cg.shared.global [%0], [%1], 16;" :: "r"(sm), "l"(gm))
#define CP_COMMIT() asm volatile("cp.async.commit_group;" ::: "memory")
#define CP_WAIT(n)  asm volatile("cp.async.wait_group %0;" :: "n"(n) : "memory")

#define LDSM_X4(r0, r1, r2, r3, a) \
    asm volatile("ldmatrix.sync.aligned.m8n8.x4.shared.b16 {%0,%1,%2,%3}, [%4];" \
        : "=r"(r0), "=r"(r1), "=r"(r2), "=r"(r3) : "r"(a))

__device__ __forceinline__ void mma_bb(float* c, const uint32_t* a, uint32_t b0, uint32_t b1) {
    asm volatile(
        "mma.sync.aligned.m16n8k16.row.col.f32.f16.f16.f32 "
        "{%0,%1,%2,%3}, {%4,%5,%6,%7}, {%8,%9}, {%0,%1,%2,%3};"
        : "+f"(c[0]), "+f"(c[1]), "+f"(c[2]), "+f"(c[3])
        : "r"(a[0]), "r"(a[1]), "r"(a[2]), "r"(a[3]), "r"(b0), "r"(b1));
}
__device__ __forceinline__ uint32_t pack_h2(float a, float b) {
    __half2 h = __floats2half2_rn(a, b);
    return *(uint32_t*)&h;
}
__device__ __forceinline__ float exp2p(float t) {
    t = fmaxf(t, -126.0f);
    float fi = rintf(t);
    float f = t - fi;
    float p = 0.0013333558f;
    p = fmaf(p, f, 0.0096181291f);
    p = fmaf(p, f, 0.0555041087f);
    p = fmaf(p, f, 0.2402265070f);
    p = fmaf(p, f, 0.6931471806f);
    p = fmaf(p, f, 1.0f);
    int ii = (int)fi;
    return p * __int_as_float((uint32_t)(ii + 127) << 23);
}

// ---------------------------------------------------------------------------
// Conversion kernels
// ---------------------------------------------------------------------------
__global__ __launch_bounds__(256)
void split_kernel(const float* __restrict__ in, __half* __restrict__ hi,
                  __half* __restrict__ lo, int n4)
{
    int idx = blockIdx.x * blockDim.x + threadIdx.x;
    if (idx >= n4) return;
    float4 v = ((const float4*)in)[idx];
    __half h[4], l[4];
    float f[4] = {v.x, v.y, v.z, v.w};
#pragma unroll
    for (int i = 0; i < 4; ++i) {
        h[i] = __float2half_rn(f[i]);
        l[i] = __float2half_rn(f[i] - __half2float(h[i]));
    }
    ((uint2*)hi)[idx] = *(const uint2*)h;
    ((uint2*)lo)[idx] = *(const uint2*)l;
}

__global__ __launch_bounds__(256)
void tsplit_kernel(const float* __restrict__ w, __half* __restrict__ wt, int K, int N)
{
    __shared__ float t[32][33];
    const int n0 = blockIdx.x * 32;
    const int k0 = blockIdx.y * 32;
#pragma unroll
    for (int i = 0; i < 4; ++i) {
        int kk = threadIdx.y + i * 8;
        t[kk][threadIdx.x] = w[(size_t)(k0 + kk) * N + n0 + threadIdx.x];
    }
    __syncthreads();
#pragma unroll
    for (int i = 0; i < 4; ++i) {
        int nn = threadIdx.y + i * 8;
        int kk = threadIdx.x;
        wt[(size_t)(n0 + nn) * K + k0 + kk] = __float2half_rn(t[kk][nn]);
    }
}

__global__ __launch_bounds__(256)
void v_tsplit_kernel(const float* __restrict__ v32, __half* __restrict__ vt)
{
    __shared__ float sm[32][33];
    const int t0 = blockIdx.x * 32;
    const int d0 = blockIdx.y * 32;
    const int bh = blockIdx.z;
#pragma unroll
    for (int i = 0; i < 4; ++i) {
        int t = t0 + threadIdx.y + i * 8;
        sm[threadIdx.y + i * 8][threadIdx.x] =
            v32[((size_t)bh * TSEQ + t) * HDIM + d0 + threadIdx.x];
    }
    __syncthreads();
#pragma unroll
    for (int i = 0; i < 4; ++i) {
        int d = d0 + threadIdx.y + i * 8;
        int t = t0 + threadIdx.x;
        vt[((size_t)(bh * HDIM + d)) * TSEQ + t] = __float2half_rn(sm[threadIdx.x][threadIdx.y + i * 8]);
    }
}

// ---------------------------------------------------------------------------
// Shared tile constants
// ---------------------------------------------------------------------------
#define BK 32
#define ASTR 40
#define A_TILE_B (128 * ASTR * 2)        // 10240 B (128 rows x 32 halfs + pad)
#define B64_TILE_B (64 * ASTR * 2)       // 5120 B
#define B128_TILE_B (128 * ASTR * 2)     // 10240 B

// ---------------------------------------------------------------------------
// 2-product GEMM, BN=64 (q path). MODE 1: q epilogue (scaled hi/lo).
// ---------------------------------------------------------------------------
#define GBUF2 (2 * A_TILE_B + B64_TILE_B)   // 25600
#define SMEM2 (3 * GBUF2)                    // 76800

__global__ __launch_bounds__(256, 2)
void gemm_q_kernel(const __half* __restrict__ Ahi,
                   const __half* __restrict__ Alo,
                   const __half* __restrict__ B,
                   uint32_t* __restrict__ qhi, uint32_t* __restrict__ qlo,
                   int K)
{
    extern __shared__ char smem[];
    const uint32_t sbase = smem_u32(smem);
    const int tid = threadIdx.x;
    const int wid = tid >> 5;
    const int lane = tid & 31;
    const int grp = lane >> 2;
    const int tig = lane & 3;
    const int warp_m = wid & 3;
    const int warp_n = wid >> 2;
    const int rowBase = blockIdx.y * 128;
    const int colBase = blockIdx.x * 64;

    const int a_row = lane & 15;
    const int a_kh  = (lane >> 4) * 8;
    uint32_t aoff[2];
#pragma unroll
    for (int mt = 0; mt < 2; ++mt)
        aoff[mt] = (uint32_t)(((warp_m * 32 + mt * 16 + a_row) * ASTR + a_kh) * 2);
    const int b_n  = (lane & 7) + ((lane >> 4) & 1) * 8;
    const int b_kh = ((lane >> 3) & 1) * 8;
    uint32_t boff[2];
#pragma unroll
    for (int np = 0; np < 2; ++np)
        boff[np] = (uint32_t)(((warp_n * 32 + np * 16 + b_n) * ASTR + b_kh) * 2);

    float acc[2][4][4];
#pragma unroll
    for (int i = 0; i < 2; ++i)
#pragma unroll
        for (int j = 0; j < 4; ++j)
#pragma unroll
            for (int k = 0; k < 4; ++k) acc[i][j][k] = 0.0f;

    const int nstages = K / BK;

#define LOAD_STAGE_Q(s) do {                                                    \
        const int _k0 = (s) * BK;                                               \
        const uint32_t _buf = sbase + ((s) % 3) * GBUF2;                        \
        _Pragma("unroll")                                                       \
        for (int _i = 0; _i < 2; ++_i) {                                        \
            int _idx = tid + _i * 256;                                          \
            int _r = _idx >> 2, _c = _idx & 3;                                  \
            CP_ASYNC16(_buf + _r * (ASTR * 2) + _c * 16,                        \
                       Ahi + (size_t)(rowBase + _r) * K + _k0 + _c * 8);        \
            CP_ASYNC16(_buf + A_TILE_B + _r * (ASTR * 2) + _c * 16,             \
                       Alo + (size_t)(rowBase + _r) * K + _k0 + _c * 8);        \
        }                                                                       \
        {                                                                       \
            int _r = tid >> 2, _c = tid & 3;                                    \
            CP_ASYNC16(_buf + 2 * A_TILE_B + _r * (ASTR * 2) + _c * 16,         \
                       B + (size_t)(colBase + _r) * K + _k0 + _c * 8);          \
        }                                                                       \
        CP_COMMIT();                                                            \
    } while (0)

    LOAD_STAGE_Q(0);
    LOAD_STAGE_Q(1);

    for (int s = 0; s < nstages; ++s) {
        if (s + 2 < nstages) { LOAD_STAGE_Q(s + 2); CP_WAIT(2); }
        else if (s + 1 < nstages) { CP_WAIT(1); }
        else { CP_WAIT(0); }
        __syncthreads();

        const uint32_t buf = sbase + (s % 3) * GBUF2;
        const uint32_t smAh = buf;
        const uint32_t smAl = buf + A_TILE_B;
        const uint32_t smB  = buf + 2 * A_TILE_B;

#pragma unroll
        for (int kkk = 0; kkk < BK; kkk += 16) {
            uint32_t ah[2][4], al[2][4], bf[2][4];
#pragma unroll
            for (int mt = 0; mt < 2; ++mt) {
                LDSM_X4(ah[mt][0], ah[mt][1], ah[mt][2], ah[mt][3], smAh + aoff[mt] + kkk * 2);
                LDSM_X4(al[mt][0], al[mt][1], al[mt][2], al[mt][3], smAl + aoff[mt] + kkk * 2);
            }
#pragma unroll
            for (int np = 0; np < 2; ++np)
                LDSM_X4(bf[np][0], bf[np][1], bf[np][2], bf[np][3], smB + boff[np] + kkk * 2);
#pragma unroll
            for (int mt = 0; mt < 2; ++mt)
#pragma unroll
                for (int nt = 0; nt < 4; ++nt) {
                    uint32_t b0 = bf[nt >> 1][(nt & 1) * 2];
                    uint32_t b1 = bf[nt >> 1][(nt & 1) * 2 + 1];
                    mma_bb(acc[mt][nt], ah[mt], b0, b1);
                    mma_bb(acc[mt][nt], al[mt], b0, b1);
                }
        }
        __syncthreads();
    }

    // q epilogue (col range [0,1024): one head per 64-col block)
    const int h = colBase >> 6;
#pragma unroll
    for (int mt = 0; mt < 2; ++mt) {
        const int r0 = rowBase + warp_m * 32 + mt * 16 + grp;
#pragma unroll
        for (int hf = 0; hf < 2; ++hf) {
            const int r = r0 + hf * 8;
            const int b = r >> 11;
            const int t = r & (TSEQ - 1);
            const size_t bhT = (size_t)(b * NHEAD + h) * TSEQ + t;
#pragma unroll
            for (int nt = 0; nt < 4; ++nt) {
                float v0 = acc[mt][nt][hf * 2], v1 = acc[mt][nt][hf * 2 + 1];
                const int dw = warp_n * 16 + nt * 4 + tig;
                float q0 = v0 * QSCALE, q1 = v1 * QSCALE;
                uint32_t hp = pack_h2(q0, q1);
                float2 fr = __half22float2(*(__half2*)&hp);
                qhi[bhT * 32 + dw] = hp;
                qlo[bhT * 32 + dw] = pack_h2(q0 - fr.x, q1 - fr.y);
            }
        }
    }
#undef LOAD_STAGE_Q
}

// ---------------------------------------------------------------------------
// 1-product GEMM, BN=128 (k/v and proj paths). 8 warps (4m x 2n), warp 32x64.
// MODE 0: fp32 C.  MODE 2: k/v epilogue.
// ---------------------------------------------------------------------------
#define GBUFW (A_TILE_B + B128_TILE_B)   // 20480
#define SMEMW (3 * GBUFW)                 // 61440

template<int MODE>
__global__ __launch_bounds__(256, 2)
void gemm_wide_kernel(const __half* __restrict__ Ahi,
                      const __half* __restrict__ B,
                      float* __restrict__ C,
                      uint32_t* __restrict__ kk, float* __restrict__ v32,
                      int N, int K, int colOff)
{
    extern __shared__ char smem[];
    const uint32_t sbase = smem_u32(smem);
    const int tid = threadIdx.x;
    const int wid = tid >> 5;
    const int lane = tid & 31;
    const int grp = lane >> 2;
    const int tig = lane & 3;
    const int warp_m = wid & 3;
    const int warp_n = wid >> 2;
    const int rowBase = blockIdx.y * 128;
    const int colBase = blockIdx.x * 128;

    const int a_row = lane & 15;
    const int a_kh  = (lane >> 4) * 8;
    uint32_t aoff[2];
#pragma unroll
    for (int mt = 0; mt < 2; ++mt)
        aoff[mt] = (uint32_t)(((warp_m * 32 + mt * 16 + a_row) * ASTR + a_kh) * 2);
    const int b_n  = (lane & 7) + ((lane >> 4) & 1) * 8;
    const int b_kh = ((lane >> 3) & 1) * 8;
    uint32_t boff[4];
#pragma unroll
    for (int np = 0; np < 4; ++np)
        boff[np] = (uint32_t)(((warp_n * 64 + np * 16 + b_n) * ASTR + b_kh) * 2);

    float acc[2][8][4];
#pragma unroll
    for (int i = 0; i < 2; ++i)
#pragma unroll
        for (int j = 0; j < 8; ++j)
#pragma unroll
            for (int k = 0; k < 4; ++k) acc[i][j][k] = 0.0f;

    const int nstages = K / BK;

#define LOAD_STAGE_W(s) do {                                                    \
        const int _k0 = (s) * BK;                                               \
        const uint32_t _buf = sbase + ((s) % 3) * GBUFW;                        \
        _Pragma("unroll")                                                       \
        for (int _i = 0; _i < 2; ++_i) {                                        \
            int _idx = tid + _i * 256;                                          \
            int _r = _idx >> 2, _c = _idx & 3;                                  \
            CP_ASYNC16(_buf + _r * (ASTR * 2) + _c * 16,                        \
                       Ahi + (size_t)(rowBase + _r) * K + _k0 + _c * 8);        \
            CP_ASYNC16(_buf + A_TILE_B + _r * (ASTR * 2) + _c * 16,             \
                       B + (size_t)(colBase + _r) * K + _k0 + _c * 8);          \
        }                                                                       \
        CP_COMMIT();                                                            \
    } while (0)

    LOAD_STAGE_W(0);
    LOAD_STAGE_W(1);

    for (int s = 0; s < nstages; ++s) {
        if (s + 2 < nstages) { LOAD_STAGE_W(s + 2); CP_WAIT(2); }
        else if (s + 1 < nstages) { CP_WAIT(1); }
        else { CP_WAIT(0); }
        __syncthreads();

        const uint32_t buf = sbase + (s % 3) * GBUFW;
        const uint32_t smA = buf;
        const uint32_t smB = buf + A_TILE_B;

#pragma unroll
        for (int kkk = 0; kkk < BK; kkk += 16) {
            uint32_t ah[2][4], bf[4][4];
#pragma unroll
            for (int mt = 0; mt < 2; ++mt)
                LDSM_X4(ah[mt][0], ah[mt][1], ah[mt][2], ah[mt][3], smA + aoff[mt] + kkk * 2);
#pragma unroll
            for (int np = 0; np < 4; ++np)
                LDSM_X4(bf[np][0], bf[np][1], bf[np][2], bf[np][3], smB + boff[np] + kkk * 2);
#pragma unroll
            for (int mt = 0; mt < 2; ++mt)
#pragma unroll
                for (int nt = 0; nt < 8; ++nt) {
                    uint32_t b0 = bf[nt >> 1][(nt & 1) * 2];
                    uint32_t b1 = bf[nt >> 1][(nt & 1) * 2 + 1];
                    mma_bb(acc[mt][nt], ah[mt], b0, b1);
                }
        }
        __syncthreads();
    }

    if (MODE == 0) {
#pragma unroll
        for (int mt = 0; mt < 2; ++mt) {
            int r = rowBase + warp_m * 32 + mt * 16 + grp;
#pragma unroll
            for (int nt = 0; nt < 8; ++nt) {
                int c = colBase + warp_n * 64 + nt * 8 + tig * 2;
                *(float2*)(C + (size_t)r * N + c) = make_float2(acc[mt][nt][0], acc[mt][nt][1]);
                *(float2*)(C + (size_t)(r + 8) * N + c) = make_float2(acc[mt][nt][2], acc[mt][nt][3]);
            }
        }
    } else {
        // k/v epilogue (col range [1024,3072))
#pragma unroll
        for (int mt = 0; mt < 2; ++mt) {
            const int r0 = rowBase + warp_m * 32 + mt * 16 + grp;
#pragma unroll
            for (int hf = 0; hf < 2; ++hf) {
                const int r = r0 + hf * 8;
                const int b = r >> 11;
                const int t = r & (TSEQ - 1);
#pragma unroll
                for (int nt = 0; nt < 8; ++nt) {
                    const int col = colOff + colBase + warp_n * 64 + nt * 8;
                    const int sec = col >> 10;           // 1=k, 2=v
                    const int h = (col & 1023) >> 6;
                    const int dw = ((col & 63) >> 1) + tig;
                    const size_t bhT = (size_t)(b * NHEAD + h) * TSEQ + t;
                    float v0 = acc[mt][nt][hf * 2], v1 = acc[mt][nt][hf * 2 + 1];
                    if (sec == 1) {
                        kk[bhT * 32 + dw] = pack_h2(v0, v1);
                    } else {
                        *(float2*)(v32 + bhT * 64 + dw * 2) = make_float2(v0, v1);
                    }
                }
            }
        }
    }
#undef LOAD_STAGE_W
}

// ---------------------------------------------------------------------------
// HMMA flash attention: S 2-product (Q hi/lo), P@V single product, y fp16 out.
// ---------------------------------------------------------------------------
#define AQ  128
#define AKV 64
#define KSW 36
#define VSW 36
#define QHI_W 0
#define QLO_W 4608
#define STG0_W 9216
#define STG_SZ_W 4608
#define KOFF_W 0
#define VOFF_W 2304
#define ATTN_SMEM_B ((STG0_W + 2 * STG_SZ_W) * 4)   // 73728 bytes

__global__ __launch_bounds__(256, 2)
void attn_hmma_kernel(const __half* __restrict__ Qh, const __half* __restrict__ Ql,
                      const __half* __restrict__ Kt, const __half* __restrict__ Vt,
                      uint32_t* __restrict__ yhi)
{
    extern __shared__ uint32_t smw[];
    const uint32_t sbase = smem_u32(smw);
    const int tid = threadIdx.x;
    const int warp = tid >> 5;
    const int lane = tid & 31;
    const int grp = lane >> 2;
    const int tig = lane & 3;
    const int qb = (int)(gridDim.x - 1 - blockIdx.x);
    const int bh = blockIdx.y;
    const int q0 = qb * AQ;
    const size_t bhT = (size_t)bh * TSEQ;

    const int a_row = lane & 15;
    const int a_kh  = (lane >> 4) * 8;
    const int b_n   = (lane & 7) + ((lane >> 4) & 1) * 8;
    const int b_kh  = ((lane >> 3) & 1) * 8;

#pragma unroll
    for (int i = 0; i < 4; ++i) {
        int idx = tid + i * 256;
        int r = idx >> 3, c = idx & 7;
        CP_ASYNC16(sbase + (QHI_W + r * KSW) * 4 + c * 16, Qh + (bhT + q0 + r) * HDIM + c * 8);
        CP_ASYNC16(sbase + (QLO_W + r * KSW) * 4 + c * 16, Ql + (bhT + q0 + r) * HDIM + c * 8);
    }
    CP_COMMIT();

#define LOAD_KV(kb_, st_) do {                                                          \
        const int _kv0 = (kb_) * AKV;                                                  \
        const uint32_t _sb = sbase + (STG0_W + (st_) * STG_SZ_W) * 4;                   \
        _Pragma("unroll")                                                               \
        for (int _i = 0; _i < 2; ++_i) {                                                \
            int _idx = tid + _i * 256;                                                  \
            int _r = _idx >> 3, _c = _idx & 7;                                          \
            CP_ASYNC16(_sb + (KOFF_W + _r * KSW) * 4 + _c * 16,                         \
                       Kt + (bhT + _kv0 + _r) * HDIM + _c * 8);                         \
        }                                                                               \
        _Pragma("unroll")                                                               \
        for (int _i = 0; _i < 2; ++_i) {                                                \
            int _idx = tid + _i * 256;                                                  \
            int _r = _idx >> 3, _c = _idx & 7;                                          \
            CP_ASYNC16(_sb + (VOFF_W + _r * VSW) * 4 + _c * 16,                         \
                       Vt + ((size_t)bh * HDIM + _r) * TSEQ + _kv0 + _c * 8);           \
        }                                                                               \
        CP_COMMIT();                                                                    \
    } while (0)

    LOAD_KV(0, 0);
    CP_WAIT(0);
    __syncthreads();

    uint32_t qfh[4][4], qfl[4][4];
    {
        const uint32_t qrow = (uint32_t)((warp * 16 + a_row) * KSW);
#pragma unroll
        for (int ks = 0; ks < 4; ++ks) {
            uint32_t ao = sbase + (QHI_W + qrow) * 4 + (ks * 16 + a_kh) * 2;
            LDSM_X4(qfh[ks][0], qfh[ks][1], qfh[ks][2], qfh[ks][3], ao);
            uint32_t al_ = ao + (QLO_W - QHI_W) * 4;
            LDSM_X4(qfl[ks][0], qfl[ks][1], qfl[ks][2], qfl[ks][3], al_);
        }
    }

    float o[8][4];
#pragma unroll
    for (int i = 0; i < 8; ++i)
#pragma unroll
        for (int j = 0; j < 4; ++j) o[i][j] = 0.0f;
    float m0 = -1e30f, m1 = -1e30f, l0 = 0.0f, l1 = 0.0f;

    const int nkb = 2 * (qb + 1);
    for (int kb = 0; kb < nkb; ++kb) {
        if (kb) { CP_WAIT(0); __syncthreads(); }
        if (kb + 1 < nkb) LOAD_KV(kb + 1, (kb + 1) & 1);

        const uint32_t stw = STG0_W + (kb & 1) * STG_SZ_W;
        const uint32_t kW = stw + KOFF_W;
        const uint32_t vW = stw + VOFF_W;

        float s[8][4];
#pragma unroll
        for (int i = 0; i < 8; ++i)
            s[i][0] = s[i][1] = s[i][2] = s[i][3] = 0.0f;
#pragma unroll
        for (int np = 0; np < 4; ++np) {
            const uint32_t krow = sbase + (kW + (np * 16 + b_n) * KSW) * 4;
#pragma unroll
            for (int ks = 0; ks < 4; ++ks) {
                uint32_t b0, b1, b2, b3;
                LDSM_X4(b0, b1, b2, b3, krow + (ks * 16 + b_kh) * 2);
                mma_bb(s[np * 2],     qfh[ks], b0, b1);
                mma_bb(s[np * 2],     qfl[ks], b0, b1);
                mma_bb(s[np * 2 + 1], qfh[ks], b2, b3);
                mma_bb(s[np * 2 + 1], qfl[ks], b2, b3);
            }
        }

        if (kb >= nkb - 2) {
            const int kv0 = kb * AKV;
            const int r0g = q0 + warp * 16 + grp;
            const int r1g = r0g + 8;
#pragma unroll
            for (int nt = 0; nt < 8; ++nt) {
                int c0 = kv0 + nt * 8 + tig * 2;
                if (c0 > r0g)     s[nt][0] = -1e30f;
                if (c0 + 1 > r0g) s[nt][1] = -1e30f;
                if (c0 > r1g)     s[nt][2] = -1e30f;
                if (c0 + 1 > r1g) s[nt][3] = -1e30f;
            }
        }

        float mx0 = -1e30f, mx1 = -1e30f;
#pragma unroll
        for (int nt = 0; nt < 8; ++nt) {
            mx0 = fmaxf(mx0, fmaxf(s[nt][0], s[nt][1]));
            mx1 = fmaxf(mx1, fmaxf(s[nt][2], s[nt][3]));
        }
        mx0 = fmaxf(mx0, __shfl_xor_sync(0xffffffffu, mx0, 1));
        mx0 = fmaxf(mx0, __shfl_xor_sync(0xffffffffu, mx0, 2));
        mx1 = fmaxf(mx1, __shfl_xor_sync(0xffffffffu, mx1, 1));
        mx1 = fmaxf(mx1, __shfl_xor_sync(0xffffffffu, mx1, 2));
        float mn0 = fmaxf(m0, mx0), mn1 = fmaxf(m1, mx1);
        float a0 = exp2p(m0 - mn0), a1 = exp2p(m1 - mn1);
        m0 = mn0; m1 = mn1;
        l0 *= a0; l1 *= a1;
#pragma unroll
        for (int nt = 0; nt < 8; ++nt) {
            o[nt][0] *= a0; o[nt][1] *= a0;
            o[nt][2] *= a1; o[nt][3] *= a1;
        }
        float sum0 = 0.0f, sum1 = 0.0f;
#pragma unroll
        for (int nt = 0; nt < 8; ++nt) {
            float p0 = exp2p(s[nt][0] - m0);
            float p1 = exp2p(s[nt][1] - m0);
            float p2 = exp2p(s[nt][2] - m1);
            float p3 = exp2p(s[nt][3] - m1);
            sum0 += p0 + p1; sum1 += p2 + p3;
            s[nt][0] = p0; s[nt][1] = p1; s[nt][2] = p2; s[nt][3] = p3;
        }
        l0 += sum0; l1 += sum1;

#pragma unroll
        for (int j = 0; j < 4; ++j) {
            uint32_t ah4[4];
#pragma unroll
            for (int u = 0; u < 2; ++u) {
                const float* pv = s[2 * j + u];
                ah4[u * 2 + 0] = pack_h2(pv[0], pv[1]);
                ah4[u * 2 + 1] = pack_h2(pv[2], pv[3]);
            }
#pragma unroll
            for (int np = 0; np < 4; ++np) {
                uint32_t v0, v1, v2, v3;
                uint32_t vrow = sbase + (vW + (np * 16 + b_n) * VSW) * 4;
                LDSM_X4(v0, v1, v2, v3, vrow + (j * 16 + b_kh) * 2);
                mma_bb(o[np * 2],     ah4, v0, v1);
                mma_bb(o[np * 2 + 1], ah4, v2, v3);
            }
        }
    }

    l0 += __shfl_xor_sync(0xffffffffu, l0, 1);
    l0 += __shfl_xor_sync(0xffffffffu, l0, 2);
    l1 += __shfl_xor_sync(0xffffffffu, l1, 1);
    l1 += __shfl_xor_sync(0xffffffffu, l1, 2);
    const float inv0 = 1.0f / l0, inv1 = 1.0f / l1;

    const int b = bh >> 4, h = bh & 15;
    const int rowg = q0 + warp * 16 + grp;
    const size_t base0 = ((size_t)(b * TSEQ) + rowg) * (NEMBD / 2) + h * (HDIM / 2);
    const size_t base1 = base0 + 8 * (NEMBD / 2);
#pragma unroll
    for (int nt = 0; nt < 8; ++nt) {
        int cw = nt * 4 + tig;
        yhi[base0 + cw] = pack_h2(o[nt][0] * inv0, o[nt][1] * inv0);
        yhi[base1 + cw] = pack_h2(o[nt][2] * inv1, o[nt][3] * inv1);
    }
#undef LOAD_KV
}

// ---------------------------------------------------------------------------
// Launch
// ---------------------------------------------------------------------------
extern "C" void kernel_launch(void* const* d_in, const int* in_sizes, int n_in,
                              void* d_out, int out_size)
{
    const float* x      = (const float*)d_in[0];
    const float* w_attn = (const float*)d_in[1];
    const float* w_proj = (const float*)d_in[2];
    float* out = (float*)d_out;

    __half *ahi, *alo, *wq, *wp, *qhi, *qlo, *kk, *vt;
    float *v32;
    cudaGetSymbolAddress((void**)&ahi, g_a_hi);
    cudaGetSymbolAddress((void**)&alo, g_a_lo);
    cudaGetSymbolAddress((void**)&wq, g_wq);
    cudaGetSymbolAddress((void**)&wp, g_wp);
    cudaGetSymbolAddress((void**)&qhi, g_q_hi);
    cudaGetSymbolAddress((void**)&qlo, g_q_lo);
    cudaGetSymbolAddress((void**)&kk, g_k);
    cudaGetSymbolAddress((void**)&v32, g_v32);
    cudaGetSymbolAddress((void**)&vt, g_vt);

    cudaFuncSetAttribute(gemm_q_kernel,
                         cudaFuncAttributeMaxDynamicSharedMemorySize, SMEM2);
    cudaFuncSetAttribute(gemm_wide_kernel<0>,
                         cudaFuncAttributeMaxDynamicSharedMemorySize, SMEMW);
    cudaFuncSetAttribute(gemm_wide_kernel<2>,
                         cudaFuncAttributeMaxDynamicSharedMemorySize, SMEMW);
    cudaFuncSetAttribute(attn_hmma_kernel,
                         cudaFuncAttributeMaxDynamicSharedMemorySize, ATTN_SMEM_B);

    const int M = BATCH * TSEQ;   // 8192
    const int K = NEMBD;          // 1024

    // Split x -> fp16 hi/lo
    {
        int n4 = (M * K) / 4;
        split_kernel<<<(n4 + 255) / 256, 256>>>(x, ahi, alo, n4);
    }
    // Transpose weights -> fp16
    {
        dim3 g1((3 * NEMBD) / 32, K / 32);
        tsplit_kernel<<<g1, dim3(32, 8)>>>(w_attn, wq, K, 3 * NEMBD);
        dim3 g2(NEMBD / 32, K / 32);
        tsplit_kernel<<<g2, dim3(32, 8)>>>(w_proj, wp, K, NEMBD);
    }
    // Stage 1a: q columns (2-product, BN=64) -> q hi/lo scaled
    {
        dim3 grid(NEMBD / 64, M / 128);
        gemm_q_kernel<<<grid, 256, SMEM2>>>(ahi, alo, wq,
                                            (uint32_t*)qhi, (uint32_t*)qlo, K);
    }
    // Stage 1b: k,v columns (1-product, BN=128) -> k fp16, v fp32
    {
        dim3 grid((2 * NEMBD) / 128, M / 128);
        gemm_wide_kernel<2><<<grid, 256, SMEMW>>>(
            ahi, wq + (size_t)NEMBD * K, nullptr,
            (uint32_t*)kk, v32, 0, K, NEMBD);
    }
    // V transpose -> [bh][d][t] fp16
    {
        dim3 gv(TSEQ / 32, HDIM / 32, BH);
        v_tsplit_kernel<<<gv, dim3(32, 8)>>>(v32, vt);
    }
    // Stage 2: flash attention -> y fp16 (into g_a_hi)
    {
        dim3 grid(TSEQ / AQ, BH);
        attn_hmma_kernel<<<grid, 256, ATTN_SMEM_B>>>(qhi, qlo, kk, vt, (uint32_t*)ahi);
    }
    // Stage 3: out = y @ w_proj (1-product, BN=128)
    {
        dim3 grid(NEMBD / 128, M / 128);
        gemm_wide_kernel<0><<<grid, 256, SMEMW>>>(
            ahi, wp, out, nullptr, nullptr, NEMBD, K, 0);
    }
}

// round 11
// speedup vs baseline: 2.0311x; 1.0285x over previous
#include <cuda_runtime.h>
#include <cuda_fp16.h>
#include <math.h>
#include <stdint.h>

// Problem constants
#define NEMBD 1024
#define NHEAD 16
#define HDIM  64
#define TSEQ  2048
#define BATCH 4
#define BH    (BATCH * NHEAD)
#define QSCALE 0.18033688011112042f   // 0.125 * log2(e)

// ---------------------------------------------------------------------------
// Scratch (device globals)
// ---------------------------------------------------------------------------
__device__ __half g_a_hi[(size_t)BATCH * TSEQ * NEMBD];   // x hi, then y (single)
__device__ __half g_a_lo[(size_t)BATCH * TSEQ * NEMBD];   // x lo
__device__ __half g_wq[(size_t)3 * NEMBD * NEMBD];        // w_attn^T [3072][1024] fp16
__device__ __half g_wp[(size_t)NEMBD * NEMBD];            // w_proj^T [1024][1024] fp16
__device__ __half g_q_hi[(size_t)BH * TSEQ * HDIM];       // [bh][t][d], pre-scaled
__device__ __half g_q_lo[(size_t)BH * TSEQ * HDIM];
__device__ __half g_k[(size_t)BH * TSEQ * HDIM];          // [bh][t][d] fp16
__device__ __half g_v[(size_t)BH * TSEQ * HDIM];          // [bh][t][d] fp16 (natural!)

// ---------------------------------------------------------------------------
// PTX helpers
// ---------------------------------------------------------------------------
__device__ __forceinline__ uint32_t smem_u32(const void* p) {
    uint32_t a;
    asm("{ .reg .u64 t; cvta.to.shared.u64 t, %1; cvt.u32.u64 %0, t; }" : "=r"(a) : "l"(p));
    return a;
}
#define CP_ASYNC16(sm, gm) \
    asm volatile("cp.async.cg.shared.global [%0], [%1], 16;" :: "r"(sm), "l"(gm))
#define CP_COMMIT() asm volatile("cp.async.commit_group;" ::: "memory")
#define CP_WAIT(n)  asm volatile("cp.async.wait_group %0;" :: "n"(n) : "memory")

#define LDSM_X4(r0, r1, r2, r3, a) \
    asm volatile("ldmatrix.sync.aligned.m8n8.x4.shared.b16 {%0,%1,%2,%3}, [%4];" \
        : "=r"(r0), "=r"(r1), "=r"(r2), "=r"(r3) : "r"(a))
#define LDSM_X4_T(r0, r1, r2, r3, a) \
    asm volatile("ldmatrix.sync.aligned.m8n8.x4.trans.shared.b16 {%0,%1,%2,%3}, [%4];" \
        : "=r"(r0), "=r"(r1), "=r"(r2), "=r"(r3) : "r"(a))

__device__ __forceinline__ void mma_bb(float* c, const uint32_t* a, uint32_t b0, uint32_t b1) {
    asm volatile(
        "mma.sync.aligned.m16n8k16.row.col.f32.f16.f16.f32 "
        "{%0,%1,%2,%3}, {%4,%5,%6,%7}, {%8,%9}, {%0,%1,%2,%3};"
        : "+f"(c[0]), "+f"(c[1]), "+f"(c[2]), "+f"(c[3])
        : "r"(a[0]), "r"(a[1]), "r"(a[2]), "r"(a[3]), "r"(b0), "r"(b1));
}
__device__ __forceinline__ uint32_t pack_h2(float a, float b) {
    __half2 h = __floats2half2_rn(a, b);
    return *(uint32_t*)&h;
}
__device__ __forceinline__ float exp2p(float t) {
    t = fmaxf(t, -126.0f);
    float fi = rintf(t);
    float f = t - fi;
    float p = 0.0013333558f;
    p = fmaf(p, f, 0.0096181291f);
    p = fmaf(p, f, 0.0555041087f);
    p = fmaf(p, f, 0.2402265070f);
    p = fmaf(p, f, 0.6931471806f);
    p = fmaf(p, f, 1.0f);
    int ii = (int)fi;
    return p * __int_as_float((uint32_t)(ii + 127) << 23);
}

// ---------------------------------------------------------------------------
// Conversion kernels
// ---------------------------------------------------------------------------
__global__ __launch_bounds__(256)
void split_kernel(const float* __restrict__ in, __half* __restrict__ hi,
                  __half* __restrict__ lo, int n4)
{
    int idx = blockIdx.x * blockDim.x + threadIdx.x;
    if (idx >= n4) return;
    float4 v = ((const float4*)in)[idx];
    __half h[4], l[4];
    float f[4] = {v.x, v.y, v.z, v.w};
#pragma unroll
    for (int i = 0; i < 4; ++i) {
        h[i] = __float2half_rn(f[i]);
        l[i] = __float2half_rn(f[i] - __half2float(h[i]));
    }
    ((uint2*)hi)[idx] = *(const uint2*)h;
    ((uint2*)lo)[idx] = *(const uint2*)l;
}

__global__ __launch_bounds__(256)
void tsplit_kernel(const float* __restrict__ w, __half* __restrict__ wt, int K, int N)
{
    __shared__ float t[32][33];
    const int n0 = blockIdx.x * 32;
    const int k0 = blockIdx.y * 32;
#pragma unroll
    for (int i = 0; i < 4; ++i) {
        int kk = threadIdx.y + i * 8;
        t[kk][threadIdx.x] = w[(size_t)(k0 + kk) * N + n0 + threadIdx.x];
    }
    __syncthreads();
#pragma unroll
    for (int i = 0; i < 4; ++i) {
        int nn = threadIdx.y + i * 8;
        int kk = threadIdx.x;
        wt[(size_t)(n0 + nn) * K + k0 + kk] = __float2half_rn(t[kk][nn]);
    }
}

// ---------------------------------------------------------------------------
// Shared tile constants
// ---------------------------------------------------------------------------
#define BK 32
#define ASTR 40
#define A_TILE_B (128 * ASTR * 2)        // 10240 B
#define B64_TILE_B (64 * ASTR * 2)       // 5120 B
#define B128_TILE_B (128 * ASTR * 2)     // 10240 B

// ---------------------------------------------------------------------------
// 2-product GEMM, BN=64 (q path): q epilogue (scaled hi/lo).
// ---------------------------------------------------------------------------
#define GBUF2 (2 * A_TILE_B + B64_TILE_B)   // 25600
#define SMEM2 (3 * GBUF2)                    // 76800

__global__ __launch_bounds__(256, 2)
void gemm_q_kernel(const __half* __restrict__ Ahi,
                   const __half* __restrict__ Alo,
                   const __half* __restrict__ B,
                   uint32_t* __restrict__ qhi, uint32_t* __restrict__ qlo,
                   int K)
{
    extern __shared__ char smem[];
    const uint32_t sbase = smem_u32(smem);
    const int tid = threadIdx.x;
    const int wid = tid >> 5;
    const int lane = tid & 31;
    const int grp = lane >> 2;
    const int tig = lane & 3;
    const int warp_m = wid & 3;
    const int warp_n = wid >> 2;
    const int rowBase = blockIdx.y * 128;
    const int colBase = blockIdx.x * 64;

    const int a_row = lane & 15;
    const int a_kh  = (lane >> 4) * 8;
    uint32_t aoff[2];
#pragma unroll
    for (int mt = 0; mt < 2; ++mt)
        aoff[mt] = (uint32_t)(((warp_m * 32 + mt * 16 + a_row) * ASTR + a_kh) * 2);
    const int b_n  = (lane & 7) + ((lane >> 4) & 1) * 8;
    const int b_kh = ((lane >> 3) & 1) * 8;
    uint32_t boff[2];
#pragma unroll
    for (int np = 0; np < 2; ++np)
        boff[np] = (uint32_t)(((warp_n * 32 + np * 16 + b_n) * ASTR + b_kh) * 2);

    float acc[2][4][4];
#pragma unroll
    for (int i = 0; i < 2; ++i)
#pragma unroll
        for (int j = 0; j < 4; ++j)
#pragma unroll
            for (int k = 0; k < 4; ++k) acc[i][j][k] = 0.0f;

    const int nstages = K / BK;

#define LOAD_STAGE_Q(s) do {                                                    \
        const int _k0 = (s) * BK;                                               \
        const uint32_t _buf = sbase + ((s) % 3) * GBUF2;                        \
        _Pragma("unroll")                                                       \
        for (int _i = 0; _i < 2; ++_i) {                                        \
            int _idx = tid + _i * 256;                                          \
            int _r = _idx >> 2, _c = _idx & 3;                                  \
            CP_ASYNC16(_buf + _r * (ASTR * 2) + _c * 16,                        \
                       Ahi + (size_t)(rowBase + _r) * K + _k0 + _c * 8);        \
            CP_ASYNC16(_buf + A_TILE_B + _r * (ASTR * 2) + _c * 16,             \
                       Alo + (size_t)(rowBase + _r) * K + _k0 + _c * 8);        \
        }                                                                       \
        {                                                                       \
            int _r = tid >> 2, _c = tid & 3;                                    \
            CP_ASYNC16(_buf + 2 * A_TILE_B + _r * (ASTR * 2) + _c * 16,         \
                       B + (size_t)(colBase + _r) * K + _k0 + _c * 8);          \
        }                                                                       \
        CP_COMMIT();                                                            \
    } while (0)

    LOAD_STAGE_Q(0);
    LOAD_STAGE_Q(1);

    for (int s = 0; s < nstages; ++s) {
        if (s + 2 < nstages) { LOAD_STAGE_Q(s + 2); CP_WAIT(2); }
        else if (s + 1 < nstages) { CP_WAIT(1); }
        else { CP_WAIT(0); }
        __syncthreads();

        const uint32_t buf = sbase + (s % 3) * GBUF2;
        const uint32_t smAh = buf;
        const uint32_t smAl = buf + A_TILE_B;
        const uint32_t smB  = buf + 2 * A_TILE_B;

#pragma unroll
        for (int kkk = 0; kkk < BK; kkk += 16) {
            uint32_t ah[2][4], al[2][4], bf[2][4];
#pragma unroll
            for (int mt = 0; mt < 2; ++mt) {
                LDSM_X4(ah[mt][0], ah[mt][1], ah[mt][2], ah[mt][3], smAh + aoff[mt] + kkk * 2);
                LDSM_X4(al[mt][0], al[mt][1], al[mt][2], al[mt][3], smAl + aoff[mt] + kkk * 2);
            }
#pragma unroll
            for (int np = 0; np < 2; ++np)
                LDSM_X4(bf[np][0], bf[np][1], bf[np][2], bf[np][3], smB + boff[np] + kkk * 2);
#pragma unroll
            for (int mt = 0; mt < 2; ++mt)
#pragma unroll
                for (int nt = 0; nt < 4; ++nt) {
                    uint32_t b0 = bf[nt >> 1][(nt & 1) * 2];
                    uint32_t b1 = bf[nt >> 1][(nt & 1) * 2 + 1];
                    mma_bb(acc[mt][nt], ah[mt], b0, b1);
                    mma_bb(acc[mt][nt], al[mt], b0, b1);
                }
        }
        __syncthreads();
    }

    const int h = colBase >> 6;
#pragma unroll
    for (int mt = 0; mt < 2; ++mt) {
        const int r0 = rowBase + warp_m * 32 + mt * 16 + grp;
#pragma unroll
        for (int hf = 0; hf < 2; ++hf) {
            const int r = r0 + hf * 8;
            const int b = r >> 11;
            const int t = r & (TSEQ - 1);
            const size_t bhT = (size_t)(b * NHEAD + h) * TSEQ + t;
#pragma unroll
            for (int nt = 0; nt < 4; ++nt) {
                float v0 = acc[mt][nt][hf * 2], v1 = acc[mt][nt][hf * 2 + 1];
                const int dw = warp_n * 16 + nt * 4 + tig;
                float q0 = v0 * QSCALE, q1 = v1 * QSCALE;
                uint32_t hp = pack_h2(q0, q1);
                float2 fr = __half22float2(*(__half2*)&hp);
                qhi[bhT * 32 + dw] = hp;
                qlo[bhT * 32 + dw] = pack_h2(q0 - fr.x, q1 - fr.y);
            }
        }
    }
#undef LOAD_STAGE_Q
}

// ---------------------------------------------------------------------------
// 1-product GEMM, BN=128. MODE 0: fp32 C.  MODE 2: k/v epilogue (both fp16).
// ---------------------------------------------------------------------------
#define GBUFW (A_TILE_B + B128_TILE_B)   // 20480
#define SMEMW (3 * GBUFW)                 // 61440

template<int MODE>
__global__ __launch_bounds__(256, 2)
void gemm_wide_kernel(const __half* __restrict__ Ahi,
                      const __half* __restrict__ B,
                      float* __restrict__ C,
                      uint32_t* __restrict__ kk, uint32_t* __restrict__ vv,
                      int N, int K, int colOff)
{
    extern __shared__ char smem[];
    const uint32_t sbase = smem_u32(smem);
    const int tid = threadIdx.x;
    const int wid = tid >> 5;
    const int lane = tid & 31;
    const int grp = lane >> 2;
    const int tig = lane & 3;
    const int warp_m = wid & 3;
    const int warp_n = wid >> 2;
    const int rowBase = blockIdx.y * 128;
    const int colBase = blockIdx.x * 128;

    const int a_row = lane & 15;
    const int a_kh  = (lane >> 4) * 8;
    uint32_t aoff[2];
#pragma unroll
    for (int mt = 0; mt < 2; ++mt)
        aoff[mt] = (uint32_t)(((warp_m * 32 + mt * 16 + a_row) * ASTR + a_kh) * 2);
    const int b_n  = (lane & 7) + ((lane >> 4) & 1) * 8;
    const int b_kh = ((lane >> 3) & 1) * 8;
    uint32_t boff[4];
#pragma unroll
    for (int np = 0; np < 4; ++np)
        boff[np] = (uint32_t)(((warp_n * 64 + np * 16 + b_n) * ASTR + b_kh) * 2);

    float acc[2][8][4];
#pragma unroll
    for (int i = 0; i < 2; ++i)
#pragma unroll
        for (int j = 0; j < 8; ++j)
#pragma unroll
            for (int k = 0; k < 4; ++k) acc[i][j][k] = 0.0f;

    const int nstages = K / BK;

#define LOAD_STAGE_W(s) do {                                                    \
        const int _k0 = (s) * BK;                                               \
        const uint32_t _buf = sbase + ((s) % 3) * GBUFW;                        \
        _Pragma("unroll")                                                       \
        for (int _i = 0; _i < 2; ++_i) {                                        \
            int _idx = tid + _i * 256;                                          \
            int _r = _idx >> 2, _c = _idx & 3;                                  \
            CP_ASYNC16(_buf + _r * (ASTR * 2) + _c * 16,                        \
                       Ahi + (size_t)(rowBase + _r) * K + _k0 + _c * 8);        \
            CP_ASYNC16(_buf + A_TILE_B + _r * (ASTR * 2) + _c * 16,             \
                       B + (size_t)(colBase + _r) * K + _k0 + _c * 8);          \
        }                                                                       \
        CP_COMMIT();                                                            \
    } while (0)

    LOAD_STAGE_W(0);
    LOAD_STAGE_W(1);

    for (int s = 0; s < nstages; ++s) {
        if (s + 2 < nstages) { LOAD_STAGE_W(s + 2); CP_WAIT(2); }
        else if (s + 1 < nstages) { CP_WAIT(1); }
        else { CP_WAIT(0); }
        __syncthreads();

        const uint32_t buf = sbase + (s % 3) * GBUFW;
        const uint32_t smA = buf;
        const uint32_t smB = buf + A_TILE_B;

#pragma unroll
        for (int kkk = 0; kkk < BK; kkk += 16) {
            uint32_t ah[2][4], bf[4][4];
#pragma unroll
            for (int mt = 0; mt < 2; ++mt)
                LDSM_X4(ah[mt][0], ah[mt][1], ah[mt][2], ah[mt][3], smA + aoff[mt] + kkk * 2);
#pragma unroll
            for (int np = 0; np < 4; ++np)
                LDSM_X4(bf[np][0], bf[np][1], bf[np][2], bf[np][3], smB + boff[np] + kkk * 2);
#pragma unroll
            for (int mt = 0; mt < 2; ++mt)
#pragma unroll
                for (int nt = 0; nt < 8; ++nt) {
                    uint32_t b0 = bf[nt >> 1][(nt & 1) * 2];
                    uint32_t b1 = bf[nt >> 1][(nt & 1) * 2 + 1];
                    mma_bb(acc[mt][nt], ah[mt], b0, b1);
                }
        }
        __syncthreads();
    }

    if (MODE == 0) {
#pragma unroll
        for (int mt = 0; mt < 2; ++mt) {
            int r = rowBase + warp_m * 32 + mt * 16 + grp;
#pragma unroll
            for (int nt = 0; nt < 8; ++nt) {
                int c = colBase + warp_n * 64 + nt * 8 + tig * 2;
                *(float2*)(C + (size_t)r * N + c) = make_float2(acc[mt][nt][0], acc[mt][nt][1]);
                *(float2*)(C + (size_t)(r + 8) * N + c) = make_float2(acc[mt][nt][2], acc[mt][nt][3]);
            }
        }
    } else {
        // k/v epilogue (col range [1024,3072)), both fp16 [bh][t][d]
#pragma unroll
        for (int mt = 0; mt < 2; ++mt) {
            const int r0 = rowBase + warp_m * 32 + mt * 16 + grp;
#pragma unroll
            for (int hf = 0; hf < 2; ++hf) {
                const int r = r0 + hf * 8;
                const int b = r >> 11;
                const int t = r & (TSEQ - 1);
#pragma unroll
                for (int nt = 0; nt < 8; ++nt) {
                    const int col = colOff + colBase + warp_n * 64 + nt * 8;
                    const int sec = col >> 10;           // 1=k, 2=v
                    const int h = (col & 1023) >> 6;
                    const int dw = ((col & 63) >> 1) + tig;
                    const size_t bhT = (size_t)(b * NHEAD + h) * TSEQ + t;
                    float v0 = acc[mt][nt][hf * 2], v1 = acc[mt][nt][hf * 2 + 1];
                    uint32_t hp = pack_h2(v0, v1);
                    if (sec == 1) kk[bhT * 32 + dw] = hp;
                    else          vv[bhT * 32 + dw] = hp;
                }
            }
        }
    }
#undef LOAD_STAGE_W
}

// ---------------------------------------------------------------------------
// HMMA flash attention: S 2-product, P@V single product via ldmatrix.trans.
// V stored naturally [bh][t][d]; no transpose kernel needed.
// ---------------------------------------------------------------------------
#define AQ  128
#define AKV 64
#define KSW 36
#define VSW 36
#define QHI_W 0
#define QLO_W 4608
#define STG0_W 9216
#define STG_SZ_W 4608
#define KOFF_W 0
#define VOFF_W 2304
#define ATTN_SMEM_B ((STG0_W + 2 * STG_SZ_W) * 4)   // 73728 bytes

__global__ __launch_bounds__(256, 2)
void attn_hmma_kernel(const __half* __restrict__ Qh, const __half* __restrict__ Ql,
                      const __half* __restrict__ Kt, const __half* __restrict__ Vh,
                      uint32_t* __restrict__ yhi)
{
    extern __shared__ uint32_t smw[];
    const uint32_t sbase = smem_u32(smw);
    const int tid = threadIdx.x;
    const int warp = tid >> 5;
    const int lane = tid & 31;
    const int grp = lane >> 2;
    const int tig = lane & 3;
    const int qb = (int)(gridDim.x - 1 - blockIdx.x);
    const int bh = blockIdx.y;
    const int q0 = qb * AQ;
    const size_t bhT = (size_t)bh * TSEQ;

    const int a_row = lane & 15;
    const int a_kh  = (lane >> 4) * 8;
    const int b_n   = (lane & 7) + ((lane >> 4) & 1) * 8;
    const int b_kh  = ((lane >> 3) & 1) * 8;

#pragma unroll
    for (int i = 0; i < 4; ++i) {
        int idx = tid + i * 256;
        int r = idx >> 3, c = idx & 7;
        CP_ASYNC16(sbase + (QHI_W + r * KSW) * 4 + c * 16, Qh + (bhT + q0 + r) * HDIM + c * 8);
        CP_ASYNC16(sbase + (QLO_W + r * KSW) * 4 + c * 16, Ql + (bhT + q0 + r) * HDIM + c * 8);
    }
    CP_COMMIT();

#define LOAD_KV(kb_, st_) do {                                                          \
        const int _kv0 = (kb_) * AKV;                                                  \
        const uint32_t _sb = sbase + (STG0_W + (st_) * STG_SZ_W) * 4;                   \
        _Pragma("unroll")                                                               \
        for (int _i = 0; _i < 2; ++_i) {   /* K: 64 rows x 8 f4 */                      \
            int _idx = tid + _i * 256;                                                  \
            int _r = _idx >> 3, _c = _idx & 7;                                          \
            CP_ASYNC16(_sb + (KOFF_W + _r * KSW) * 4 + _c * 16,                         \
                       Kt + (bhT + _kv0 + _r) * HDIM + _c * 8);                         \
        }                                                                               \
        _Pragma("unroll")                                                               \
        for (int _i = 0; _i < 2; ++_i) {   /* V: 64 kv-rows x 8 f4, natural layout */   \
            int _idx = tid + _i * 256;                                                  \
            int _r = _idx >> 3, _c = _idx & 7;                                          \
            CP_ASYNC16(_sb + (VOFF_W + _r * VSW) * 4 + _c * 16,                         \
                       Vh + (bhT + _kv0 + _r) * HDIM + _c * 8);                         \
        }                                                                               \
        CP_COMMIT();                                                                    \
    } while (0)

    LOAD_KV(0, 0);
    CP_WAIT(0);
    __syncthreads();

    uint32_t qfh[4][4], qfl[4][4];
    {
        const uint32_t qrow = (uint32_t)((warp * 16 + a_row) * KSW);
#pragma unroll
        for (int ks = 0; ks < 4; ++ks) {
            uint32_t ao = sbase + (QHI_W + qrow) * 4 + (ks * 16 + a_kh) * 2;
            LDSM_X4(qfh[ks][0], qfh[ks][1], qfh[ks][2], qfh[ks][3], ao);
            uint32_t al_ = ao + (QLO_W - QHI_W) * 4;
            LDSM_X4(qfl[ks][0], qfl[ks][1], qfl[ks][2], qfl[ks][3], al_);
        }
    }

    float o[8][4];
#pragma unroll
    for (int i = 0; i < 8; ++i)
#pragma unroll
        for (int j = 0; j < 4; ++j) o[i][j] = 0.0f;
    float m0 = -1e30f, m1 = -1e30f, l0 = 0.0f, l1 = 0.0f;

    const int nkb = 2 * (qb + 1);
    for (int kb = 0; kb < nkb; ++kb) {
        if (kb) { CP_WAIT(0); __syncthreads(); }
        if (kb + 1 < nkb) LOAD_KV(kb + 1, (kb + 1) & 1);

        const uint32_t stw = STG0_W + (kb & 1) * STG_SZ_W;
        const uint32_t kW = stw + KOFF_W;
        const uint32_t vW = stw + VOFF_W;

        float s[8][4];
#pragma unroll
        for (int i = 0; i < 8; ++i)
            s[i][0] = s[i][1] = s[i][2] = s[i][3] = 0.0f;
#pragma unroll
        for (int np = 0; np < 4; ++np) {
            const uint32_t krow = sbase + (kW + (np * 16 + b_n) * KSW) * 4;
#pragma unroll
            for (int ks = 0; ks < 4; ++ks) {
                uint32_t b0, b1, b2, b3;
                LDSM_X4(b0, b1, b2, b3, krow + (ks * 16 + b_kh) * 2);
                mma_bb(s[np * 2],     qfh[ks], b0, b1);
                mma_bb(s[np * 2],     qfl[ks], b0, b1);
                mma_bb(s[np * 2 + 1], qfh[ks], b2, b3);
                mma_bb(s[np * 2 + 1], qfl[ks], b2, b3);
            }
        }

        if (kb >= nkb - 2) {
            const int kv0 = kb * AKV;
            const int r0g = q0 + warp * 16 + grp;
            const int r1g = r0g + 8;
#pragma unroll
            for (int nt = 0; nt < 8; ++nt) {
                int c0 = kv0 + nt * 8 + tig * 2;
                if (c0 > r0g)     s[nt][0] = -1e30f;
                if (c0 + 1 > r0g) s[nt][1] = -1e30f;
                if (c0 > r1g)     s[nt][2] = -1e30f;
                if (c0 + 1 > r1g) s[nt][3] = -1e30f;
            }
        }

        float mx0 = -1e30f, mx1 = -1e30f;
#pragma unroll
        for (int nt = 0; nt < 8; ++nt) {
            mx0 = fmaxf(mx0, fmaxf(s[nt][0], s[nt][1]));
            mx1 = fmaxf(mx1, fmaxf(s[nt][2], s[nt][3]));
        }
        mx0 = fmaxf(mx0, __shfl_xor_sync(0xffffffffu, mx0, 1));
        mx0 = fmaxf(mx0, __shfl_xor_sync(0xffffffffu, mx0, 2));
        mx1 = fmaxf(mx1, __shfl_xor_sync(0xffffffffu, mx1, 1));
        mx1 = fmaxf(mx1, __shfl_xor_sync(0xffffffffu, mx1, 2));
        float mn0 = fmaxf(m0, mx0), mn1 = fmaxf(m1, mx1);
        float a0 = exp2p(m0 - mn0), a1 = exp2p(m1 - mn1);
        m0 = mn0; m1 = mn1;
        l0 *= a0; l1 *= a1;
#pragma unroll
        for (int nt = 0; nt < 8; ++nt) {
            o[nt][0] *= a0; o[nt][1] *= a0;
            o[nt][2] *= a1; o[nt][3] *= a1;
        }
        float sum0 = 0.0f, sum1 = 0.0f;
#pragma unroll
        for (int nt = 0; nt < 8; ++nt) {
            float p0 = exp2p(s[nt][0] - m0);
            float p1 = exp2p(s[nt][1] - m0);
            float p2 = exp2p(s[nt][2] - m1);
            float p3 = exp2p(s[nt][3] - m1);
            sum0 += p0 + p1; sum1 += p2 + p3;
            s[nt][0] = p0; s[nt][1] = p1; s[nt][2] = p2; s[nt][3] = p3;
        }
        l0 += sum0; l1 += sum1;

        // O += P @ V : B operand via ldmatrix.trans from natural-layout V tile.
        // r0 = (k 0-7, n 0-7), r1 = (k 8-15, n 0-7), r2/r3 = n 8-15.
#pragma unroll
        for (int j = 0; j < 4; ++j) {
            uint32_t ah4[4];
#pragma unroll
            for (int u = 0; u < 2; ++u) {
                const float* pv = s[2 * j + u];
                ah4[u * 2 + 0] = pack_h2(pv[0], pv[1]);
                ah4[u * 2 + 1] = pack_h2(pv[2], pv[3]);
            }
#pragma unroll
            for (int np = 0; np < 4; ++np) {
                uint32_t v0, v1, v2, v3;
                uint32_t vaddr = sbase + (vW + (j * 16 + a_row) * VSW) * 4
                               + (np * 16 + a_kh) * 2;
                LDSM_X4_T(v0, v1, v2, v3, vaddr);
                mma_bb(o[np * 2],     ah4, v0, v1);
                mma_bb(o[np * 2 + 1], ah4, v2, v3);
            }
        }
    }

    l0 += __shfl_xor_sync(0xffffffffu, l0, 1);
    l0 += __shfl_xor_sync(0xffffffffu, l0, 2);
    l1 += __shfl_xor_sync(0xffffffffu, l1, 1);
    l1 += __shfl_xor_sync(0xffffffffu, l1, 2);
    const float inv0 = 1.0f / l0, inv1 = 1.0f / l1;

    const int b = bh >> 4, h = bh & 15;
    const int rowg = q0 + warp * 16 + grp;
    const size_t base0 = ((size_t)(b * TSEQ) + rowg) * (NEMBD / 2) + h * (HDIM / 2);
    const size_t base1 = base0 + 8 * (NEMBD / 2);
#pragma unroll
    for (int nt = 0; nt < 8; ++nt) {
        int cw = nt * 4 + tig;
        yhi[base0 + cw] = pack_h2(o[nt][0] * inv0, o[nt][1] * inv0);
        yhi[base1 + cw] = pack_h2(o[nt][2] * inv1, o[nt][3] * inv1);
    }
#undef LOAD_KV
}

// ---------------------------------------------------------------------------
// Launch
// ---------------------------------------------------------------------------
extern "C" void kernel_launch(void* const* d_in, const int* in_sizes, int n_in,
                              void* d_out, int out_size)
{
    const float* x      = (const float*)d_in[0];
    const float* w_attn = (const float*)d_in[1];
    const float* w_proj = (const float*)d_in[2];
    float* out = (float*)d_out;

    __half *ahi, *alo, *wq, *wp, *qhi, *qlo, *kk, *vv;
    cudaGetSymbolAddress((void**)&ahi, g_a_hi);
    cudaGetSymbolAddress((void**)&alo, g_a_lo);
    cudaGetSymbolAddress((void**)&wq, g_wq);
    cudaGetSymbolAddress((void**)&wp, g_wp);
    cudaGetSymbolAddress((void**)&qhi, g_q_hi);
    cudaGetSymbolAddress((void**)&qlo, g_q_lo);
    cudaGetSymbolAddress((void**)&kk, g_k);
    cudaGetSymbolAddress((void**)&vv, g_v);

    cudaFuncSetAttribute(gemm_q_kernel,
                         cudaFuncAttributeMaxDynamicSharedMemorySize, SMEM2);
    cudaFuncSetAttribute(gemm_wide_kernel<0>,
                         cudaFuncAttributeMaxDynamicSharedMemorySize, SMEMW);
    cudaFuncSetAttribute(gemm_wide_kernel<2>,
                         cudaFuncAttributeMaxDynamicSharedMemorySize, SMEMW);
    cudaFuncSetAttribute(attn_hmma_kernel,
                         cudaFuncAttributeMaxDynamicSharedMemorySize, ATTN_SMEM_B);

    const int M = BATCH * TSEQ;   // 8192
    const int K = NEMBD;          // 1024

    // Split x -> fp16 hi/lo
    {
        int n4 = (M * K) / 4;
        split_kernel<<<(n4 + 255) / 256, 256>>>(x, ahi, alo, n4);
    }
    // Transpose weights -> fp16
    {
        dim3 g1((3 * NEMBD) / 32, K / 32);
        tsplit_kernel<<<g1, dim3(32, 8)>>>(w_attn, wq, K, 3 * NEMBD);
        dim3 g2(NEMBD / 32, K / 32);
        tsplit_kernel<<<g2, dim3(32, 8)>>>(w_proj, wp, K, NEMBD);
    }
    // Stage 1a: q columns (2-product, BN=64) -> q hi/lo scaled
    {
        dim3 grid(NEMBD / 64, M / 128);
        gemm_q_kernel<<<grid, 256, SMEM2>>>(ahi, alo, wq,
                                            (uint32_t*)qhi, (uint32_t*)qlo, K);
    }
    // Stage 1b: k,v columns (1-product, BN=128) -> k,v fp16 [bh][t][d]
    {
        dim3 grid((2 * NEMBD) / 128, M / 128);
        gemm_wide_kernel<2><<<grid, 256, SMEMW>>>(
            ahi, wq + (size_t)NEMBD * K, nullptr,
            (uint32_t*)kk, (uint32_t*)vv, 0, K, NEMBD);
    }
    // Stage 2: flash attention -> y fp16 (into g_a_hi)
    {
        dim3 grid(TSEQ / AQ, BH);
        attn_hmma_kernel<<<grid, 256, ATTN_SMEM_B>>>(qhi, qlo, kk, vv, (uint32_t*)ahi);
    }
    // Stage 3: out = y @ w_proj (1-product, BN=128)
    {
        dim3 grid(NEMBD / 128, M / 128);
        gemm_wide_kernel<0><<<grid, 256, SMEMW>>>(
            ahi, wp, out, nullptr, nullptr, NEMBD, K, 0);
    }
}